// round 1
// baseline (speedup 1.0000x reference)
#include <cuda_runtime.h>
#include <cuda_bf16.h>
#include <mma.h>

using namespace nvcuda;

// ---------------- problem constants ----------------
#define BB 4
#define TT 2048
#define DM 1024
#define HH 4
#define DKd 128
#define DVd 256
#define HDK 512     // H*DK
#define HDV 1024    // H*DV
#define BT  8192    // B*T tokens
#define CH  64      // chunk
#define NC  32      // chunks per sequence
#define NCHUNK 128  // total chunks (B*NC)
#define NCH 512     // chunk-heads (NCHUNK*H)
#define LR 16       // gate low rank
#define GNORM 16.0f
#define EPS 1e-5f

// ---------------- scratch (device globals; no allocation allowed) ----------------
__device__ float d_q   [BT * HDK];
__device__ float d_k   [BT * HDK];
__device__ float d_v   [BT * HDV];
__device__ float d_g   [BT * HDV];
__device__ float d_gk  [BT * HDK];
__device__ float d_x1  [BT * LR];
__device__ float d_qg  [BT * HDK];
__device__ float d_kint[BT * HDK];
__device__ float d_kg  [BT * HDK];
__device__ float d_glast[NCHUNK * HDK];
__device__ float d_S   [NCH * DKd * DVd];   // per-chunk-head: U_n, then converted in-place to S_{n-1}
__device__ float d_o   [BT * HDV];
__device__ float d_y   [BT * HDV];

// ---------------- helpers ----------------
template <typename Frag>
__device__ __forceinline__ void to_tf32(Frag& f) {
#pragma unroll
    for (int i = 0; i < f.num_elements; i++) f.x[i] = wmma::__float_to_tf32(f.x[i]);
}

typedef wmma::fragment<wmma::matrix_a, 16, 16, 8, wmma::precision::tf32, wmma::row_major> FragA;
typedef wmma::fragment<wmma::matrix_a, 16, 16, 8, wmma::precision::tf32, wmma::col_major> FragAT;
typedef wmma::fragment<wmma::matrix_b, 16, 16, 8, wmma::precision::tf32, wmma::row_major> FragB;
typedef wmma::fragment<wmma::matrix_b, 16, 16, 8, wmma::precision::tf32, wmma::col_major> FragBT;
typedef wmma::fragment<wmma::accumulator, 16, 16, 8, float> FragC;

// ---------------- generic tf32 GEMM: C[M,N] = A[M,K] @ B[K,N], all row-major ----------------
// BM=128, BN=128, BK=16, 256 threads (8 warps, each 32x64 = 2x4 16x16 tiles)
__global__ __launch_bounds__(256) void gemm_tf32_kernel(
    const float* __restrict__ A, const float* __restrict__ B, float* __restrict__ C,
    int M, int N, int K)
{
    __shared__ float As[128 * 16];
    __shared__ float Bs[16 * 128];

    const int bm = blockIdx.y, bn = blockIdx.x;
    const int tid = threadIdx.x;
    const int w = tid >> 5;
    const int wr = w >> 1;     // 0..3 (32-row band)
    const int wc = w & 1;      // 0..1 (64-col band)

    FragC acc[2][4];
#pragma unroll
    for (int r = 0; r < 2; r++)
#pragma unroll
        for (int c = 0; c < 4; c++) wmma::fill_fragment(acc[r][c], 0.0f);

    const float* Ab = A + (size_t)bm * 128 * K;
    const float* Bb = B + (size_t)bn * 128;

    for (int k0 = 0; k0 < K; k0 += 16) {
        // load A tile 128x16 (512 float4)
#pragma unroll
        for (int i = tid; i < 512; i += 256) {
            int row = i >> 2, c4 = i & 3;
            *(float4*)&As[row * 16 + c4 * 4] =
                *(const float4*)&Ab[(size_t)row * K + k0 + c4 * 4];
        }
        // load B tile 16x128 (512 float4)
#pragma unroll
        for (int i = tid; i < 512; i += 256) {
            int row = i >> 5, c4 = i & 31;
            *(float4*)&Bs[row * 128 + c4 * 4] =
                *(const float4*)&Bb[(size_t)(k0 + row) * N + c4 * 4];
        }
        __syncthreads();
#pragma unroll
        for (int kk = 0; kk < 16; kk += 8) {
            FragA af[2];
            FragB bf[4];
#pragma unroll
            for (int r = 0; r < 2; r++) {
                wmma::load_matrix_sync(af[r], &As[(wr * 32 + r * 16) * 16 + kk], 16);
                to_tf32(af[r]);
            }
#pragma unroll
            for (int c = 0; c < 4; c++) {
                wmma::load_matrix_sync(bf[c], &Bs[kk * 128 + wc * 64 + c * 16], 128);
                to_tf32(bf[c]);
            }
#pragma unroll
            for (int r = 0; r < 2; r++)
#pragma unroll
                for (int c = 0; c < 4; c++)
                    wmma::mma_sync(acc[r][c], af[r], bf[c], acc[r][c]);
        }
        __syncthreads();
    }
#pragma unroll
    for (int r = 0; r < 2; r++)
#pragma unroll
        for (int c = 0; c < 4; c++)
            wmma::store_matrix_sync(
                C + (size_t)(bm * 128 + wr * 32 + r * 16) * N + bn * 128 + wc * 64 + c * 16,
                acc[r][c], N, wmma::mem_row_major);
}

// ---------------- low-rank gate: x1 = x @ Wgk1 (K=1024, N=16) ----------------
__global__ __launch_bounds__(256) void gk1_kernel(
    const float* __restrict__ x, const float* __restrict__ W, float* __restrict__ x1)
{
    int t = blockIdx.x * 8 + (threadIdx.x >> 5);
    int lane = threadIdx.x & 31;
    if (t >= BT) return;
    const float* xr = x + (size_t)t * DM;
    float acc[LR];
#pragma unroll
    for (int n = 0; n < LR; n++) acc[n] = 0.0f;
    for (int j = lane; j < DM; j += 32) {
        float xv = xr[j];
        const float* wr = W + (size_t)j * LR;
#pragma unroll
        for (int n = 0; n < LR; n++) acc[n] += xv * wr[n];
    }
#pragma unroll
    for (int n = 0; n < LR; n++) {
#pragma unroll
        for (int off = 16; off > 0; off >>= 1)
            acc[n] += __shfl_xor_sync(0xffffffff, acc[n], off);
    }
    if (lane == 0) {
#pragma unroll
        for (int n = 0; n < LR; n++) x1[(size_t)t * LR + n] = acc[n];
    }
}

// ---------------- gk = log_sigmoid(x1 @ Wgk2 + b) / 16 ----------------
__global__ __launch_bounds__(256) void gk2_kernel(
    const float* __restrict__ x1, const float* __restrict__ W2,
    const float* __restrict__ bias, float* __restrict__ gk)
{
    int idx = blockIdx.x * 256 + threadIdx.x;
    if (idx >= BT * HDK) return;
    int t = idx >> 9;        // /512
    int n = idx & 511;
    const float* xr = x1 + (size_t)t * LR;
    float a = bias[n];
#pragma unroll
    for (int k = 0; k < LR; k++) a += xr[k] * W2[k * HDK + n];
    // stable log-sigmoid: min(a,0) - log1p(exp(-|a|))
    float ls = fminf(a, 0.0f) - log1pf(expf(-fabsf(a)));
    gk[idx] = ls * (1.0f / GNORM);
}

// ---------------- decay prep: per chunk, per column, compute qg/kint/kg/glast ----------------
__global__ __launch_bounds__(512) void decay_prep_kernel(
    const float* __restrict__ q, const float* __restrict__ k, const float* __restrict__ gk,
    float* __restrict__ qg, float* __restrict__ kint, float* __restrict__ kg,
    float* __restrict__ glast)
{
    int c = blockIdx.x;          // global chunk 0..127
    int col = threadIdx.x;       // 0..511 (= h*DK + dk)
    size_t base = (size_t)c * CH * HDK + col;
    float tot = 0.0f;
#pragma unroll 8
    for (int i = 0; i < CH; i++) tot += gk[base + (size_t)i * HDK];
    glast[(size_t)c * HDK + col] = expf(tot);
    const float scale = 0.088388347648318447f;   // 128^-0.5
    float run = 0.0f;
    for (int i = 0; i < CH; i++) {
        size_t idx = base + (size_t)i * HDK;
        run += gk[idx];
        qg[idx]   = q[idx] * expf(run) * scale;
        kint[idx] = k[idx] * expf(-run);
        kg[idx]   = k[idx] * expf(tot - run);
    }
}

// ---------------- intra-chunk: A=tril(qg kint^T); o=A v; U=kg^T v ----------------
__global__ __launch_bounds__(256) void gla_intra_kernel(
    const float* __restrict__ qg, const float* __restrict__ kint,
    const float* __restrict__ kg, const float* __restrict__ v,
    float* __restrict__ o, float* __restrict__ U)
{
    const int ch = blockIdx.x;   // 0..511
    const int c = ch >> 2;
    const int h = ch & 3;
    const size_t t0 = (size_t)c * CH;

    const float* qgb = qg   + t0 * HDK + h * DKd;  // ld HDK
    const float* kib = kint + t0 * HDK + h * DKd;
    const float* kgb = kg   + t0 * HDK + h * DKd;
    const float* vb  = v    + t0 * HDV + h * DVd;  // ld HDV
    float* ob = o + t0 * HDV + h * DVd;
    float* Ub = U + (size_t)ch * DKd * DVd;        // ld DVd

    __shared__ float As[64 * 72];
    const int tid = threadIdx.x;
    const int w = tid >> 5;

    // ---- A = qg @ kint^T (64x64, K=128), 16 tiles, 2 per warp ----
#pragma unroll
    for (int tIdx = w * 2; tIdx < w * 2 + 2; tIdx++) {
        int ti = tIdx >> 2, tj = tIdx & 3;
        FragC acc;
        wmma::fill_fragment(acc, 0.0f);
#pragma unroll
        for (int kk = 0; kk < DKd; kk += 8) {
            FragA a; FragBT b;
            wmma::load_matrix_sync(a, qgb + (size_t)(ti * 16) * HDK + kk, HDK); to_tf32(a);
            wmma::load_matrix_sync(b, kib + (size_t)(tj * 16) * HDK + kk, HDK); to_tf32(b);
            wmma::mma_sync(acc, a, b, acc);
        }
        wmma::store_matrix_sync(&As[(ti * 16) * 72 + tj * 16], acc, 72, wmma::mem_row_major);
    }
    __syncthreads();
    // causal mask (keep j<=i)
    for (int i = tid; i < 64 * 64; i += 256) {
        int r = i >> 6, cc = i & 63;
        if (cc > r) As[r * 72 + cc] = 0.0f;
    }
    __syncthreads();

    // ---- o_intra = As(64x64) @ v(64x256) ----
    {
        int ti = w >> 1, tjb = (w & 1) * 8;
        FragC acc2[8];
#pragma unroll
        for (int j = 0; j < 8; j++) wmma::fill_fragment(acc2[j], 0.0f);
#pragma unroll
        for (int kk = 0; kk < CH; kk += 8) {
            FragA a;
            wmma::load_matrix_sync(a, &As[(ti * 16) * 72 + kk], 72); to_tf32(a);
#pragma unroll
            for (int j = 0; j < 8; j++) {
                FragB b;
                wmma::load_matrix_sync(b, vb + (size_t)kk * HDV + (tjb + j) * 16, HDV); to_tf32(b);
                wmma::mma_sync(acc2[j], a, b, acc2[j]);
            }
        }
#pragma unroll
        for (int j = 0; j < 8; j++)
            wmma::store_matrix_sync(ob + (size_t)(ti * 16) * HDV + (tjb + j) * 16,
                                    acc2[j], HDV, wmma::mem_row_major);
    }

    // ---- U = kg^T(128x64) @ v(64x256), warp owns 16-row band, 2 halves of 8 col-tiles ----
#pragma unroll
    for (int half = 0; half < 2; half++) {
        FragC acc3[8];
#pragma unroll
        for (int j = 0; j < 8; j++) wmma::fill_fragment(acc3[j], 0.0f);
#pragma unroll
        for (int kk = 0; kk < CH; kk += 8) {
            FragAT a;
            wmma::load_matrix_sync(a, kgb + (size_t)kk * HDK + w * 16, HDK); to_tf32(a);
#pragma unroll
            for (int j = 0; j < 8; j++) {
                int nj = half * 8 + j;
                FragB b;
                wmma::load_matrix_sync(b, vb + (size_t)kk * HDV + nj * 16, HDV); to_tf32(b);
                wmma::mma_sync(acc3[j], a, b, acc3[j]);
            }
        }
#pragma unroll
        for (int j = 0; j < 8; j++)
            wmma::store_matrix_sync(Ub + (size_t)(w * 16) * DVd + (half * 8 + j) * 16,
                                    acc3[j], DVd, wmma::mem_row_major);
    }
}

// ---------------- chunk-state scan (in-place U_n -> S_{n-1}) ----------------
// grid: B*H*8 = 128 CTAs (each owns 16 dk rows x 256 dv), block 256 (thread = dv)
__global__ __launch_bounds__(256) void scan_kernel(
    float* __restrict__ S, const float* __restrict__ glast)
{
    int id = blockIdx.x;
    int bh = id >> 3, dkb = id & 7;
    int b = bh >> 2, h = bh & 3;
    int dk0 = dkb * 16;
    int dv = threadIdx.x;
    float s[16];
#pragma unroll
    for (int r = 0; r < 16; r++) s[r] = 0.0f;
    for (int n = 0; n < NC; n++) {
        int c = b * NC + n;
        size_t chbase = ((size_t)(c * HH + h)) * DKd * DVd;
        const float* gl = glast + (size_t)c * HDK + h * DKd + dk0;
#pragma unroll
        for (int r = 0; r < 16; r++) {
            size_t a = chbase + (size_t)(dk0 + r) * DVd + dv;
            float u = S[a];
            S[a] = s[r];                 // state BEFORE chunk n
            s[r] = s[r] * gl[r] + u;     // state AFTER chunk n
        }
    }
}

// ---------------- inter-chunk: o += qg @ S_{n-1} (64x256, K=128) ----------------
__global__ __launch_bounds__(256) void gla_inter_kernel(
    const float* __restrict__ qg, const float* __restrict__ S, float* __restrict__ o)
{
    const int ch = blockIdx.x;
    const int c = ch >> 2;
    const int h = ch & 3;
    const size_t t0 = (size_t)c * CH;
    const float* qgb = qg + t0 * HDK + h * DKd;
    const float* Sb = S + (size_t)ch * DKd * DVd;   // ld DVd
    float* ob = o + t0 * HDV + h * DVd;

    const int w = threadIdx.x >> 5;
    const int ti = w >> 1, tjb = (w & 1) * 8;

    FragC acc[8];
#pragma unroll
    for (int j = 0; j < 8; j++)
        wmma::load_matrix_sync(acc[j], ob + (size_t)(ti * 16) * HDV + (tjb + j) * 16,
                               HDV, wmma::mem_row_major);
#pragma unroll
    for (int kk = 0; kk < DKd; kk += 8) {
        FragA a;
        wmma::load_matrix_sync(a, qgb + (size_t)(ti * 16) * HDK + kk, HDK); to_tf32(a);
#pragma unroll
        for (int j = 0; j < 8; j++) {
            FragB b;
            wmma::load_matrix_sync(b, Sb + (size_t)kk * DVd + (tjb + j) * 16, DVd); to_tf32(b);
            wmma::mma_sync(acc[j], a, b, acc[j]);
        }
    }
#pragma unroll
    for (int j = 0; j < 8; j++)
        wmma::store_matrix_sync(ob + (size_t)(ti * 16) * HDV + (tjb + j) * 16,
                                acc[j], HDV, wmma::mem_row_major);
}

// ---------------- gated RMSNorm: y = RMSNorm(o)*gnw * g*sigmoid(g) ----------------
__global__ __launch_bounds__(256) void norm_gate_kernel(
    const float* __restrict__ o, const float* __restrict__ g,
    const float* __restrict__ gnw, float* __restrict__ y)
{
    int row = blockIdx.x * 8 + (threadIdx.x >> 5);  // token-head row, 0..32767
    int lane = threadIdx.x & 31;
    size_t base = (size_t)row * DVd;
    float v[8];
    float ss = 0.0f;
#pragma unroll
    for (int j = 0; j < 8; j++) {
        v[j] = o[base + lane + j * 32];
        ss += v[j] * v[j];
    }
#pragma unroll
    for (int off = 16; off > 0; off >>= 1)
        ss += __shfl_xor_sync(0xffffffff, ss, off);
    float r = rsqrtf(ss * (1.0f / DVd) + EPS);
#pragma unroll
    for (int j = 0; j < 8; j++) {
        int dv = lane + j * 32;
        float gv = g[base + dv];
        float sw = gv / (1.0f + expf(-gv));   // swish
        y[base + dv] = v[j] * r * gnw[dv] * sw;
    }
}

// ---------------- launch ----------------
extern "C" void kernel_launch(void* const* d_in, const int* in_sizes, int n_in,
                              void* d_out, int out_size)
{
    const float* x    = (const float*)d_in[0];
    const float* Wq   = (const float*)d_in[1];
    const float* Wk   = (const float*)d_in[2];
    const float* Wv   = (const float*)d_in[3];
    const float* Wg   = (const float*)d_in[4];
    const float* Wgk1 = (const float*)d_in[5];
    const float* Wgk2 = (const float*)d_in[6];
    const float* bgk2 = (const float*)d_in[7];
    const float* Wo   = (const float*)d_in[8];
    const float* gnw  = (const float*)d_in[9];
    float* out = (float*)d_out;

    float *q, *k, *v, *g, *gk, *x1, *qg, *kint, *kg, *glast, *S, *o, *y;
    cudaGetSymbolAddress((void**)&q, d_q);
    cudaGetSymbolAddress((void**)&k, d_k);
    cudaGetSymbolAddress((void**)&v, d_v);
    cudaGetSymbolAddress((void**)&g, d_g);
    cudaGetSymbolAddress((void**)&gk, d_gk);
    cudaGetSymbolAddress((void**)&x1, d_x1);
    cudaGetSymbolAddress((void**)&qg, d_qg);
    cudaGetSymbolAddress((void**)&kint, d_kint);
    cudaGetSymbolAddress((void**)&kg, d_kg);
    cudaGetSymbolAddress((void**)&glast, d_glast);
    cudaGetSymbolAddress((void**)&S, d_S);
    cudaGetSymbolAddress((void**)&o, d_o);
    cudaGetSymbolAddress((void**)&y, d_y);

    // input projections (tf32 wmma GEMMs)
    gemm_tf32_kernel<<<dim3(HDK / 128, BT / 128), 256>>>(x, Wq, q, BT, HDK, DM);
    gemm_tf32_kernel<<<dim3(HDK / 128, BT / 128), 256>>>(x, Wk, k, BT, HDK, DM);
    gemm_tf32_kernel<<<dim3(HDV / 128, BT / 128), 256>>>(x, Wv, v, BT, HDV, DM);
    gemm_tf32_kernel<<<dim3(HDV / 128, BT / 128), 256>>>(x, Wg, g, BT, HDV, DM);

    // low-rank gate path (exact fp32)
    gk1_kernel<<<BT / 8, 256>>>(x, Wgk1, x1);
    gk2_kernel<<<(BT * HDK) / 256, 256>>>(x1, Wgk2, bgk2, gk);

    // decay factors
    decay_prep_kernel<<<NCHUNK, 512>>>(q, k, gk, qg, kint, kg, glast);

    // chunkwise GLA
    gla_intra_kernel<<<NCH, 256>>>(qg, kint, kg, v, o, S);
    scan_kernel<<<BB * HH * 8, 256>>>(S, glast);
    gla_inter_kernel<<<NCH, 256>>>(qg, S, o);

    // gated RMSNorm + output projection
    norm_gate_kernel<<<(BT * HH) / 8, 256>>>(o, g, gnw, y);
    gemm_tf32_kernel<<<dim3(DM / 128, BT / 128), 256>>>(y, Wo, out, BT, DM, DM);
}

// round 2
// speedup vs baseline: 1.1439x; 1.1439x over previous
#include <cuda_runtime.h>
#include <cuda_bf16.h>
#include <mma.h>
#include <cstdint>

using namespace nvcuda;

// ---------------- problem constants ----------------
#define BB 4
#define TT 2048
#define DM 1024
#define HH 4
#define DKd 128
#define DVd 256
#define HDK 512     // H*DK
#define HDV 1024    // H*DV
#define BT  8192    // B*T tokens
#define CH  64      // chunk
#define NC  32      // chunks per sequence
#define NCHUNK 128  // total chunks (B*NC)
#define NCH 512     // chunk-heads (NCHUNK*H)
#define LR 16       // gate low rank
#define GNORM 16.0f
#define EPS 1e-5f

// ---------------- scratch (device globals; no allocation allowed) ----------------
__device__ float d_q   [BT * HDK];
__device__ float d_k   [BT * HDK];
__device__ float d_v   [BT * HDV];
__device__ float d_g   [BT * HDV];
__device__ float d_gk  [BT * HDK];
__device__ float d_x1  [BT * LR];
__device__ float d_qg  [BT * HDK];
__device__ float d_kint[BT * HDK];
__device__ float d_kg  [BT * HDK];
__device__ float d_glast[NCHUNK * HDK];
__device__ float d_S   [NCH * DKd * DVd];
__device__ float d_o   [BT * HDV];
__device__ float d_y   [BT * HDV];

// ---------------- helpers ----------------
template <typename Frag>
__device__ __forceinline__ void to_tf32(Frag& f) {
#pragma unroll
    for (int i = 0; i < f.num_elements; i++) f.x[i] = wmma::__float_to_tf32(f.x[i]);
}

typedef wmma::fragment<wmma::matrix_a, 16, 16, 8, wmma::precision::tf32, wmma::row_major> FragA;
typedef wmma::fragment<wmma::matrix_a, 16, 16, 8, wmma::precision::tf32, wmma::col_major> FragAT;
typedef wmma::fragment<wmma::matrix_b, 16, 16, 8, wmma::precision::tf32, wmma::row_major> FragB;
typedef wmma::fragment<wmma::matrix_b, 16, 16, 8, wmma::precision::tf32, wmma::col_major> FragBT;
typedef wmma::fragment<wmma::accumulator, 16, 16, 8, float> FragC;

__device__ __forceinline__ uint32_t smem_u32(const void* p) {
    return (uint32_t)__cvta_generic_to_shared(p);
}
__device__ __forceinline__ void cpasync16(float* dst, const float* src) {
    asm volatile("cp.async.cg.shared.global [%0], [%1], 16;\n"
                 :: "r"(smem_u32(dst)), "l"(src));
}
__device__ __forceinline__ void cp_commit() {
    asm volatile("cp.async.commit_group;\n");
}

// ---------------- double-buffered tf32 GEMM core: 128x128 tile, BK=16 ----------------
// smem: As[2][128*20] + Bs[2][16*132]  (9344 floats = 37376 B)
#define AS_STRIDE 20
#define BS_STRIDE 132
#define GEMM_SMEM_FLOATS (2 * 128 * AS_STRIDE + 2 * 16 * BS_STRIDE)

__device__ __forceinline__ void gemm128x128_core(
    const float* __restrict__ A, int lda,     // 128 rows of A
    const float* __restrict__ B, int ldb,     // K x 128 tile of B
    float* __restrict__ C, int ldc,           // 128x128 tile of C
    int K, float* sm)
{
    const int tid = threadIdx.x;
    const int w = tid >> 5;
    const int wr = w >> 1;     // 0..3
    const int wc = w & 1;      // 0..1

    float* As0 = sm;
    float* As1 = sm + 128 * AS_STRIDE;
    float* Bs0 = sm + 2 * 128 * AS_STRIDE;
    float* Bs1 = Bs0 + 16 * BS_STRIDE;
    float* Asb[2] = {As0, As1};
    float* Bsb[2] = {Bs0, Bs1};

    FragC acc[2][4];
#pragma unroll
    for (int r = 0; r < 2; r++)
#pragma unroll
        for (int c = 0; c < 4; c++) wmma::fill_fragment(acc[r][c], 0.0f);

    const int ntiles = K / 16;

    // issue tile 0
    {
        const float* Ab = A;
        const float* Bb = B;
#pragma unroll
        for (int i = tid; i < 512; i += 256) {
            int r = i >> 2, c4 = i & 3;
            cpasync16(&As0[r * AS_STRIDE + c4 * 4], Ab + (size_t)r * lda + c4 * 4);
        }
#pragma unroll
        for (int i = tid; i < 512; i += 256) {
            int r = i >> 5, c = i & 31;
            cpasync16(&Bs0[r * BS_STRIDE + c * 4], Bb + (size_t)r * ldb + c * 4);
        }
        cp_commit();
    }

    for (int it = 0; it < ntiles; it++) {
        const int buf = it & 1;
        if (it + 1 < ntiles) {
            float* Asn = Asb[buf ^ 1];
            float* Bsn = Bsb[buf ^ 1];
            const float* Ab = A + (it + 1) * 16;
            const float* Bb = B + (size_t)(it + 1) * 16 * ldb;
#pragma unroll
            for (int i = tid; i < 512; i += 256) {
                int r = i >> 2, c4 = i & 3;
                cpasync16(&Asn[r * AS_STRIDE + c4 * 4], Ab + (size_t)r * lda + c4 * 4);
            }
#pragma unroll
            for (int i = tid; i < 512; i += 256) {
                int r = i >> 5, c = i & 31;
                cpasync16(&Bsn[r * BS_STRIDE + c * 4], Bb + (size_t)r * ldb + c * 4);
            }
            cp_commit();
            asm volatile("cp.async.wait_group 1;\n");
        } else {
            asm volatile("cp.async.wait_group 0;\n");
        }
        __syncthreads();

        float* Ac = Asb[buf];
        float* Bc = Bsb[buf];
#pragma unroll
        for (int kk = 0; kk < 16; kk += 8) {
            FragA af[2];
            FragB bf[4];
#pragma unroll
            for (int r = 0; r < 2; r++) {
                wmma::load_matrix_sync(af[r], &Ac[(wr * 32 + r * 16) * AS_STRIDE + kk], AS_STRIDE);
                to_tf32(af[r]);
            }
#pragma unroll
            for (int c = 0; c < 4; c++) {
                wmma::load_matrix_sync(bf[c], &Bc[kk * BS_STRIDE + wc * 64 + c * 16], BS_STRIDE);
                to_tf32(bf[c]);
            }
#pragma unroll
            for (int r = 0; r < 2; r++)
#pragma unroll
                for (int c = 0; c < 4; c++)
                    wmma::mma_sync(acc[r][c], af[r], bf[c], acc[r][c]);
        }
        __syncthreads();
    }

#pragma unroll
    for (int r = 0; r < 2; r++)
#pragma unroll
        for (int c = 0; c < 4; c++)
            wmma::store_matrix_sync(
                C + (size_t)(wr * 32 + r * 16) * ldc + wc * 64 + c * 16,
                acc[r][c], ldc, wmma::mem_row_major);
}

// ---------------- fused q/k/v/g projections in ONE launch ----------------
// grid.x: 0..3 -> Wq, 4..7 -> Wk, 8..15 -> Wv, 16..23 -> Wg; grid.y = BT/128
__global__ __launch_bounds__(256) void proj_qkvg_kernel(
    const float* __restrict__ x,
    const float* __restrict__ Wq, const float* __restrict__ Wk,
    const float* __restrict__ Wv, const float* __restrict__ Wg,
    float* __restrict__ q, float* __restrict__ k,
    float* __restrict__ v, float* __restrict__ g)
{
    __shared__ float sm[GEMM_SMEM_FLOATS];
    const int bn = blockIdx.x;
    const int bm = blockIdx.y;
    const float* B;
    float* C;
    int n0, ldn;
    if (bn < 4)       { B = Wq; C = q; n0 = bn;      ldn = HDK; }
    else if (bn < 8)  { B = Wk; C = k; n0 = bn - 4;  ldn = HDK; }
    else if (bn < 16) { B = Wv; C = v; n0 = bn - 8;  ldn = HDV; }
    else              { B = Wg; C = g; n0 = bn - 16; ldn = HDV; }
    gemm128x128_core(x + (size_t)bm * 128 * DM, DM,
                     B + n0 * 128, ldn,
                     C + (size_t)bm * 128 * ldn + n0 * 128, ldn,
                     DM, sm);
}

// ---------------- output projection: out = y @ Wo ----------------
__global__ __launch_bounds__(256) void gemm_wo_kernel(
    const float* __restrict__ y, const float* __restrict__ Wo, float* __restrict__ out)
{
    __shared__ float sm[GEMM_SMEM_FLOATS];
    const int bn = blockIdx.x, bm = blockIdx.y;
    gemm128x128_core(y + (size_t)bm * 128 * HDV, HDV,
                     Wo + bn * 128, DM,
                     out + (size_t)bm * 128 * DM + bn * 128,
                     DM, HDV, sm);
}

// ---------------- low-rank gate: x1 = x @ Wgk1 (K=1024, N=16) ----------------
__global__ __launch_bounds__(256) void gk1_kernel(
    const float* __restrict__ x, const float* __restrict__ W, float* __restrict__ x1)
{
    int t = blockIdx.x * 8 + (threadIdx.x >> 5);
    int lane = threadIdx.x & 31;
    if (t >= BT) return;
    const float* xr = x + (size_t)t * DM;
    float acc[LR];
#pragma unroll
    for (int n = 0; n < LR; n++) acc[n] = 0.0f;
    for (int j = lane; j < DM; j += 32) {
        float xv = xr[j];
        const float* wr = W + (size_t)j * LR;
#pragma unroll
        for (int n = 0; n < LR; n++) acc[n] += xv * wr[n];
    }
#pragma unroll
    for (int n = 0; n < LR; n++) {
#pragma unroll
        for (int off = 16; off > 0; off >>= 1)
            acc[n] += __shfl_xor_sync(0xffffffff, acc[n], off);
    }
    if (lane == 0) {
#pragma unroll
        for (int n = 0; n < LR; n++) x1[(size_t)t * LR + n] = acc[n];
    }
}

// ---------------- gk = log_sigmoid(x1 @ Wgk2 + b) / 16 ----------------
__global__ __launch_bounds__(256) void gk2_kernel(
    const float* __restrict__ x1, const float* __restrict__ W2,
    const float* __restrict__ bias, float* __restrict__ gk)
{
    int idx = blockIdx.x * 256 + threadIdx.x;
    if (idx >= BT * HDK) return;
    int t = idx >> 9;
    int n = idx & 511;
    const float* xr = x1 + (size_t)t * LR;
    float a = bias[n];
#pragma unroll
    for (int kx = 0; kx < LR; kx++) a += xr[kx] * W2[kx * HDK + n];
    float ls = fminf(a, 0.0f) - log1pf(expf(-fabsf(a)));
    gk[idx] = ls * (1.0f / GNORM);
}

// ---------------- decay prep ----------------
__global__ __launch_bounds__(512) void decay_prep_kernel(
    const float* __restrict__ q, const float* __restrict__ k, const float* __restrict__ gk,
    float* __restrict__ qg, float* __restrict__ kint, float* __restrict__ kg,
    float* __restrict__ glast)
{
    int c = blockIdx.x;
    int col = threadIdx.x;
    size_t base = (size_t)c * CH * HDK + col;
    float tot = 0.0f;
#pragma unroll 8
    for (int i = 0; i < CH; i++) tot += gk[base + (size_t)i * HDK];
    glast[(size_t)c * HDK + col] = expf(tot);
    const float scale = 0.088388347648318447f;   // 128^-0.5
    float run = 0.0f;
    for (int i = 0; i < CH; i++) {
        size_t idx = base + (size_t)i * HDK;
        run += gk[idx];
        qg[idx]   = q[idx] * expf(run) * scale;
        kint[idx] = k[idx] * expf(-run);
        kg[idx]   = k[idx] * expf(tot - run);
    }
}

// ---------------- intra-chunk: A=tril(qg kint^T); o=A v; U=kg^T v ----------------
// dynamic smem: Vs[64*260] + As[64*72]  (84992 bytes)
#define VS_STRIDE 260
#define INTRA_SMEM_BYTES ((64 * VS_STRIDE + 64 * 72) * 4)

__global__ __launch_bounds__(256) void gla_intra_kernel(
    const float* __restrict__ qg, const float* __restrict__ kint,
    const float* __restrict__ kg, const float* __restrict__ v,
    float* __restrict__ o, float* __restrict__ U)
{
    extern __shared__ float sm[];
    float* Vs = sm;                 // 64 x 260
    float* As = sm + 64 * VS_STRIDE; // 64 x 72

    const int ch = blockIdx.x;
    const int c = ch >> 2;
    const int h = ch & 3;
    const size_t t0 = (size_t)c * CH;

    const float* qgb = qg   + t0 * HDK + h * DKd;
    const float* kib = kint + t0 * HDK + h * DKd;
    const float* kgb = kg   + t0 * HDK + h * DKd;
    const float* vb  = v    + t0 * HDV + h * DVd;
    float* ob = o + t0 * HDV + h * DVd;
    float* Ub = U + (size_t)ch * DKd * DVd;

    const int tid = threadIdx.x;
    const int w = tid >> 5;

    // stage v tile (64x256) into smem
#pragma unroll
    for (int i = tid; i < 64 * 64; i += 256) {
        int r = i >> 6, c4 = i & 63;
        *(float4*)&Vs[r * VS_STRIDE + c4 * 4] =
            *(const float4*)&vb[(size_t)r * HDV + c4 * 4];
    }

    // ---- A = qg @ kint^T (64x64, K=128), 16 tiles, 2 per warp ----
#pragma unroll
    for (int tIdx = w * 2; tIdx < w * 2 + 2; tIdx++) {
        int ti = tIdx >> 2, tj = tIdx & 3;
        FragC acc;
        wmma::fill_fragment(acc, 0.0f);
#pragma unroll
        for (int kk = 0; kk < DKd; kk += 8) {
            FragA a; FragBT b;
            wmma::load_matrix_sync(a, qgb + (size_t)(ti * 16) * HDK + kk, HDK); to_tf32(a);
            wmma::load_matrix_sync(b, kib + (size_t)(tj * 16) * HDK + kk, HDK); to_tf32(b);
            wmma::mma_sync(acc, a, b, acc);
        }
        wmma::store_matrix_sync(&As[(ti * 16) * 72 + tj * 16], acc, 72, wmma::mem_row_major);
    }
    __syncthreads();
    // causal mask
    for (int i = tid; i < 64 * 64; i += 256) {
        int r = i >> 6, cc = i & 63;
        if (cc > r) As[r * 72 + cc] = 0.0f;
    }
    __syncthreads();

    // ---- o_intra = As(64x64) @ Vs(64x256) ----
    {
        int ti = w >> 1, tjb = (w & 1) * 8;
        FragC acc2[8];
#pragma unroll
        for (int j = 0; j < 8; j++) wmma::fill_fragment(acc2[j], 0.0f);
#pragma unroll
        for (int kk = 0; kk < CH; kk += 8) {
            FragA a;
            wmma::load_matrix_sync(a, &As[(ti * 16) * 72 + kk], 72); to_tf32(a);
#pragma unroll
            for (int j = 0; j < 8; j++) {
                FragB b;
                wmma::load_matrix_sync(b, &Vs[kk * VS_STRIDE + (tjb + j) * 16], VS_STRIDE); to_tf32(b);
                wmma::mma_sync(acc2[j], a, b, acc2[j]);
            }
        }
#pragma unroll
        for (int j = 0; j < 8; j++)
            wmma::store_matrix_sync(ob + (size_t)(ti * 16) * HDV + (tjb + j) * 16,
                                    acc2[j], HDV, wmma::mem_row_major);
    }

    // ---- U = kg^T(128x64) @ Vs(64x256) ----
#pragma unroll
    for (int half = 0; half < 2; half++) {
        FragC acc3[8];
#pragma unroll
        for (int j = 0; j < 8; j++) wmma::fill_fragment(acc3[j], 0.0f);
#pragma unroll
        for (int kk = 0; kk < CH; kk += 8) {
            FragAT a;
            wmma::load_matrix_sync(a, kgb + (size_t)kk * HDK + w * 16, HDK); to_tf32(a);
#pragma unroll
            for (int j = 0; j < 8; j++) {
                int nj = half * 8 + j;
                FragB b;
                wmma::load_matrix_sync(b, &Vs[kk * VS_STRIDE + nj * 16], VS_STRIDE); to_tf32(b);
                wmma::mma_sync(acc3[j], a, b, acc3[j]);
            }
        }
#pragma unroll
        for (int j = 0; j < 8; j++)
            wmma::store_matrix_sync(Ub + (size_t)(w * 16) * DVd + (half * 8 + j) * 16,
                                    acc3[j], DVd, wmma::mem_row_major);
    }
}

// ---------------- chunk-state scan (in-place U_n -> S_{n-1}) ----------------
__global__ __launch_bounds__(256) void scan_kernel(
    float* __restrict__ S, const float* __restrict__ glast)
{
    int id = blockIdx.x;
    int bh = id >> 3, dkb = id & 7;
    int b = bh >> 2, h = bh & 3;
    int dk0 = dkb * 16;
    int dv = threadIdx.x;
    float s[16];
#pragma unroll
    for (int r = 0; r < 16; r++) s[r] = 0.0f;
    for (int n = 0; n < NC; n++) {
        int c = b * NC + n;
        size_t chbase = ((size_t)(c * HH + h)) * DKd * DVd;
        const float* gl = glast + (size_t)c * HDK + h * DKd + dk0;
#pragma unroll
        for (int r = 0; r < 16; r++) {
            size_t a = chbase + (size_t)(dk0 + r) * DVd + dv;
            float u = S[a];
            S[a] = s[r];
            s[r] = s[r] * gl[r] + u;
        }
    }
}

// ---------------- inter-chunk: o += qg @ S_{n-1} ----------------
__global__ __launch_bounds__(256) void gla_inter_kernel(
    const float* __restrict__ qg, const float* __restrict__ S, float* __restrict__ o)
{
    const int ch = blockIdx.x;
    const int c = ch >> 2;
    const int h = ch & 3;
    const size_t t0 = (size_t)c * CH;
    const float* qgb = qg + t0 * HDK + h * DKd;
    const float* Sb = S + (size_t)ch * DKd * DVd;
    float* ob = o + t0 * HDV + h * DVd;

    const int w = threadIdx.x >> 5;
    const int ti = w >> 1, tjb = (w & 1) * 8;

    FragC acc[8];
#pragma unroll
    for (int j = 0; j < 8; j++)
        wmma::load_matrix_sync(acc[j], ob + (size_t)(ti * 16) * HDV + (tjb + j) * 16,
                               HDV, wmma::mem_row_major);
#pragma unroll
    for (int kk = 0; kk < DKd; kk += 8) {
        FragA a;
        wmma::load_matrix_sync(a, qgb + (size_t)(ti * 16) * HDK + kk, HDK); to_tf32(a);
#pragma unroll
        for (int j = 0; j < 8; j++) {
            FragB b;
            wmma::load_matrix_sync(b, Sb + (size_t)kk * DVd + (tjb + j) * 16, DVd); to_tf32(b);
            wmma::mma_sync(acc[j], a, b, acc[j]);
        }
    }
#pragma unroll
    for (int j = 0; j < 8; j++)
        wmma::store_matrix_sync(ob + (size_t)(ti * 16) * HDV + (tjb + j) * 16,
                                acc[j], HDV, wmma::mem_row_major);
}

// ---------------- gated RMSNorm ----------------
__global__ __launch_bounds__(256) void norm_gate_kernel(
    const float* __restrict__ o, const float* __restrict__ g,
    const float* __restrict__ gnw, float* __restrict__ y)
{
    int row = blockIdx.x * 8 + (threadIdx.x >> 5);
    int lane = threadIdx.x & 31;
    size_t base = (size_t)row * DVd;
    float v[8];
    float ss = 0.0f;
#pragma unroll
    for (int j = 0; j < 8; j++) {
        v[j] = o[base + lane + j * 32];
        ss += v[j] * v[j];
    }
#pragma unroll
    for (int off = 16; off > 0; off >>= 1)
        ss += __shfl_xor_sync(0xffffffff, ss, off);
    float r = rsqrtf(ss * (1.0f / DVd) + EPS);
#pragma unroll
    for (int j = 0; j < 8; j++) {
        int dv = lane + j * 32;
        float gv = g[base + dv];
        float sw = gv / (1.0f + expf(-gv));
        y[base + dv] = v[j] * r * gnw[dv] * sw;
    }
}

// ---------------- launch ----------------
extern "C" void kernel_launch(void* const* d_in, const int* in_sizes, int n_in,
                              void* d_out, int out_size)
{
    const float* x    = (const float*)d_in[0];
    const float* Wq   = (const float*)d_in[1];
    const float* Wk   = (const float*)d_in[2];
    const float* Wv   = (const float*)d_in[3];
    const float* Wg   = (const float*)d_in[4];
    const float* Wgk1 = (const float*)d_in[5];
    const float* Wgk2 = (const float*)d_in[6];
    const float* bgk2 = (const float*)d_in[7];
    const float* Wo   = (const float*)d_in[8];
    const float* gnw  = (const float*)d_in[9];
    float* out = (float*)d_out;

    float *q, *k, *v, *g, *gk, *x1, *qg, *kint, *kg, *glast, *S, *o, *y;
    cudaGetSymbolAddress((void**)&q, d_q);
    cudaGetSymbolAddress((void**)&k, d_k);
    cudaGetSymbolAddress((void**)&v, d_v);
    cudaGetSymbolAddress((void**)&g, d_g);
    cudaGetSymbolAddress((void**)&gk, d_gk);
    cudaGetSymbolAddress((void**)&x1, d_x1);
    cudaGetSymbolAddress((void**)&qg, d_qg);
    cudaGetSymbolAddress((void**)&kint, d_kint);
    cudaGetSymbolAddress((void**)&kg, d_kg);
    cudaGetSymbolAddress((void**)&glast, d_glast);
    cudaGetSymbolAddress((void**)&S, d_S);
    cudaGetSymbolAddress((void**)&o, d_o);
    cudaGetSymbolAddress((void**)&y, d_y);

    static bool attr_done = false;
    if (!attr_done) {
        cudaFuncSetAttribute(gla_intra_kernel,
                             cudaFuncAttributeMaxDynamicSharedMemorySize, INTRA_SMEM_BYTES);
        attr_done = true;
    }

    // fused input projections (q,k,v,g) — one launch, 1536 CTAs
    proj_qkvg_kernel<<<dim3(24, BT / 128), 256>>>(x, Wq, Wk, Wv, Wg, q, k, v, g);

    // low-rank gate path (exact fp32)
    gk1_kernel<<<BT / 8, 256>>>(x, Wgk1, x1);
    gk2_kernel<<<(BT * HDK) / 256, 256>>>(x1, Wgk2, bgk2, gk);

    // decay factors
    decay_prep_kernel<<<NCHUNK, 512>>>(q, k, gk, qg, kint, kg, glast);

    // chunkwise GLA
    gla_intra_kernel<<<NCH, 256, INTRA_SMEM_BYTES>>>(qg, kint, kg, v, o, S);
    scan_kernel<<<BB * HH * 8, 256>>>(S, glast);
    gla_inter_kernel<<<NCH, 256>>>(qg, S, o);

    // gated RMSNorm + output projection
    norm_gate_kernel<<<(BT * HH) / 8, 256>>>(o, g, gnw, y);
    gemm_wo_kernel<<<dim3(DM / 128, BT / 128), 256>>>(y, Wo, out);
}

// round 3
// speedup vs baseline: 1.1837x; 1.0348x over previous
#include <cuda_runtime.h>
#include <cuda_bf16.h>
#include <mma.h>
#include <cstdint>

using namespace nvcuda;

// ---------------- problem constants ----------------
#define BB 4
#define TT 2048
#define DM 1024
#define HH 4
#define DKd 128
#define DVd 256
#define HDK 512     // H*DK
#define HDV 1024    // H*DV
#define BT  8192    // B*T tokens
#define CH  64      // chunk
#define NC  32      // chunks per sequence
#define NCHUNK 128  // total chunks (B*NC)
#define LR 16       // gate low rank
#define GNORM 16.0f
#define EPS 1e-5f

// ---------------- scratch (device globals; no allocation allowed) ----------------
__device__ float d_q   [BT * HDK];
__device__ float d_k   [BT * HDK];
__device__ float d_v   [BT * HDV];
__device__ float d_g   [BT * HDV];
__device__ float d_gk  [BT * HDK];
__device__ float d_x1  [BT * LR];
__device__ float d_qg  [BT * HDK];
__device__ float d_kint[BT * HDK];
__device__ float d_kg  [BT * HDK];
__device__ float d_glast[NCHUNK * HDK];
__device__ float d_o   [BT * HDV];
__device__ float d_y   [BT * HDV];

// ---------------- helpers ----------------
template <typename Frag>
__device__ __forceinline__ void to_tf32(Frag& f) {
#pragma unroll
    for (int i = 0; i < f.num_elements; i++) f.x[i] = wmma::__float_to_tf32(f.x[i]);
}

typedef wmma::fragment<wmma::matrix_a, 16, 16, 8, wmma::precision::tf32, wmma::row_major> FragA;
typedef wmma::fragment<wmma::matrix_a, 16, 16, 8, wmma::precision::tf32, wmma::col_major> FragAT;
typedef wmma::fragment<wmma::matrix_b, 16, 16, 8, wmma::precision::tf32, wmma::row_major> FragB;
typedef wmma::fragment<wmma::matrix_b, 16, 16, 8, wmma::precision::tf32, wmma::col_major> FragBT;
typedef wmma::fragment<wmma::accumulator, 16, 16, 8, float> FragC;

__device__ __forceinline__ uint32_t smem_u32(const void* p) {
    return (uint32_t)__cvta_generic_to_shared(p);
}
__device__ __forceinline__ void cpasync16(float* dst, const float* src) {
    asm volatile("cp.async.cg.shared.global [%0], [%1], 16;\n"
                 :: "r"(smem_u32(dst)), "l"(src));
}
__device__ __forceinline__ void cp_commit() {
    asm volatile("cp.async.commit_group;\n");
}

// ---------------- 3-stage pipelined tf32 GEMM core: 128x128 tile, BK=16 ----------------
#define AS_STRIDE 20
#define BS_STRIDE 132
#define STAGE_FLOATS (128 * AS_STRIDE + 16 * BS_STRIDE)  // 4672
#define GEMM_SMEM_BYTES (3 * STAGE_FLOATS * 4)           // 56064

__device__ __forceinline__ void gemm_load_tile(
    float* sm, int buf, const float* A, int lda, const float* B, int ldb, int it, int tid)
{
    float* As = sm + buf * STAGE_FLOATS;
    float* Bs = As + 128 * AS_STRIDE;
    const float* Ab = A + it * 16;
    const float* Bb = B + (size_t)it * 16 * ldb;
#pragma unroll
    for (int i = tid; i < 512; i += 256) {
        int r = i >> 2, c4 = i & 3;
        cpasync16(&As[r * AS_STRIDE + c4 * 4], Ab + (size_t)r * lda + c4 * 4);
    }
#pragma unroll
    for (int i = tid; i < 512; i += 256) {
        int r = i >> 5, c = i & 31;
        cpasync16(&Bs[r * BS_STRIDE + c * 4], Bb + (size_t)r * ldb + c * 4);
    }
    cp_commit();
}

__device__ __forceinline__ void gemm128x128_core(
    const float* __restrict__ A, int lda,
    const float* __restrict__ B, int ldb,
    float* __restrict__ C, int ldc,
    int K, float* sm)
{
    const int tid = threadIdx.x;
    const int w = tid >> 5;
    const int wr = w >> 1;     // 0..3
    const int wc = w & 1;      // 0..1

    FragC acc[2][4];
#pragma unroll
    for (int r = 0; r < 2; r++)
#pragma unroll
        for (int c = 0; c < 4; c++) wmma::fill_fragment(acc[r][c], 0.0f);

    const int ntiles = K / 16;

    gemm_load_tile(sm, 0, A, lda, B, ldb, 0, tid);
    gemm_load_tile(sm, 1, A, lda, B, ldb, 1, tid);

    for (int it = 0; it < ntiles; it++) {
        if (it < ntiles - 1) {
            asm volatile("cp.async.wait_group 1;\n");
        } else {
            asm volatile("cp.async.wait_group 0;\n");
        }
        __syncthreads();
        if (it + 2 < ntiles)
            gemm_load_tile(sm, (it + 2) % 3, A, lda, B, ldb, it + 2, tid);

        float* Ac = sm + (it % 3) * STAGE_FLOATS;
        float* Bc = Ac + 128 * AS_STRIDE;
#pragma unroll
        for (int kk = 0; kk < 16; kk += 8) {
            FragA af[2];
            FragB bf[4];
#pragma unroll
            for (int r = 0; r < 2; r++) {
                wmma::load_matrix_sync(af[r], &Ac[(wr * 32 + r * 16) * AS_STRIDE + kk], AS_STRIDE);
                to_tf32(af[r]);
            }
#pragma unroll
            for (int c = 0; c < 4; c++) {
                wmma::load_matrix_sync(bf[c], &Bc[kk * BS_STRIDE + wc * 64 + c * 16], BS_STRIDE);
                to_tf32(bf[c]);
            }
#pragma unroll
            for (int r = 0; r < 2; r++)
#pragma unroll
                for (int c = 0; c < 4; c++)
                    wmma::mma_sync(acc[r][c], af[r], bf[c], acc[r][c]);
        }
    }
    __syncthreads();

#pragma unroll
    for (int r = 0; r < 2; r++)
#pragma unroll
        for (int c = 0; c < 4; c++)
            wmma::store_matrix_sync(
                C + (size_t)(wr * 32 + r * 16) * ldc + wc * 64 + c * 16,
                acc[r][c], ldc, wmma::mem_row_major);
}

// ---------------- fused q/k/v/g projections in ONE launch ----------------
__global__ __launch_bounds__(256) void proj_qkvg_kernel(
    const float* __restrict__ x,
    const float* __restrict__ Wq, const float* __restrict__ Wk,
    const float* __restrict__ Wv, const float* __restrict__ Wg,
    float* __restrict__ q, float* __restrict__ k,
    float* __restrict__ v, float* __restrict__ g)
{
    extern __shared__ float sm[];
    const int bn = blockIdx.x;
    const int bm = blockIdx.y;
    const float* B;
    float* C;
    int n0, ldn;
    if (bn < 4)       { B = Wq; C = q; n0 = bn;      ldn = HDK; }
    else if (bn < 8)  { B = Wk; C = k; n0 = bn - 4;  ldn = HDK; }
    else if (bn < 16) { B = Wv; C = v; n0 = bn - 8;  ldn = HDV; }
    else              { B = Wg; C = g; n0 = bn - 16; ldn = HDV; }
    gemm128x128_core(x + (size_t)bm * 128 * DM, DM,
                     B + n0 * 128, ldn,
                     C + (size_t)bm * 128 * ldn + n0 * 128, ldn,
                     DM, sm);
}

// ---------------- output projection: out = y @ Wo ----------------
__global__ __launch_bounds__(256) void gemm_wo_kernel(
    const float* __restrict__ y, const float* __restrict__ Wo, float* __restrict__ out)
{
    extern __shared__ float sm[];
    const int bn = blockIdx.x, bm = blockIdx.y;
    gemm128x128_core(y + (size_t)bm * 128 * HDV, HDV,
                     Wo + bn * 128, DM,
                     out + (size_t)bm * 128 * DM + bn * 128,
                     DM, HDV, sm);
}

// ---------------- low-rank gate: x1 = x @ Wgk1 ----------------
__global__ __launch_bounds__(256) void gk1_kernel(
    const float* __restrict__ x, const float* __restrict__ W, float* __restrict__ x1)
{
    int t = blockIdx.x * 8 + (threadIdx.x >> 5);
    int lane = threadIdx.x & 31;
    if (t >= BT) return;
    const float* xr = x + (size_t)t * DM;
    float acc[LR];
#pragma unroll
    for (int n = 0; n < LR; n++) acc[n] = 0.0f;
    for (int j = lane; j < DM; j += 32) {
        float xv = xr[j];
        const float* wr = W + (size_t)j * LR;
#pragma unroll
        for (int n = 0; n < LR; n++) acc[n] += xv * wr[n];
    }
#pragma unroll
    for (int n = 0; n < LR; n++) {
#pragma unroll
        for (int off = 16; off > 0; off >>= 1)
            acc[n] += __shfl_xor_sync(0xffffffff, acc[n], off);
    }
    if (lane == 0) {
#pragma unroll
        for (int n = 0; n < LR; n++) x1[(size_t)t * LR + n] = acc[n];
    }
}

// ---------------- gk = log_sigmoid(x1 @ Wgk2 + b) / 16 ----------------
__global__ __launch_bounds__(256) void gk2_kernel(
    const float* __restrict__ x1, const float* __restrict__ W2,
    const float* __restrict__ bias, float* __restrict__ gk)
{
    int idx = blockIdx.x * 256 + threadIdx.x;
    if (idx >= BT * HDK) return;
    int t = idx >> 9;
    int n = idx & 511;
    const float* xr = x1 + (size_t)t * LR;
    float a = bias[n];
#pragma unroll
    for (int kx = 0; kx < LR; kx++) a += xr[kx] * W2[kx * HDK + n];
    float ls = fminf(a, 0.0f) - log1pf(expf(-fabsf(a)));
    gk[idx] = ls * (1.0f / GNORM);
}

// ---------------- decay prep (regridded: 512 CTAs x 128 thr, __expf) ----------------
__global__ __launch_bounds__(128) void decay_prep_kernel(
    const float* __restrict__ q, const float* __restrict__ k, const float* __restrict__ gk,
    float* __restrict__ qg, float* __restrict__ kint, float* __restrict__ kg,
    float* __restrict__ glast)
{
    int c = blockIdx.x >> 2;
    int col = ((blockIdx.x & 3) << 7) + threadIdx.x;
    size_t base = (size_t)c * CH * HDK + col;
    float tot = 0.0f;
#pragma unroll 8
    for (int i = 0; i < CH; i++) tot += gk[base + (size_t)i * HDK];
    glast[(size_t)c * HDK + col] = __expf(tot);
    const float scale = 0.088388347648318447f;   // 128^-0.5
    float run = 0.0f;
#pragma unroll 4
    for (int i = 0; i < CH; i++) {
        size_t idx = base + (size_t)i * HDK;
        run += gk[idx];
        qg[idx]   = q[idx] * __expf(run) * scale;
        kint[idx] = k[idx] * __expf(-run);
        kg[idx]   = k[idx] * __expf(tot - run);
    }
}

// ---------------- FUSED chunkwise GLA (intra + state scan + inter) ----------------
// Grid: 64 CTAs = (b, h, dvb) with dvb = 64-wide dv block. S persists in smem.
#define S_STRIDE 68
#define V_STRIDE 68
#define A_STRIDE 72
#define U_STRIDE 72
#define FUSED_SMEM_FLOATS (128 * S_STRIDE + 64 * V_STRIDE + 64 * A_STRIDE + 128 * U_STRIDE + 128)
#define FUSED_SMEM_BYTES (FUSED_SMEM_FLOATS * 4)   // 108032

__global__ __launch_bounds__(256) void gla_fused_kernel(
    const float* __restrict__ qg, const float* __restrict__ kint,
    const float* __restrict__ kg, const float* __restrict__ v,
    const float* __restrict__ glast, float* __restrict__ o)
{
    extern __shared__ float sm[];
    float* Ssm = sm;                          // 128 x 68
    float* Vs  = Ssm + 128 * S_STRIDE;        // 64 x 68
    float* As  = Vs + 64 * V_STRIDE;          // 64 x 72
    float* Us  = As + 64 * A_STRIDE;          // 128 x 72
    float* sgl = Us + 128 * U_STRIDE;         // 128

    const int id = blockIdx.x;
    const int b = id >> 4, h = (id >> 2) & 3, dvb = id & 3;
    const int tid = threadIdx.x, w = tid >> 5;

    for (int i = tid; i < 128 * S_STRIDE; i += 256) Ssm[i] = 0.0f;

    for (int n = 0; n < NC; n++) {
        const int c = b * NC + n;
        const size_t t0 = (size_t)c * CH;
        const float* qgb = qg   + t0 * HDK + h * DKd;
        const float* kib = kint + t0 * HDK + h * DKd;
        const float* kgb = kg   + t0 * HDK + h * DKd;
        const float* vb  = v    + t0 * HDV + h * DVd + dvb * 64;
        float* ob        = o    + t0 * HDV + h * DVd + dvb * 64;

        __syncthreads();   // prev S-update done; Vs/sgl free

        // stage v slice (64x64) and per-chunk decay into smem
#pragma unroll
        for (int j = 0; j < 4; j++) {
            int idx = j * 256 + tid;
            int r = idx >> 4, c4 = idx & 15;
            *(float4*)&Vs[r * V_STRIDE + c4 * 4] =
                *(const float4*)&vb[(size_t)r * HDV + c4 * 4];
        }
        if (tid < 128) sgl[tid] = glast[(size_t)c * HDK + h * DKd + tid];

        // ---- A = qg @ kint^T (64x64, K=128) ----
#pragma unroll
        for (int tIdx = w * 2; tIdx < w * 2 + 2; tIdx++) {
            int ti = tIdx >> 2, tj = tIdx & 3;
            FragC acc;
            wmma::fill_fragment(acc, 0.0f);
#pragma unroll
            for (int kk = 0; kk < DKd; kk += 8) {
                FragA a; FragBT bfr;
                wmma::load_matrix_sync(a, qgb + (size_t)(ti * 16) * HDK + kk, HDK); to_tf32(a);
                wmma::load_matrix_sync(bfr, kib + (size_t)(tj * 16) * HDK + kk, HDK); to_tf32(bfr);
                wmma::mma_sync(acc, a, bfr, acc);
            }
            wmma::store_matrix_sync(&As[(ti * 16) * A_STRIDE + tj * 16], acc,
                                    A_STRIDE, wmma::mem_row_major);
        }
        __syncthreads();
        // causal mask
        for (int i = tid; i < 64 * 64; i += 256) {
            int r = i >> 6, cc = i & 63;
            if (cc > r) As[r * A_STRIDE + cc] = 0.0f;
        }
        __syncthreads();

        // ---- o = tril(A) @ Vs + qg @ S  (64x64 out) ----
        {
            int ti = w >> 1;
            int tj0 = (w & 1) * 2;
            FragC acc2[2];
#pragma unroll
            for (int j = 0; j < 2; j++) wmma::fill_fragment(acc2[j], 0.0f);
#pragma unroll
            for (int kk = 0; kk < CH; kk += 8) {
                FragA a;
                wmma::load_matrix_sync(a, &As[(ti * 16) * A_STRIDE + kk], A_STRIDE); to_tf32(a);
#pragma unroll
                for (int j = 0; j < 2; j++) {
                    FragB bf;
                    wmma::load_matrix_sync(bf, &Vs[kk * V_STRIDE + (tj0 + j) * 16], V_STRIDE); to_tf32(bf);
                    wmma::mma_sync(acc2[j], a, bf, acc2[j]);
                }
            }
#pragma unroll
            for (int kk = 0; kk < DKd; kk += 8) {
                FragA a;
                wmma::load_matrix_sync(a, qgb + (size_t)(ti * 16) * HDK + kk, HDK); to_tf32(a);
#pragma unroll
                for (int j = 0; j < 2; j++) {
                    FragB bf;
                    wmma::load_matrix_sync(bf, &Ssm[kk * S_STRIDE + (tj0 + j) * 16], S_STRIDE); to_tf32(bf);
                    wmma::mma_sync(acc2[j], a, bf, acc2[j]);
                }
            }
#pragma unroll
            for (int j = 0; j < 2; j++)
                wmma::store_matrix_sync(ob + (size_t)(ti * 16) * HDV + (tj0 + j) * 16,
                                        acc2[j], HDV, wmma::mem_row_major);
        }

        // ---- U = kg^T (128x64) @ Vs (64x64) -> Us ----
        {
            FragC acc4[4];
#pragma unroll
            for (int j = 0; j < 4; j++) wmma::fill_fragment(acc4[j], 0.0f);
#pragma unroll
            for (int kk = 0; kk < CH; kk += 8) {
                FragAT a;
                wmma::load_matrix_sync(a, kgb + (size_t)kk * HDK + w * 16, HDK); to_tf32(a);
#pragma unroll
                for (int j = 0; j < 4; j++) {
                    FragB bf;
                    wmma::load_matrix_sync(bf, &Vs[kk * V_STRIDE + j * 16], V_STRIDE); to_tf32(bf);
                    wmma::mma_sync(acc4[j], a, bf, acc4[j]);
                }
            }
#pragma unroll
            for (int j = 0; j < 4; j++)
                wmma::store_matrix_sync(&Us[(w * 16) * U_STRIDE + j * 16], acc4[j],
                                        U_STRIDE, wmma::mem_row_major);
        }
        __syncthreads();

        // ---- S = S * diag(gl) + U ----
#pragma unroll
        for (int j = 0; j < 32; j++) {
            int i = j * 256 + tid;
            int r = i >> 6, cc = i & 63;
            Ssm[r * S_STRIDE + cc] = Ssm[r * S_STRIDE + cc] * sgl[r] + Us[r * U_STRIDE + cc];
        }
    }
}

// ---------------- gated RMSNorm ----------------
__global__ __launch_bounds__(256) void norm_gate_kernel(
    const float* __restrict__ o, const float* __restrict__ g,
    const float* __restrict__ gnw, float* __restrict__ y)
{
    int row = blockIdx.x * 8 + (threadIdx.x >> 5);
    int lane = threadIdx.x & 31;
    size_t base = (size_t)row * DVd;
    float v[8];
    float ss = 0.0f;
#pragma unroll
    for (int j = 0; j < 8; j++) {
        v[j] = o[base + lane + j * 32];
        ss += v[j] * v[j];
    }
#pragma unroll
    for (int off = 16; off > 0; off >>= 1)
        ss += __shfl_xor_sync(0xffffffff, ss, off);
    float r = rsqrtf(ss * (1.0f / DVd) + EPS);
#pragma unroll
    for (int j = 0; j < 8; j++) {
        int dv = lane + j * 32;
        float gv = g[base + dv];
        float sw = gv / (1.0f + expf(-gv));
        y[base + dv] = v[j] * r * gnw[dv] * sw;
    }
}

// ---------------- launch ----------------
extern "C" void kernel_launch(void* const* d_in, const int* in_sizes, int n_in,
                              void* d_out, int out_size)
{
    const float* x    = (const float*)d_in[0];
    const float* Wq   = (const float*)d_in[1];
    const float* Wk   = (const float*)d_in[2];
    const float* Wv   = (const float*)d_in[3];
    const float* Wg   = (const float*)d_in[4];
    const float* Wgk1 = (const float*)d_in[5];
    const float* Wgk2 = (const float*)d_in[6];
    const float* bgk2 = (const float*)d_in[7];
    const float* Wo   = (const float*)d_in[8];
    const float* gnw  = (const float*)d_in[9];
    float* out = (float*)d_out;

    float *q, *k, *v, *g, *gk, *x1, *qg, *kint, *kg, *glast, *o, *y;
    cudaGetSymbolAddress((void**)&q, d_q);
    cudaGetSymbolAddress((void**)&k, d_k);
    cudaGetSymbolAddress((void**)&v, d_v);
    cudaGetSymbolAddress((void**)&g, d_g);
    cudaGetSymbolAddress((void**)&gk, d_gk);
    cudaGetSymbolAddress((void**)&x1, d_x1);
    cudaGetSymbolAddress((void**)&qg, d_qg);
    cudaGetSymbolAddress((void**)&kint, d_kint);
    cudaGetSymbolAddress((void**)&kg, d_kg);
    cudaGetSymbolAddress((void**)&glast, d_glast);
    cudaGetSymbolAddress((void**)&o, d_o);
    cudaGetSymbolAddress((void**)&y, d_y);

    cudaFuncSetAttribute(proj_qkvg_kernel,
                         cudaFuncAttributeMaxDynamicSharedMemorySize, GEMM_SMEM_BYTES);
    cudaFuncSetAttribute(gemm_wo_kernel,
                         cudaFuncAttributeMaxDynamicSharedMemorySize, GEMM_SMEM_BYTES);
    cudaFuncSetAttribute(gla_fused_kernel,
                         cudaFuncAttributeMaxDynamicSharedMemorySize, FUSED_SMEM_BYTES);

    // fused input projections (q,k,v,g)
    proj_qkvg_kernel<<<dim3(24, BT / 128), 256, GEMM_SMEM_BYTES>>>(x, Wq, Wk, Wv, Wg, q, k, v, g);

    // low-rank gate path
    gk1_kernel<<<BT / 8, 256>>>(x, Wgk1, x1);
    gk2_kernel<<<(BT * HDK) / 256, 256>>>(x1, Wgk2, bgk2, gk);

    // decay factors
    decay_prep_kernel<<<NCHUNK * 4, 128>>>(q, k, gk, qg, kint, kg, glast);

    // fused chunkwise GLA (intra + scan + inter), S resident in smem
    gla_fused_kernel<<<BB * HH * 4, 256, FUSED_SMEM_BYTES>>>(qg, kint, kg, v, glast, o);

    // gated RMSNorm + output projection
    norm_gate_kernel<<<(BT * HH) / 8, 256>>>(o, g, gnw, y);
    gemm_wo_kernel<<<dim3(DM / 128, BT / 128), 256, GEMM_SMEM_BYTES>>>(y, Wo, out);
}

// round 4
// speedup vs baseline: 1.2298x; 1.0389x over previous
#include <cuda_runtime.h>
#include <cuda_bf16.h>
#include <mma.h>
#include <cstdint>

using namespace nvcuda;

// ---------------- problem constants ----------------
#define BB 4
#define TT 2048
#define DM 1024
#define HH 4
#define DKd 128
#define DVd 256
#define HDK 512     // H*DK
#define HDV 1024    // H*DV
#define BT  8192    // B*T tokens
#define CH  64      // chunk
#define NC  32      // chunks per sequence
#define NCHUNK 128  // total chunks (B*NC)
#define LR 16       // gate low rank
#define GNORM 16.0f
#define EPS 1e-5f

// ---------------- scratch ----------------
__device__ float d_q   [BT * HDK];
__device__ float d_k   [BT * HDK];
__device__ float d_v   [BT * HDV];
__device__ float d_g   [BT * HDV];
__device__ float d_gk  [BT * HDK];
__device__ float d_x1  [BT * LR];
__device__ float d_qg  [BT * HDK];
__device__ float d_kint[BT * HDK];
__device__ float d_kg  [BT * HDK];
__device__ float d_glast[NCHUNK * HDK];
__device__ float d_o   [BT * HDV];
__device__ float d_y   [BT * HDV];

// ---------------- helpers ----------------
template <typename Frag>
__device__ __forceinline__ void to_tf32(Frag& f) {
#pragma unroll
    for (int i = 0; i < f.num_elements; i++) f.x[i] = wmma::__float_to_tf32(f.x[i]);
}

typedef wmma::fragment<wmma::matrix_a, 16, 16, 8, wmma::precision::tf32, wmma::row_major> FragA;
typedef wmma::fragment<wmma::matrix_a, 16, 16, 8, wmma::precision::tf32, wmma::col_major> FragAT;
typedef wmma::fragment<wmma::matrix_b, 16, 16, 8, wmma::precision::tf32, wmma::row_major> FragB;
typedef wmma::fragment<wmma::matrix_b, 16, 16, 8, wmma::precision::tf32, wmma::col_major> FragBT;
typedef wmma::fragment<wmma::accumulator, 16, 16, 8, float> FragC;

__device__ __forceinline__ uint32_t smem_u32(const void* p) {
    return (uint32_t)__cvta_generic_to_shared(p);
}
__device__ __forceinline__ void cpasync16(float* dst, const float* src) {
    asm volatile("cp.async.cg.shared.global [%0], [%1], 16;\n"
                 :: "r"(smem_u32(dst)), "l"(src));
}
__device__ __forceinline__ void cp_commit() {
    asm volatile("cp.async.commit_group;\n");
}

// ---------------- 3-stage pipelined tf32 GEMM: CTA tile 128x256, warp tile 64x64 ----------------
#define AS_STRIDE 20
#define BS_STRIDE 260
#define STAGE_FLOATS (128 * AS_STRIDE + 16 * BS_STRIDE)  // 6720
#define GEMM_SMEM_BYTES (3 * STAGE_FLOATS * 4)           // 80640

__device__ __forceinline__ void gemm_load_tile(
    float* sm, int buf, const float* A, int lda, const float* B, int ldb, int it, int tid)
{
    float* As = sm + buf * STAGE_FLOATS;
    float* Bs = As + 128 * AS_STRIDE;
    const float* Ab = A + it * 16;
    const float* Bb = B + (size_t)it * 16 * ldb;
#pragma unroll
    for (int i = tid; i < 512; i += 256) {      // A: 128x16
        int r = i >> 2, c4 = i & 3;
        cpasync16(&As[r * AS_STRIDE + c4 * 4], Ab + (size_t)r * lda + c4 * 4);
    }
#pragma unroll
    for (int i = tid; i < 1024; i += 256) {     // B: 16x256
        int r = i >> 6, c = i & 63;
        cpasync16(&Bs[r * BS_STRIDE + c * 4], Bb + (size_t)r * ldb + c * 4);
    }
    cp_commit();
}

// C tile: 128 x 256. 8 warps in 2x4, each warp 64x64 (4x4 fragments).
__device__ __forceinline__ void gemm128x256_core(
    const float* __restrict__ A, int lda,
    const float* __restrict__ B, int ldb,
    float* __restrict__ C, int ldc,
    int K, float* sm)
{
    const int tid = threadIdx.x;
    const int w = tid >> 5;
    const int wr = w >> 2;     // 0..1 (64-row band)
    const int wc = w & 3;      // 0..3 (64-col band)

    FragC acc[4][4];
#pragma unroll
    for (int r = 0; r < 4; r++)
#pragma unroll
        for (int c = 0; c < 4; c++) wmma::fill_fragment(acc[r][c], 0.0f);

    const int ntiles = K / 16;

    gemm_load_tile(sm, 0, A, lda, B, ldb, 0, tid);
    gemm_load_tile(sm, 1, A, lda, B, ldb, 1, tid);

    for (int it = 0; it < ntiles; it++) {
        if (it < ntiles - 1) {
            asm volatile("cp.async.wait_group 1;\n");
        } else {
            asm volatile("cp.async.wait_group 0;\n");
        }
        __syncthreads();
        if (it + 2 < ntiles)
            gemm_load_tile(sm, (it + 2) % 3, A, lda, B, ldb, it + 2, tid);

        float* Ac = sm + (it % 3) * STAGE_FLOATS;
        float* Bc = Ac + 128 * AS_STRIDE;
#pragma unroll
        for (int kk = 0; kk < 16; kk += 8) {
            FragA af[4];
            FragB bf[4];
#pragma unroll
            for (int r = 0; r < 4; r++) {
                wmma::load_matrix_sync(af[r], &Ac[(wr * 64 + r * 16) * AS_STRIDE + kk], AS_STRIDE);
                to_tf32(af[r]);
            }
#pragma unroll
            for (int c = 0; c < 4; c++) {
                wmma::load_matrix_sync(bf[c], &Bc[kk * BS_STRIDE + wc * 64 + c * 16], BS_STRIDE);
                to_tf32(bf[c]);
            }
#pragma unroll
            for (int r = 0; r < 4; r++)
#pragma unroll
                for (int c = 0; c < 4; c++)
                    wmma::mma_sync(acc[r][c], af[r], bf[c], acc[r][c]);
        }
    }
    __syncthreads();

#pragma unroll
    for (int r = 0; r < 4; r++)
#pragma unroll
        for (int c = 0; c < 4; c++)
            wmma::store_matrix_sync(
                C + (size_t)(wr * 64 + r * 16) * ldc + wc * 64 + c * 16,
                acc[r][c], ldc, wmma::mem_row_major);
}

// ---------------- fused q/k/v/g projections: 256-col tiles ----------------
// grid.x: 0..1 q, 2..3 k, 4..7 v, 8..11 g; grid.y = BT/128
__global__ __launch_bounds__(256) void proj_qkvg_kernel(
    const float* __restrict__ x,
    const float* __restrict__ Wq, const float* __restrict__ Wk,
    const float* __restrict__ Wv, const float* __restrict__ Wg,
    float* __restrict__ q, float* __restrict__ k,
    float* __restrict__ v, float* __restrict__ g)
{
    extern __shared__ float sm[];
    const int bn = blockIdx.x;
    const int bm = blockIdx.y;
    const float* B;
    float* C;
    int n0, ldn;
    if (bn < 2)       { B = Wq; C = q; n0 = bn;     ldn = HDK; }
    else if (bn < 4)  { B = Wk; C = k; n0 = bn - 2; ldn = HDK; }
    else if (bn < 8)  { B = Wv; C = v; n0 = bn - 4; ldn = HDV; }
    else              { B = Wg; C = g; n0 = bn - 8; ldn = HDV; }
    gemm128x256_core(x + (size_t)bm * 128 * DM, DM,
                     B + n0 * 256, ldn,
                     C + (size_t)bm * 128 * ldn + n0 * 256, ldn,
                     DM, sm);
}

// ---------------- output projection: out = y @ Wo ----------------
__global__ __launch_bounds__(256) void gemm_wo_kernel(
    const float* __restrict__ y, const float* __restrict__ Wo, float* __restrict__ out)
{
    extern __shared__ float sm[];
    const int bn = blockIdx.x, bm = blockIdx.y;
    gemm128x256_core(y + (size_t)bm * 128 * HDV, HDV,
                     Wo + bn * 256, DM,
                     out + (size_t)bm * 128 * DM + bn * 256,
                     DM, HDV, sm);
}

// ---------------- low-rank gate: x1 = x @ Wgk1 ----------------
__global__ __launch_bounds__(256) void gk1_kernel(
    const float* __restrict__ x, const float* __restrict__ W, float* __restrict__ x1)
{
    int t = blockIdx.x * 8 + (threadIdx.x >> 5);
    int lane = threadIdx.x & 31;
    if (t >= BT) return;
    const float* xr = x + (size_t)t * DM;
    float acc[LR];
#pragma unroll
    for (int n = 0; n < LR; n++) acc[n] = 0.0f;
    for (int j = lane; j < DM; j += 32) {
        float xv = xr[j];
        const float* wr = W + (size_t)j * LR;
#pragma unroll
        for (int n = 0; n < LR; n++) acc[n] += xv * wr[n];
    }
#pragma unroll
    for (int n = 0; n < LR; n++) {
#pragma unroll
        for (int off = 16; off > 0; off >>= 1)
            acc[n] += __shfl_xor_sync(0xffffffff, acc[n], off);
    }
    if (lane == 0) {
#pragma unroll
        for (int n = 0; n < LR; n++) x1[(size_t)t * LR + n] = acc[n];
    }
}

// ---------------- gk = log_sigmoid(x1 @ Wgk2 + b) / 16 ----------------
__global__ __launch_bounds__(256) void gk2_kernel(
    const float* __restrict__ x1, const float* __restrict__ W2,
    const float* __restrict__ bias, float* __restrict__ gk)
{
    int idx = blockIdx.x * 256 + threadIdx.x;
    if (idx >= BT * HDK) return;
    int t = idx >> 9;
    int n = idx & 511;
    const float* xr = x1 + (size_t)t * LR;
    float a = bias[n];
#pragma unroll
    for (int kx = 0; kx < LR; kx++) a += xr[kx] * W2[kx * HDK + n];
    float ls = fminf(a, 0.0f) - log1pf(expf(-fabsf(a)));
    gk[idx] = ls * (1.0f / GNORM);
}

// ---------------- decay prep ----------------
__global__ __launch_bounds__(128) void decay_prep_kernel(
    const float* __restrict__ q, const float* __restrict__ k, const float* __restrict__ gk,
    float* __restrict__ qg, float* __restrict__ kint, float* __restrict__ kg,
    float* __restrict__ glast)
{
    int c = blockIdx.x >> 2;
    int col = ((blockIdx.x & 3) << 7) + threadIdx.x;
    size_t base = (size_t)c * CH * HDK + col;
    float tot = 0.0f;
#pragma unroll 8
    for (int i = 0; i < CH; i++) tot += gk[base + (size_t)i * HDK];
    glast[(size_t)c * HDK + col] = __expf(tot);
    const float scale = 0.088388347648318447f;   // 128^-0.5
    float run = 0.0f;
#pragma unroll 4
    for (int i = 0; i < CH; i++) {
        size_t idx = base + (size_t)i * HDK;
        run += gk[idx];
        qg[idx]   = q[idx] * __expf(run) * scale;
        kint[idx] = k[idx] * __expf(-run);
        kg[idx]   = k[idx] * __expf(tot - run);
    }
}

// ---------------- FUSED chunkwise GLA (intra + scan + inter), dv-block = 32 ----------------
// Grid: 128 CTAs = (b, h, dvb). S (128x32) persists in smem.
#define S_STRIDE 36
#define V_STRIDE 36
#define A_STRIDE 72
#define U_STRIDE 36
#define FUSED_SMEM_FLOATS (128 * S_STRIDE + 64 * V_STRIDE + 64 * A_STRIDE + 128 * U_STRIDE + 128)
#define FUSED_SMEM_BYTES (FUSED_SMEM_FLOATS * 4)   // 65024

__global__ __launch_bounds__(256) void gla_fused_kernel(
    const float* __restrict__ qg, const float* __restrict__ kint,
    const float* __restrict__ kg, const float* __restrict__ v,
    const float* __restrict__ glast, float* __restrict__ o)
{
    extern __shared__ float sm[];
    float* Ssm = sm;                          // 128 x 36
    float* Vs  = Ssm + 128 * S_STRIDE;        // 64 x 36
    float* As  = Vs + 64 * V_STRIDE;          // 64 x 72
    float* Us  = As + 64 * A_STRIDE;          // 128 x 36
    float* sgl = Us + 128 * U_STRIDE;         // 128

    const int id = blockIdx.x;
    const int b = id >> 5, h = (id >> 3) & 3, dvb = id & 7;
    const int tid = threadIdx.x, w = tid >> 5;

    for (int i = tid; i < 128 * S_STRIDE; i += 256) Ssm[i] = 0.0f;

    for (int n = 0; n < NC; n++) {
        const int c = b * NC + n;
        const size_t t0 = (size_t)c * CH;
        const float* qgb = qg   + t0 * HDK + h * DKd;
        const float* kib = kint + t0 * HDK + h * DKd;
        const float* kgb = kg   + t0 * HDK + h * DKd;
        const float* vb  = v    + t0 * HDV + h * DVd + dvb * 32;
        float* ob        = o    + t0 * HDV + h * DVd + dvb * 32;

        __syncthreads();   // prev S-update done; Vs/sgl free

        // stage v slice (64x32) + per-chunk decay
#pragma unroll
        for (int j = 0; j < 2; j++) {
            int idx = j * 256 + tid;
            int r = idx >> 3, c4 = idx & 7;
            *(float4*)&Vs[r * V_STRIDE + c4 * 4] =
                *(const float4*)&vb[(size_t)r * HDV + c4 * 4];
        }
        if (tid < 128) sgl[tid] = glast[(size_t)c * HDK + h * DKd + tid];

        // ---- A = qg @ kint^T (64x64, K=128), 2 tiles per warp ----
#pragma unroll
        for (int tIdx = w * 2; tIdx < w * 2 + 2; tIdx++) {
            int ti = tIdx >> 2, tj = tIdx & 3;
            FragC acc;
            wmma::fill_fragment(acc, 0.0f);
#pragma unroll
            for (int kk = 0; kk < DKd; kk += 8) {
                FragA a; FragBT bfr;
                wmma::load_matrix_sync(a, qgb + (size_t)(ti * 16) * HDK + kk, HDK); to_tf32(a);
                wmma::load_matrix_sync(bfr, kib + (size_t)(tj * 16) * HDK + kk, HDK); to_tf32(bfr);
                wmma::mma_sync(acc, a, bfr, acc);
            }
            wmma::store_matrix_sync(&As[(ti * 16) * A_STRIDE + tj * 16], acc,
                                    A_STRIDE, wmma::mem_row_major);
        }
        __syncthreads();
        // causal mask
        for (int i = tid; i < 64 * 64; i += 256) {
            int r = i >> 6, cc = i & 63;
            if (cc > r) As[r * A_STRIDE + cc] = 0.0f;
        }
        __syncthreads();

        // ---- o = tril(A) @ Vs + qg @ S  (64x32 out; warp -> one 16x16 frag) ----
        {
            int ti = w >> 1;
            int tj = w & 1;
            FragC acc2;
            wmma::fill_fragment(acc2, 0.0f);
#pragma unroll
            for (int kk = 0; kk < CH; kk += 8) {
                FragA a; FragB bf;
                wmma::load_matrix_sync(a, &As[(ti * 16) * A_STRIDE + kk], A_STRIDE); to_tf32(a);
                wmma::load_matrix_sync(bf, &Vs[kk * V_STRIDE + tj * 16], V_STRIDE); to_tf32(bf);
                wmma::mma_sync(acc2, a, bf, acc2);
            }
#pragma unroll
            for (int kk = 0; kk < DKd; kk += 8) {
                FragA a; FragB bf;
                wmma::load_matrix_sync(a, qgb + (size_t)(ti * 16) * HDK + kk, HDK); to_tf32(a);
                wmma::load_matrix_sync(bf, &Ssm[kk * S_STRIDE + tj * 16], S_STRIDE); to_tf32(bf);
                wmma::mma_sync(acc2, a, bf, acc2);
            }
            wmma::store_matrix_sync(ob + (size_t)(ti * 16) * HDV + tj * 16,
                                    acc2, HDV, wmma::mem_row_major);
        }

        // ---- U = kg^T (128x32) @ Vs (64x32): warp -> 16-row band, 2 col tiles ----
        {
            FragC acc4[2];
#pragma unroll
            for (int j = 0; j < 2; j++) wmma::fill_fragment(acc4[j], 0.0f);
#pragma unroll
            for (int kk = 0; kk < CH; kk += 8) {
                FragAT a;
                wmma::load_matrix_sync(a, kgb + (size_t)kk * HDK + w * 16, HDK); to_tf32(a);
#pragma unroll
                for (int j = 0; j < 2; j++) {
                    FragB bf;
                    wmma::load_matrix_sync(bf, &Vs[kk * V_STRIDE + j * 16], V_STRIDE); to_tf32(bf);
                    wmma::mma_sync(acc4[j], a, bf, acc4[j]);
                }
            }
#pragma unroll
            for (int j = 0; j < 2; j++)
                wmma::store_matrix_sync(&Us[(w * 16) * U_STRIDE + j * 16], acc4[j],
                                        U_STRIDE, wmma::mem_row_major);
        }
        __syncthreads();

        // ---- S = S * diag(gl) + U ----
#pragma unroll
        for (int j = 0; j < 16; j++) {
            int i = j * 256 + tid;
            int r = i >> 5, cc = i & 31;
            Ssm[r * S_STRIDE + cc] = Ssm[r * S_STRIDE + cc] * sgl[r] + Us[r * U_STRIDE + cc];
        }
    }
}

// ---------------- gated RMSNorm ----------------
__global__ __launch_bounds__(256) void norm_gate_kernel(
    const float* __restrict__ o, const float* __restrict__ g,
    const float* __restrict__ gnw, float* __restrict__ y)
{
    int row = blockIdx.x * 8 + (threadIdx.x >> 5);
    int lane = threadIdx.x & 31;
    size_t base = (size_t)row * DVd;
    float v[8];
    float ss = 0.0f;
#pragma unroll
    for (int j = 0; j < 8; j++) {
        v[j] = o[base + lane + j * 32];
        ss += v[j] * v[j];
    }
#pragma unroll
    for (int off = 16; off > 0; off >>= 1)
        ss += __shfl_xor_sync(0xffffffff, ss, off);
    float r = rsqrtf(ss * (1.0f / DVd) + EPS);
#pragma unroll
    for (int j = 0; j < 8; j++) {
        int dv = lane + j * 32;
        float gv = g[base + dv];
        float sw = gv / (1.0f + expf(-gv));
        y[base + dv] = v[j] * r * gnw[dv] * sw;
    }
}

// ---------------- launch ----------------
extern "C" void kernel_launch(void* const* d_in, const int* in_sizes, int n_in,
                              void* d_out, int out_size)
{
    const float* x    = (const float*)d_in[0];
    const float* Wq   = (const float*)d_in[1];
    const float* Wk   = (const float*)d_in[2];
    const float* Wv   = (const float*)d_in[3];
    const float* Wg   = (const float*)d_in[4];
    const float* Wgk1 = (const float*)d_in[5];
    const float* Wgk2 = (const float*)d_in[6];
    const float* bgk2 = (const float*)d_in[7];
    const float* Wo   = (const float*)d_in[8];
    const float* gnw  = (const float*)d_in[9];
    float* out = (float*)d_out;

    float *q, *k, *v, *g, *gk, *x1, *qg, *kint, *kg, *glast, *o, *y;
    cudaGetSymbolAddress((void**)&q, d_q);
    cudaGetSymbolAddress((void**)&k, d_k);
    cudaGetSymbolAddress((void**)&v, d_v);
    cudaGetSymbolAddress((void**)&g, d_g);
    cudaGetSymbolAddress((void**)&gk, d_gk);
    cudaGetSymbolAddress((void**)&x1, d_x1);
    cudaGetSymbolAddress((void**)&qg, d_qg);
    cudaGetSymbolAddress((void**)&kint, d_kint);
    cudaGetSymbolAddress((void**)&kg, d_kg);
    cudaGetSymbolAddress((void**)&glast, d_glast);
    cudaGetSymbolAddress((void**)&o, d_o);
    cudaGetSymbolAddress((void**)&y, d_y);

    cudaFuncSetAttribute(proj_qkvg_kernel,
                         cudaFuncAttributeMaxDynamicSharedMemorySize, GEMM_SMEM_BYTES);
    cudaFuncSetAttribute(gemm_wo_kernel,
                         cudaFuncAttributeMaxDynamicSharedMemorySize, GEMM_SMEM_BYTES);
    cudaFuncSetAttribute(gla_fused_kernel,
                         cudaFuncAttributeMaxDynamicSharedMemorySize, FUSED_SMEM_BYTES);

    // fused input projections (q,k,v,g): 12 x 64 = 768 CTAs
    proj_qkvg_kernel<<<dim3(12, BT / 128), 256, GEMM_SMEM_BYTES>>>(x, Wq, Wk, Wv, Wg, q, k, v, g);

    // low-rank gate path
    gk1_kernel<<<BT / 8, 256>>>(x, Wgk1, x1);
    gk2_kernel<<<(BT * HDK) / 256, 256>>>(x1, Wgk2, bgk2, gk);

    // decay factors
    decay_prep_kernel<<<NCHUNK * 4, 128>>>(q, k, gk, qg, kint, kg, glast);

    // fused chunkwise GLA
    gla_fused_kernel<<<BB * HH * 8, 256, FUSED_SMEM_BYTES>>>(qg, kint, kg, v, glast, o);

    // gated RMSNorm + output projection
    norm_gate_kernel<<<(BT * HH) / 8, 256>>>(o, g, gnw, y);
    gemm_wo_kernel<<<dim3(DM / 256, BT / 128), 256, GEMM_SMEM_BYTES>>>(y, Wo, out);
}

// round 5
// speedup vs baseline: 1.3038x; 1.0602x over previous
#include <cuda_runtime.h>
#include <cuda_bf16.h>
#include <mma.h>
#include <cstdint>

using namespace nvcuda;

// ---------------- problem constants ----------------
#define BB 4
#define TT 2048
#define DM 1024
#define HH 4
#define DKd 128
#define DVd 256
#define HDK 512     // H*DK
#define HDV 1024    // H*DV
#define BT  8192    // B*T tokens
#define CH  64      // chunk
#define NC  32      // chunks per sequence
#define NCHUNK 128  // total chunks (B*NC)
#define LR 16       // gate low rank
#define GNORM 16.0f
#define EPS 1e-5f

// ---------------- scratch ----------------
__device__ float d_xr  [BT * DM];       // tf32-rounded x
__device__ float d_Wqr [DM * HDK];
__device__ float d_Wkr [DM * HDK];
__device__ float d_Wvr [DM * HDV];
__device__ float d_Wgr [DM * HDV];
__device__ float d_Wor [HDV * DM];
__device__ float d_q   [BT * HDK];
__device__ float d_k   [BT * HDK];
__device__ float d_v   [BT * HDV];
__device__ float d_g   [BT * HDV];
__device__ float d_gk  [BT * HDK];
__device__ float d_x1  [BT * LR];
__device__ float d_qg  [BT * HDK];
__device__ float d_kint[BT * HDK];
__device__ float d_kg  [BT * HDK];
__device__ float d_glast[NCHUNK * HDK];
__device__ float d_A   [NCHUNK * HH * CH * CH];   // masked+rounded intra A
__device__ float d_o   [BT * HDV];
__device__ float d_y   [BT * HDV];

// ---------------- helpers ----------------
__device__ __forceinline__ float rtf32(float x) {
    return wmma::__float_to_tf32(x);
}
template <typename Frag>
__device__ __forceinline__ void to_tf32(Frag& f) {
#pragma unroll
    for (int i = 0; i < f.num_elements; i++) f.x[i] = wmma::__float_to_tf32(f.x[i]);
}

typedef wmma::fragment<wmma::matrix_a, 16, 16, 8, wmma::precision::tf32, wmma::row_major> FragA;
typedef wmma::fragment<wmma::matrix_a, 16, 16, 8, wmma::precision::tf32, wmma::col_major> FragAT;
typedef wmma::fragment<wmma::matrix_b, 16, 16, 8, wmma::precision::tf32, wmma::row_major> FragB;
typedef wmma::fragment<wmma::matrix_b, 16, 16, 8, wmma::precision::tf32, wmma::col_major> FragBT;
typedef wmma::fragment<wmma::accumulator, 16, 16, 8, float> FragC;

__device__ __forceinline__ uint32_t smem_u32(const void* p) {
    return (uint32_t)__cvta_generic_to_shared(p);
}
__device__ __forceinline__ void cpasync16(float* dst, const float* src) {
    asm volatile("cp.async.cg.shared.global [%0], [%1], 16;\n"
                 :: "r"(smem_u32(dst)), "l"(src));
}
__device__ __forceinline__ void cp_commit() {
    asm volatile("cp.async.commit_group;\n");
}

// ---------------- tf32 rounding pass ----------------
__global__ __launch_bounds__(256) void round_tf32_kernel(
    const float4* __restrict__ in, float4* __restrict__ out, int n4)
{
    int i = blockIdx.x * 256 + threadIdx.x;
    if (i >= n4) return;
    float4 a = in[i];
    a.x = rtf32(a.x); a.y = rtf32(a.y); a.z = rtf32(a.z); a.w = rtf32(a.w);
    out[i] = a;
}

// ---------------- 3-stage pipelined tf32 GEMM: CTA 128x256, warp 64x64, NO converts ----------------
#define AS_STRIDE 20
#define BS_STRIDE 260
#define STAGE_FLOATS (128 * AS_STRIDE + 16 * BS_STRIDE)  // 6720
#define GEMM_SMEM_BYTES (3 * STAGE_FLOATS * 4)           // 80640

__device__ __forceinline__ void gemm_load_tile(
    float* sm, int buf, const float* A, int lda, const float* B, int ldb, int it, int tid)
{
    float* As = sm + buf * STAGE_FLOATS;
    float* Bs = As + 128 * AS_STRIDE;
    const float* Ab = A + it * 16;
    const float* Bb = B + (size_t)it * 16 * ldb;
#pragma unroll
    for (int i = tid; i < 512; i += 256) {      // A: 128x16
        int r = i >> 2, c4 = i & 3;
        cpasync16(&As[r * AS_STRIDE + c4 * 4], Ab + (size_t)r * lda + c4 * 4);
    }
#pragma unroll
    for (int i = tid; i < 1024; i += 256) {     // B: 16x256
        int r = i >> 6, c = i & 63;
        cpasync16(&Bs[r * BS_STRIDE + c * 4], Bb + (size_t)r * ldb + c * 4);
    }
    cp_commit();
}

__device__ __forceinline__ void gemm128x256_core(
    const float* __restrict__ A, int lda,
    const float* __restrict__ B, int ldb,
    float* __restrict__ C, int ldc,
    int K, float* sm)
{
    const int tid = threadIdx.x;
    const int w = tid >> 5;
    const int wr = w >> 2;     // 0..1
    const int wc = w & 3;      // 0..3

    FragC acc[4][4];
#pragma unroll
    for (int r = 0; r < 4; r++)
#pragma unroll
        for (int c = 0; c < 4; c++) wmma::fill_fragment(acc[r][c], 0.0f);

    const int ntiles = K / 16;

    gemm_load_tile(sm, 0, A, lda, B, ldb, 0, tid);
    gemm_load_tile(sm, 1, A, lda, B, ldb, 1, tid);

    for (int it = 0; it < ntiles; it++) {
        if (it < ntiles - 1) {
            asm volatile("cp.async.wait_group 1;\n");
        } else {
            asm volatile("cp.async.wait_group 0;\n");
        }
        __syncthreads();
        if (it + 2 < ntiles)
            gemm_load_tile(sm, (it + 2) % 3, A, lda, B, ldb, it + 2, tid);

        float* Ac = sm + (it % 3) * STAGE_FLOATS;
        float* Bc = Ac + 128 * AS_STRIDE;
#pragma unroll
        for (int kk = 0; kk < 16; kk += 8) {
            FragA af[4];
            FragB bf[4];
#pragma unroll
            for (int r = 0; r < 4; r++)
                wmma::load_matrix_sync(af[r], &Ac[(wr * 64 + r * 16) * AS_STRIDE + kk], AS_STRIDE);
#pragma unroll
            for (int c = 0; c < 4; c++)
                wmma::load_matrix_sync(bf[c], &Bc[kk * BS_STRIDE + wc * 64 + c * 16], BS_STRIDE);
#pragma unroll
            for (int r = 0; r < 4; r++)
#pragma unroll
                for (int c = 0; c < 4; c++)
                    wmma::mma_sync(acc[r][c], af[r], bf[c], acc[r][c]);
        }
    }
    __syncthreads();

#pragma unroll
    for (int r = 0; r < 4; r++)
#pragma unroll
        for (int c = 0; c < 4; c++)
            wmma::store_matrix_sync(
                C + (size_t)(wr * 64 + r * 16) * ldc + wc * 64 + c * 16,
                acc[r][c], ldc, wmma::mem_row_major);
}

// ---------------- fused q/k/v/g projections ----------------
__global__ __launch_bounds__(256) void proj_qkvg_kernel(
    const float* __restrict__ x,
    const float* __restrict__ Wq, const float* __restrict__ Wk,
    const float* __restrict__ Wv, const float* __restrict__ Wg,
    float* __restrict__ q, float* __restrict__ k,
    float* __restrict__ v, float* __restrict__ g)
{
    extern __shared__ float sm[];
    const int bn = blockIdx.x;
    const int bm = blockIdx.y;
    const float* B;
    float* C;
    int n0, ldn;
    if (bn < 2)       { B = Wq; C = q; n0 = bn;     ldn = HDK; }
    else if (bn < 4)  { B = Wk; C = k; n0 = bn - 2; ldn = HDK; }
    else if (bn < 8)  { B = Wv; C = v; n0 = bn - 4; ldn = HDV; }
    else              { B = Wg; C = g; n0 = bn - 8; ldn = HDV; }
    gemm128x256_core(x + (size_t)bm * 128 * DM, DM,
                     B + n0 * 256, ldn,
                     C + (size_t)bm * 128 * ldn + n0 * 256, ldn,
                     DM, sm);
}

// ---------------- output projection ----------------
__global__ __launch_bounds__(256) void gemm_wo_kernel(
    const float* __restrict__ y, const float* __restrict__ Wo, float* __restrict__ out)
{
    extern __shared__ float sm[];
    const int bn = blockIdx.x, bm = blockIdx.y;
    gemm128x256_core(y + (size_t)bm * 128 * HDV, HDV,
                     Wo + bn * 256, DM,
                     out + (size_t)bm * 128 * DM + bn * 256,
                     DM, HDV, sm);
}

// ---------------- low-rank gate: x1 = x @ Wgk1 ----------------
__global__ __launch_bounds__(256) void gk1_kernel(
    const float* __restrict__ x, const float* __restrict__ W, float* __restrict__ x1)
{
    int t = blockIdx.x * 8 + (threadIdx.x >> 5);
    int lane = threadIdx.x & 31;
    if (t >= BT) return;
    const float* xr = x + (size_t)t * DM;
    float acc[LR];
#pragma unroll
    for (int n = 0; n < LR; n++) acc[n] = 0.0f;
    for (int j = lane; j < DM; j += 32) {
        float xv = xr[j];
        const float* wr = W + (size_t)j * LR;
#pragma unroll
        for (int n = 0; n < LR; n++) acc[n] += xv * wr[n];
    }
#pragma unroll
    for (int n = 0; n < LR; n++) {
#pragma unroll
        for (int off = 16; off > 0; off >>= 1)
            acc[n] += __shfl_xor_sync(0xffffffff, acc[n], off);
    }
    if (lane == 0) {
#pragma unroll
        for (int n = 0; n < LR; n++) x1[(size_t)t * LR + n] = acc[n];
    }
}

// ---------------- gk = log_sigmoid(x1 @ Wgk2 + b) / 16 ----------------
__global__ __launch_bounds__(256) void gk2_kernel(
    const float* __restrict__ x1, const float* __restrict__ W2,
    const float* __restrict__ bias, float* __restrict__ gk)
{
    int idx = blockIdx.x * 256 + threadIdx.x;
    if (idx >= BT * HDK) return;
    int t = idx >> 9;
    int n = idx & 511;
    const float* xr = x1 + (size_t)t * LR;
    float a = bias[n];
#pragma unroll
    for (int kx = 0; kx < LR; kx++) a += xr[kx] * W2[kx * HDK + n];
    float ls = fminf(a, 0.0f) - log1pf(expf(-fabsf(a)));
    gk[idx] = ls * (1.0f / GNORM);
}

// ---------------- decay prep (stores tf32-rounded qg/kint/kg) ----------------
__global__ __launch_bounds__(128) void decay_prep_kernel(
    const float* __restrict__ q, const float* __restrict__ k, const float* __restrict__ gk,
    float* __restrict__ qg, float* __restrict__ kint, float* __restrict__ kg,
    float* __restrict__ glast)
{
    int c = blockIdx.x >> 2;
    int col = ((blockIdx.x & 3) << 7) + threadIdx.x;
    size_t base = (size_t)c * CH * HDK + col;
    float tot = 0.0f;
#pragma unroll 8
    for (int i = 0; i < CH; i++) tot += gk[base + (size_t)i * HDK];
    glast[(size_t)c * HDK + col] = __expf(tot);
    const float scale = 0.088388347648318447f;   // 128^-0.5
    float run = 0.0f;
#pragma unroll 4
    for (int i = 0; i < CH; i++) {
        size_t idx = base + (size_t)i * HDK;
        run += gk[idx];
        qg[idx]   = rtf32(q[idx] * __expf(run) * scale);
        kint[idx] = rtf32(k[idx] * __expf(-run));
        kg[idx]   = rtf32(k[idx] * __expf(tot - run));
    }
}

// ---------------- intra A matrix: A = tril(qg @ kint^T), rounded, to global ----------------
__global__ __launch_bounds__(256) void gla_A_kernel(
    const float* __restrict__ qg, const float* __restrict__ kint, float* __restrict__ A)
{
    __shared__ float As[64 * 72];
    const int ch = blockIdx.x;          // 0..511 = c*4+h
    const int c = ch >> 2, h = ch & 3;
    const size_t t0 = (size_t)c * CH;
    const float* qgb = qg   + t0 * HDK + h * DKd;
    const float* kib = kint + t0 * HDK + h * DKd;
    const int tid = threadIdx.x, w = tid >> 5;

#pragma unroll
    for (int tIdx = w * 2; tIdx < w * 2 + 2; tIdx++) {
        int ti = tIdx >> 2, tj = tIdx & 3;
        FragC acc;
        wmma::fill_fragment(acc, 0.0f);
#pragma unroll
        for (int kk = 0; kk < DKd; kk += 8) {
            FragA a; FragBT b;
            wmma::load_matrix_sync(a, qgb + (size_t)(ti * 16) * HDK + kk, HDK);
            wmma::load_matrix_sync(b, kib + (size_t)(tj * 16) * HDK + kk, HDK);
            wmma::mma_sync(acc, a, b, acc);
        }
        wmma::store_matrix_sync(&As[(ti * 16) * 72 + tj * 16], acc, 72, wmma::mem_row_major);
    }
    __syncthreads();
    float* Ab = A + (size_t)ch * CH * CH;
    for (int i = tid; i < 64 * 64; i += 256) {
        int r = i >> 6, cc = i & 63;
        Ab[i] = (cc > r) ? 0.0f : rtf32(As[r * 72 + cc]);
    }
}

// ---------------- FUSED chunkwise GLA (inter + intra-apply + scan), dv-block = 32 ----------------
#define S_STRIDE 36
#define V_STRIDE 36
#define U_STRIDE 36

__global__ __launch_bounds__(256) void gla_fused_kernel(
    const float* __restrict__ Amat, const float* __restrict__ qg,
    const float* __restrict__ kg, const float* __restrict__ v,
    const float* __restrict__ glast, float* __restrict__ o)
{
    __shared__ float Ssm[128 * S_STRIDE];
    __shared__ float Vs[64 * V_STRIDE];
    __shared__ float Us[128 * U_STRIDE];
    __shared__ float sgl[128];

    const int id = blockIdx.x;
    const int b = id >> 5, h = (id >> 3) & 3, dvb = id & 7;
    const int tid = threadIdx.x, w = tid >> 5;

    for (int i = tid; i < 128 * S_STRIDE; i += 256) Ssm[i] = 0.0f;

    for (int n = 0; n < NC; n++) {
        const int c = b * NC + n;
        const int ch = c * HH + h;
        const size_t t0 = (size_t)c * CH;
        const float* qgb = qg + t0 * HDK + h * DKd;
        const float* kgb = kg + t0 * HDK + h * DKd;
        const float* vb  = v  + t0 * HDV + h * DVd + dvb * 32;
        const float* Ab  = Amat + (size_t)ch * CH * CH;     // 64x64, ld 64
        float* ob        = o  + t0 * HDV + h * DVd + dvb * 32;

        __syncthreads();   // prev S-update complete; Vs free

        // stage v slice (64x32) + per-chunk decay
#pragma unroll
        for (int j = 0; j < 2; j++) {
            int idx = j * 256 + tid;
            int r = idx >> 3, c4 = idx & 7;
            *(float4*)&Vs[r * V_STRIDE + c4 * 4] =
                *(const float4*)&vb[(size_t)r * HDV + c4 * 4];
        }
        if (tid < 128) sgl[tid] = glast[(size_t)c * HDK + h * DKd + tid];
        __syncthreads();

        // ---- o = A @ Vs + qg @ S  (64x32; warp -> one 16x16 frag) ----
        {
            int ti = w >> 1;
            int tj = w & 1;
            FragC acc2;
            wmma::fill_fragment(acc2, 0.0f);
#pragma unroll
            for (int kk = 0; kk < CH; kk += 8) {
                FragA a; FragB bf;
                wmma::load_matrix_sync(a, Ab + (size_t)(ti * 16) * CH + kk, CH);
                wmma::load_matrix_sync(bf, &Vs[kk * V_STRIDE + tj * 16], V_STRIDE);
                wmma::mma_sync(acc2, a, bf, acc2);
            }
#pragma unroll
            for (int kk = 0; kk < DKd; kk += 8) {
                FragA a; FragB bf;
                wmma::load_matrix_sync(a, qgb + (size_t)(ti * 16) * HDK + kk, HDK);
                wmma::load_matrix_sync(bf, &Ssm[kk * S_STRIDE + tj * 16], S_STRIDE);
                to_tf32(bf);   // S stays fp32 in smem; round at use
                wmma::mma_sync(acc2, a, bf, acc2);
            }
            wmma::store_matrix_sync(ob + (size_t)(ti * 16) * HDV + tj * 16,
                                    acc2, HDV, wmma::mem_row_major);
        }

        // ---- U = kg^T (128x32) @ Vs (64x32) ----
        {
            FragC acc4[2];
#pragma unroll
            for (int j = 0; j < 2; j++) wmma::fill_fragment(acc4[j], 0.0f);
#pragma unroll
            for (int kk = 0; kk < CH; kk += 8) {
                FragAT a;
                wmma::load_matrix_sync(a, kgb + (size_t)kk * HDK + w * 16, HDK);
#pragma unroll
                for (int j = 0; j < 2; j++) {
                    FragB bf;
                    wmma::load_matrix_sync(bf, &Vs[kk * V_STRIDE + j * 16], V_STRIDE);
                    wmma::mma_sync(acc4[j], a, bf, acc4[j]);
                }
            }
#pragma unroll
            for (int j = 0; j < 2; j++)
                wmma::store_matrix_sync(&Us[(w * 16) * U_STRIDE + j * 16], acc4[j],
                                        U_STRIDE, wmma::mem_row_major);
        }
        __syncthreads();

        // ---- S = S * diag(gl) + U ----
#pragma unroll
        for (int j = 0; j < 16; j++) {
            int i = j * 256 + tid;
            int r = i >> 5, cc = i & 31;
            Ssm[r * S_STRIDE + cc] = Ssm[r * S_STRIDE + cc] * sgl[r] + Us[r * U_STRIDE + cc];
        }
    }
}

// ---------------- gated RMSNorm (stores tf32-rounded y) ----------------
__global__ __launch_bounds__(256) void norm_gate_kernel(
    const float* __restrict__ o, const float* __restrict__ g,
    const float* __restrict__ gnw, float* __restrict__ y)
{
    int row = blockIdx.x * 8 + (threadIdx.x >> 5);
    int lane = threadIdx.x & 31;
    size_t base = (size_t)row * DVd;
    float v[8];
    float ss = 0.0f;
#pragma unroll
    for (int j = 0; j < 8; j++) {
        v[j] = o[base + lane + j * 32];
        ss += v[j] * v[j];
    }
#pragma unroll
    for (int off = 16; off > 0; off >>= 1)
        ss += __shfl_xor_sync(0xffffffff, ss, off);
    float r = rsqrtf(ss * (1.0f / DVd) + EPS);
#pragma unroll
    for (int j = 0; j < 8; j++) {
        int dv = lane + j * 32;
        float gv = g[base + dv];
        float sw = gv / (1.0f + expf(-gv));
        y[base + dv] = rtf32(v[j] * r * gnw[dv] * sw);
    }
}

// ---------------- launch ----------------
extern "C" void kernel_launch(void* const* d_in, const int* in_sizes, int n_in,
                              void* d_out, int out_size)
{
    const float* x    = (const float*)d_in[0];
    const float* Wq   = (const float*)d_in[1];
    const float* Wk   = (const float*)d_in[2];
    const float* Wv   = (const float*)d_in[3];
    const float* Wg   = (const float*)d_in[4];
    const float* Wgk1 = (const float*)d_in[5];
    const float* Wgk2 = (const float*)d_in[6];
    const float* bgk2 = (const float*)d_in[7];
    const float* Wo   = (const float*)d_in[8];
    const float* gnw  = (const float*)d_in[9];
    float* out = (float*)d_out;

    float *xr, *Wqr, *Wkr, *Wvr, *Wgr, *Wor;
    float *q, *k, *v, *g, *gk, *x1, *qg, *kint, *kg, *glast, *A, *o, *y;
    cudaGetSymbolAddress((void**)&xr, d_xr);
    cudaGetSymbolAddress((void**)&Wqr, d_Wqr);
    cudaGetSymbolAddress((void**)&Wkr, d_Wkr);
    cudaGetSymbolAddress((void**)&Wvr, d_Wvr);
    cudaGetSymbolAddress((void**)&Wgr, d_Wgr);
    cudaGetSymbolAddress((void**)&Wor, d_Wor);
    cudaGetSymbolAddress((void**)&q, d_q);
    cudaGetSymbolAddress((void**)&k, d_k);
    cudaGetSymbolAddress((void**)&v, d_v);
    cudaGetSymbolAddress((void**)&g, d_g);
    cudaGetSymbolAddress((void**)&gk, d_gk);
    cudaGetSymbolAddress((void**)&x1, d_x1);
    cudaGetSymbolAddress((void**)&qg, d_qg);
    cudaGetSymbolAddress((void**)&kint, d_kint);
    cudaGetSymbolAddress((void**)&kg, d_kg);
    cudaGetSymbolAddress((void**)&glast, d_glast);
    cudaGetSymbolAddress((void**)&A, d_A);
    cudaGetSymbolAddress((void**)&o, d_o);
    cudaGetSymbolAddress((void**)&y, d_y);

    cudaFuncSetAttribute(proj_qkvg_kernel,
                         cudaFuncAttributeMaxDynamicSharedMemorySize, GEMM_SMEM_BYTES);
    cudaFuncSetAttribute(gemm_wo_kernel,
                         cudaFuncAttributeMaxDynamicSharedMemorySize, GEMM_SMEM_BYTES);

    // one-time tf32 pre-rounding (removes all converts from GEMM mainloops)
    round_tf32_kernel<<<(BT * DM / 4) / 256, 256>>>((const float4*)x, (float4*)xr, BT * DM / 4);
    round_tf32_kernel<<<(DM * HDK / 4) / 256, 256>>>((const float4*)Wq, (float4*)Wqr, DM * HDK / 4);
    round_tf32_kernel<<<(DM * HDK / 4) / 256, 256>>>((const float4*)Wk, (float4*)Wkr, DM * HDK / 4);
    round_tf32_kernel<<<(DM * HDV / 4) / 256, 256>>>((const float4*)Wv, (float4*)Wvr, DM * HDV / 4);
    round_tf32_kernel<<<(DM * HDV / 4) / 256, 256>>>((const float4*)Wg, (float4*)Wgr, DM * HDV / 4);
    round_tf32_kernel<<<(HDV * DM / 4) / 256, 256>>>((const float4*)Wo, (float4*)Wor, HDV * DM / 4);

    // fused input projections
    proj_qkvg_kernel<<<dim3(12, BT / 128), 256, GEMM_SMEM_BYTES>>>(xr, Wqr, Wkr, Wvr, Wgr, q, k, v, g);

    // low-rank gate path (exact fp32 on original x)
    gk1_kernel<<<BT / 8, 256>>>(x, Wgk1, x1);
    gk2_kernel<<<(BT * HDK) / 256, 256>>>(x1, Wgk2, bgk2, gk);

    // decay factors (rounded at store)
    decay_prep_kernel<<<NCHUNK * 4, 128>>>(q, k, gk, qg, kint, kg, glast);

    // round v in place (it feeds tensor ops in the fused kernel)
    round_tf32_kernel<<<(BT * HDV / 4) / 256, 256>>>((const float4*)v, (float4*)v, BT * HDV / 4);

    // intra A matrices (computed ONCE per chunk-head, 512-way parallel)
    gla_A_kernel<<<NCHUNK * HH, 256>>>(qg, kint, A);

    // fused chunkwise GLA
    gla_fused_kernel<<<BB * HH * 8, 256>>>(A, qg, kg, v, glast, o);

    // gated RMSNorm (rounded y) + output projection
    norm_gate_kernel<<<(BT * HH) / 8, 256>>>(o, g, gnw, y);
    gemm_wo_kernel<<<dim3(DM / 256, BT / 128), 256, GEMM_SMEM_BYTES>>>(y, Wor, out);
}

// round 7
// speedup vs baseline: 2.1996x; 1.6870x over previous
#include <cuda_runtime.h>
#include <cuda_fp16.h>
#include <mma.h>
#include <cstdint>

using namespace nvcuda;

// ---------------- problem constants ----------------
#define BB 4
#define TT 2048
#define DM 1024
#define HH 4
#define DKd 128
#define DVd 256
#define HDK 512     // H*DK
#define HDV 1024    // H*DV
#define BT  8192    // B*T tokens
#define CH  64      // chunk
#define NC  32      // chunks per sequence
#define NCHUNK 128  // total chunks (B*NC)
#define LR 16       // gate low rank
#define GNORM 16.0f
#define EPS 1e-5f

// ---------------- scratch ----------------
__device__ __half d_xh [BT * DM];       // fp16 x
__device__ __half d_Wqh[DM * HDK];      // fp16 weights (same [K,N] layout)
__device__ __half d_Wkh[DM * HDK];
__device__ __half d_Wvh[DM * HDV];
__device__ __half d_Wgh[DM * HDV];
__device__ __half d_Woh[HDV * DM];
__device__ __half d_yh [BT * HDV];      // fp16 normed/gated output
__device__ float d_q   [BT * HDK];
__device__ float d_k   [BT * HDK];
__device__ float d_v   [BT * HDV];
__device__ float d_g   [BT * HDV];
__device__ float d_gk  [BT * HDK];
__device__ float d_x1  [BT * LR];
__device__ float d_qg  [BT * HDK];
__device__ float d_kint[BT * HDK];
__device__ float d_kg  [BT * HDK];
__device__ float d_glast[NCHUNK * HDK];
__device__ float d_A   [NCHUNK * HH * CH * CH];
__device__ float d_o   [BT * HDV];

// ---------------- helpers ----------------
__device__ __forceinline__ float rtf32(float x) {
    return wmma::__float_to_tf32(x);
}
template <typename Frag>
__device__ __forceinline__ void to_tf32(Frag& f) {
#pragma unroll
    for (int i = 0; i < f.num_elements; i++) f.x[i] = wmma::__float_to_tf32(f.x[i]);
}

// tf32 fragments (GLA section)
typedef wmma::fragment<wmma::matrix_a, 16, 16, 8, wmma::precision::tf32, wmma::row_major> FragA;
typedef wmma::fragment<wmma::matrix_a, 16, 16, 8, wmma::precision::tf32, wmma::col_major> FragAT;
typedef wmma::fragment<wmma::matrix_b, 16, 16, 8, wmma::precision::tf32, wmma::row_major> FragB;
typedef wmma::fragment<wmma::matrix_b, 16, 16, 8, wmma::precision::tf32, wmma::col_major> FragBT;
typedef wmma::fragment<wmma::accumulator, 16, 16, 8, float> FragC;

// fp16 fragments (dense GEMMs)
typedef wmma::fragment<wmma::matrix_a, 16, 16, 16, __half, wmma::row_major> FragAh;
typedef wmma::fragment<wmma::matrix_b, 16, 16, 16, __half, wmma::row_major> FragBh;
typedef wmma::fragment<wmma::accumulator, 16, 16, 16, float> FragCh;

__device__ __forceinline__ uint32_t smem_u32(const void* p) {
    return (uint32_t)__cvta_generic_to_shared(p);
}
__device__ __forceinline__ void cpasync16(void* dst, const void* src) {
    asm volatile("cp.async.cg.shared.global [%0], [%1], 16;\n"
                 :: "r"(smem_u32(dst)), "l"(src));
}
__device__ __forceinline__ void cp_commit() {
    asm volatile("cp.async.commit_group;\n");
}

// ---------------- float -> half conversion ----------------
__global__ __launch_bounds__(256) void f2h_kernel(
    const float4* __restrict__ in, uint2* __restrict__ out, int n4)
{
    int i = blockIdx.x * 256 + threadIdx.x;
    if (i >= n4) return;
    float4 a = in[i];
    __half2 lo = __floats2half2_rn(a.x, a.y);
    __half2 hi = __floats2half2_rn(a.z, a.w);
    uint2 p;
    p.x = *(uint32_t*)&lo;
    p.y = *(uint32_t*)&hi;
    out[i] = p;
}

// ---------------- tf32 rounding pass (for v) ----------------
__global__ __launch_bounds__(256) void round_tf32_kernel(
    const float4* __restrict__ in, float4* __restrict__ out, int n4)
{
    int i = blockIdx.x * 256 + threadIdx.x;
    if (i >= n4) return;
    float4 a = in[i];
    a.x = rtf32(a.x); a.y = rtf32(a.y); a.z = rtf32(a.z); a.w = rtf32(a.w);
    out[i] = a;
}

// ---------------- 3-stage pipelined fp16 GEMM: CTA 128x256, warp 64x64, BK=32 ----------------
#define AS_STRIDE 40     // halves (32 + 8 pad)
#define BS_STRIDE 264    // halves (256 + 8 pad)
#define STAGE_HALFS (128 * AS_STRIDE + 32 * BS_STRIDE)   // 13568
#define GEMM_SMEM_BYTES (3 * STAGE_HALFS * 2)            // 81408

__device__ __forceinline__ void gemm_load_tile_h(
    __half* sm, int buf, const __half* A, int lda, const __half* B, int ldb, int it, int tid)
{
    __half* As = sm + buf * STAGE_HALFS;
    __half* Bs = As + 128 * AS_STRIDE;
    const __half* Ab = A + it * 32;
    const __half* Bb = B + (size_t)it * 32 * ldb;
#pragma unroll
    for (int i = tid; i < 512; i += 256) {       // A: 128 rows x 32 halves (4 x 16B)
        int r = i >> 2, c = i & 3;
        cpasync16(&As[r * AS_STRIDE + c * 8], Ab + (size_t)r * lda + c * 8);
    }
#pragma unroll
    for (int i = tid; i < 1024; i += 256) {      // B: 32 rows x 256 halves (32 x 16B)
        int r = i >> 5, c = i & 31;
        cpasync16(&Bs[r * BS_STRIDE + c * 8], Bb + (size_t)r * ldb + c * 8);
    }
    cp_commit();
}

__device__ __forceinline__ void gemm128x256_fp16(
    const __half* __restrict__ A, int lda,
    const __half* __restrict__ B, int ldb,
    float* __restrict__ C, int ldc,
    int K, __half* sm)
{
    const int tid = threadIdx.x;
    const int w = tid >> 5;
    const int wr = w >> 2;     // 0..1
    const int wc = w & 3;      // 0..3

    FragCh acc[4][4];
#pragma unroll
    for (int r = 0; r < 4; r++)
#pragma unroll
        for (int c = 0; c < 4; c++) wmma::fill_fragment(acc[r][c], 0.0f);

    const int ntiles = K / 32;

    gemm_load_tile_h(sm, 0, A, lda, B, ldb, 0, tid);
    gemm_load_tile_h(sm, 1, A, lda, B, ldb, 1, tid);

    for (int it = 0; it < ntiles; it++) {
        if (it < ntiles - 1) {
            asm volatile("cp.async.wait_group 1;\n");
        } else {
            asm volatile("cp.async.wait_group 0;\n");
        }
        __syncthreads();
        if (it + 2 < ntiles)
            gemm_load_tile_h(sm, (it + 2) % 3, A, lda, B, ldb, it + 2, tid);

        __half* Ac = sm + (it % 3) * STAGE_HALFS;
        __half* Bc = Ac + 128 * AS_STRIDE;
#pragma unroll
        for (int kk = 0; kk < 32; kk += 16) {
            FragAh af[4];
            FragBh bf[4];
#pragma unroll
            for (int r = 0; r < 4; r++)
                wmma::load_matrix_sync(af[r], &Ac[(wr * 64 + r * 16) * AS_STRIDE + kk], AS_STRIDE);
#pragma unroll
            for (int c = 0; c < 4; c++)
                wmma::load_matrix_sync(bf[c], &Bc[kk * BS_STRIDE + wc * 64 + c * 16], BS_STRIDE);
#pragma unroll
            for (int r = 0; r < 4; r++)
#pragma unroll
                for (int c = 0; c < 4; c++)
                    wmma::mma_sync(acc[r][c], af[r], bf[c], acc[r][c]);
        }
    }
    __syncthreads();

#pragma unroll
    for (int r = 0; r < 4; r++)
#pragma unroll
        for (int c = 0; c < 4; c++)
            wmma::store_matrix_sync(
                C + (size_t)(wr * 64 + r * 16) * ldc + wc * 64 + c * 16,
                acc[r][c], ldc, wmma::mem_row_major);
}

// ---------------- fused q/k/v/g projections (fp16) ----------------
// grid.x: 0..1 q, 2..3 k, 4..7 v, 8..11 g; grid.y = BT/128
__global__ __launch_bounds__(256) void proj_qkvg_kernel(
    const __half* __restrict__ xh,
    const __half* __restrict__ Wq, const __half* __restrict__ Wk,
    const __half* __restrict__ Wv, const __half* __restrict__ Wg,
    float* __restrict__ q, float* __restrict__ k,
    float* __restrict__ v, float* __restrict__ g)
{
    extern __shared__ __half smh[];
    const int bn = blockIdx.x;
    const int bm = blockIdx.y;
    const __half* B;
    float* C;
    int n0, ldn;
    if (bn < 2)       { B = Wq; C = q; n0 = bn;     ldn = HDK; }
    else if (bn < 4)  { B = Wk; C = k; n0 = bn - 2; ldn = HDK; }
    else if (bn < 8)  { B = Wv; C = v; n0 = bn - 4; ldn = HDV; }
    else              { B = Wg; C = g; n0 = bn - 8; ldn = HDV; }
    gemm128x256_fp16(xh + (size_t)bm * 128 * DM, DM,
                     B + n0 * 256, ldn,
                     C + (size_t)bm * 128 * ldn + n0 * 256, ldn,
                     DM, smh);
}

// ---------------- output projection (fp16) ----------------
__global__ __launch_bounds__(256) void gemm_wo_kernel(
    const __half* __restrict__ yh, const __half* __restrict__ Wo, float* __restrict__ out)
{
    extern __shared__ __half smh[];
    const int bn = blockIdx.x, bm = blockIdx.y;
    gemm128x256_fp16(yh + (size_t)bm * 128 * HDV, HDV,
                     Wo + bn * 256, DM,
                     out + (size_t)bm * 128 * DM + bn * 256,
                     DM, HDV, smh);
}

// ---------------- low-rank gate: x1 = x @ Wgk1 (exact fp32) ----------------
__global__ __launch_bounds__(256) void gk1_kernel(
    const float* __restrict__ x, const float* __restrict__ W, float* __restrict__ x1)
{
    int t = blockIdx.x * 8 + (threadIdx.x >> 5);
    int lane = threadIdx.x & 31;
    if (t >= BT) return;
    const float* xr = x + (size_t)t * DM;
    float acc[LR];
#pragma unroll
    for (int n = 0; n < LR; n++) acc[n] = 0.0f;
    for (int j = lane; j < DM; j += 32) {
        float xv = xr[j];
        const float* wr = W + (size_t)j * LR;
#pragma unroll
        for (int n = 0; n < LR; n++) acc[n] += xv * wr[n];
    }
#pragma unroll
    for (int n = 0; n < LR; n++) {
#pragma unroll
        for (int off = 16; off > 0; off >>= 1)
            acc[n] += __shfl_xor_sync(0xffffffff, acc[n], off);
    }
    if (lane == 0) {
#pragma unroll
        for (int n = 0; n < LR; n++) x1[(size_t)t * LR + n] = acc[n];
    }
}

// ---------------- gk = log_sigmoid(x1 @ Wgk2 + b) / 16 ----------------
__global__ __launch_bounds__(256) void gk2_kernel(
    const float* __restrict__ x1, const float* __restrict__ W2,
    const float* __restrict__ bias, float* __restrict__ gk)
{
    int idx = blockIdx.x * 256 + threadIdx.x;
    if (idx >= BT * HDK) return;
    int t = idx >> 9;
    int n = idx & 511;
    const float* xr = x1 + (size_t)t * LR;
    float a = bias[n];
#pragma unroll
    for (int kx = 0; kx < LR; kx++) a += xr[kx] * W2[kx * HDK + n];
    float ls = fminf(a, 0.0f) - log1pf(expf(-fabsf(a)));
    gk[idx] = ls * (1.0f / GNORM);
}

// ---------------- decay prep (stores tf32-rounded qg/kint/kg) ----------------
__global__ __launch_bounds__(128) void decay_prep_kernel(
    const float* __restrict__ q, const float* __restrict__ k, const float* __restrict__ gk,
    float* __restrict__ qg, float* __restrict__ kint, float* __restrict__ kg,
    float* __restrict__ glast)
{
    int c = blockIdx.x >> 2;
    int col = ((blockIdx.x & 3) << 7) + threadIdx.x;
    size_t base = (size_t)c * CH * HDK + col;
    float tot = 0.0f;
#pragma unroll 8
    for (int i = 0; i < CH; i++) tot += gk[base + (size_t)i * HDK];
    glast[(size_t)c * HDK + col] = __expf(tot);
    const float scale = 0.088388347648318447f;   // 128^-0.5
    float run = 0.0f;
#pragma unroll 4
    for (int i = 0; i < CH; i++) {
        size_t idx = base + (size_t)i * HDK;
        run += gk[idx];
        qg[idx]   = rtf32(q[idx] * __expf(run) * scale);
        kint[idx] = rtf32(k[idx] * __expf(-run));
        kg[idx]   = rtf32(k[idx] * __expf(tot - run));
    }
}

// ---------------- intra A matrix: A = tril(qg @ kint^T), rounded, to global ----------------
__global__ __launch_bounds__(256) void gla_A_kernel(
    const float* __restrict__ qg, const float* __restrict__ kint, float* __restrict__ A)
{
    __shared__ float As[64 * 72];
    const int ch = blockIdx.x;
    const int c = ch >> 2, h = ch & 3;
    const size_t t0 = (size_t)c * CH;
    const float* qgb = qg   + t0 * HDK + h * DKd;
    const float* kib = kint + t0 * HDK + h * DKd;
    const int tid = threadIdx.x, w = tid >> 5;

#pragma unroll
    for (int tIdx = w * 2; tIdx < w * 2 + 2; tIdx++) {
        int ti = tIdx >> 2, tj = tIdx & 3;
        FragC acc;
        wmma::fill_fragment(acc, 0.0f);
#pragma unroll
        for (int kk = 0; kk < DKd; kk += 8) {
            FragA a; FragBT b;
            wmma::load_matrix_sync(a, qgb + (size_t)(ti * 16) * HDK + kk, HDK);
            wmma::load_matrix_sync(b, kib + (size_t)(tj * 16) * HDK + kk, HDK);
            wmma::mma_sync(acc, a, b, acc);
        }
        wmma::store_matrix_sync(&As[(ti * 16) * 72 + tj * 16], acc, 72, wmma::mem_row_major);
    }
    __syncthreads();
    float* Ab = A + (size_t)ch * CH * CH;
    for (int i = tid; i < 64 * 64; i += 256) {
        int r = i >> 6, cc = i & 63;
        Ab[i] = (cc > r) ? 0.0f : rtf32(As[r * 72 + cc]);
    }
}

// ---------------- FUSED chunkwise GLA, dv-block = 32 ----------------
#define S_STRIDE 36
#define V_STRIDE 36
#define U_STRIDE 36

__global__ __launch_bounds__(256) void gla_fused_kernel(
    const float* __restrict__ Amat, const float* __restrict__ qg,
    const float* __restrict__ kg, const float* __restrict__ v,
    const float* __restrict__ glast, float* __restrict__ o)
{
    __shared__ float Ssm[128 * S_STRIDE];
    __shared__ float Vs[64 * V_STRIDE];
    __shared__ float Us[128 * U_STRIDE];
    __shared__ float sgl[128];

    const int id = blockIdx.x;
    const int b = id >> 5, h = (id >> 3) & 3, dvb = id & 7;
    const int tid = threadIdx.x, w = tid >> 5;

    for (int i = tid; i < 128 * S_STRIDE; i += 256) Ssm[i] = 0.0f;

    for (int n = 0; n < NC; n++) {
        const int c = b * NC + n;
        const int ch = c * HH + h;
        const size_t t0 = (size_t)c * CH;
        const float* qgb = qg + t0 * HDK + h * DKd;
        const float* kgb = kg + t0 * HDK + h * DKd;
        const float* vb  = v  + t0 * HDV + h * DVd + dvb * 32;
        const float* Ab  = Amat + (size_t)ch * CH * CH;
        float* ob        = o  + t0 * HDV + h * DVd + dvb * 32;

        __syncthreads();

#pragma unroll
        for (int j = 0; j < 2; j++) {
            int idx = j * 256 + tid;
            int r = idx >> 3, c4 = idx & 7;
            *(float4*)&Vs[r * V_STRIDE + c4 * 4] =
                *(const float4*)&vb[(size_t)r * HDV + c4 * 4];
        }
        if (tid < 128) sgl[tid] = glast[(size_t)c * HDK + h * DKd + tid];
        __syncthreads();

        // o = A @ Vs + qg @ S
        {
            int ti = w >> 1;
            int tj = w & 1;
            FragC acc2;
            wmma::fill_fragment(acc2, 0.0f);
#pragma unroll
            for (int kk = 0; kk < CH; kk += 8) {
                FragA a; FragB bf;
                wmma::load_matrix_sync(a, Ab + (size_t)(ti * 16) * CH + kk, CH);
                wmma::load_matrix_sync(bf, &Vs[kk * V_STRIDE + tj * 16], V_STRIDE);
                wmma::mma_sync(acc2, a, bf, acc2);
            }
#pragma unroll
            for (int kk = 0; kk < DKd; kk += 8) {
                FragA a; FragB bf;
                wmma::load_matrix_sync(a, qgb + (size_t)(ti * 16) * HDK + kk, HDK);
                wmma::load_matrix_sync(bf, &Ssm[kk * S_STRIDE + tj * 16], S_STRIDE);
                to_tf32(bf);
                wmma::mma_sync(acc2, a, bf, acc2);
            }
            wmma::store_matrix_sync(ob + (size_t)(ti * 16) * HDV + tj * 16,
                                    acc2, HDV, wmma::mem_row_major);
        }

        // U = kg^T @ Vs
        {
            FragC acc4[2];
#pragma unroll
            for (int j = 0; j < 2; j++) wmma::fill_fragment(acc4[j], 0.0f);
#pragma unroll
            for (int kk = 0; kk < CH; kk += 8) {
                FragAT a;
                wmma::load_matrix_sync(a, kgb + (size_t)kk * HDK + w * 16, HDK);
#pragma unroll
                for (int j = 0; j < 2; j++) {
                    FragB bf;
                    wmma::load_matrix_sync(bf, &Vs[kk * V_STRIDE + j * 16], V_STRIDE);
                    wmma::mma_sync(acc4[j], a, bf, acc4[j]);
                }
            }
#pragma unroll
            for (int j = 0; j < 2; j++)
                wmma::store_matrix_sync(&Us[(w * 16) * U_STRIDE + j * 16], acc4[j],
                                        U_STRIDE, wmma::mem_row_major);
        }
        __syncthreads();

        // S = S * diag(gl) + U
#pragma unroll
        for (int j = 0; j < 16; j++) {
            int i = j * 256 + tid;
            int r = i >> 5, cc = i & 31;
            Ssm[r * S_STRIDE + cc] = Ssm[r * S_STRIDE + cc] * sgl[r] + Us[r * U_STRIDE + cc];
        }
    }
}

// ---------------- gated RMSNorm (emits fp16 y) ----------------
__global__ __launch_bounds__(256) void norm_gate_kernel(
    const float* __restrict__ o, const float* __restrict__ g,
    const float* __restrict__ gnw, __half* __restrict__ yh)
{
    int row = blockIdx.x * 8 + (threadIdx.x >> 5);
    int lane = threadIdx.x & 31;
    size_t base = (size_t)row * DVd;
    float v[8];
    float ss = 0.0f;
#pragma unroll
    for (int j = 0; j < 8; j++) {
        v[j] = o[base + lane + j * 32];
        ss += v[j] * v[j];
    }
#pragma unroll
    for (int off = 16; off > 0; off >>= 1)
        ss += __shfl_xor_sync(0xffffffff, ss, off);
    float r = rsqrtf(ss * (1.0f / DVd) + EPS);
#pragma unroll
    for (int j = 0; j < 8; j++) {
        int dv = lane + j * 32;
        float gv = g[base + dv];
        float sw = gv / (1.0f + expf(-gv));
        yh[base + dv] = __float2half(v[j] * r * gnw[dv] * sw);
    }
}

// ---------------- launch ----------------
extern "C" void kernel_launch(void* const* d_in, const int* in_sizes, int n_in,
                              void* d_out, int out_size)
{
    const float* x    = (const float*)d_in[0];
    const float* Wq   = (const float*)d_in[1];
    const float* Wk   = (const float*)d_in[2];
    const float* Wv   = (const float*)d_in[3];
    const float* Wg   = (const float*)d_in[4];
    const float* Wgk1 = (const float*)d_in[5];
    const float* Wgk2 = (const float*)d_in[6];
    const float* bgk2 = (const float*)d_in[7];
    const float* Wo   = (const float*)d_in[8];
    const float* gnw  = (const float*)d_in[9];
    float* out = (float*)d_out;

    __half *xh, *Wqh, *Wkh, *Wvh, *Wgh, *Woh, *yh;
    float *q, *k, *v, *g, *gk, *x1, *qg, *kint, *kg, *glast, *A, *o;
    cudaGetSymbolAddress((void**)&xh, d_xh);
    cudaGetSymbolAddress((void**)&Wqh, d_Wqh);
    cudaGetSymbolAddress((void**)&Wkh, d_Wkh);
    cudaGetSymbolAddress((void**)&Wvh, d_Wvh);
    cudaGetSymbolAddress((void**)&Wgh, d_Wgh);
    cudaGetSymbolAddress((void**)&Woh, d_Woh);
    cudaGetSymbolAddress((void**)&yh, d_yh);
    cudaGetSymbolAddress((void**)&q, d_q);
    cudaGetSymbolAddress((void**)&k, d_k);
    cudaGetSymbolAddress((void**)&v, d_v);
    cudaGetSymbolAddress((void**)&g, d_g);
    cudaGetSymbolAddress((void**)&gk, d_gk);
    cudaGetSymbolAddress((void**)&x1, d_x1);
    cudaGetSymbolAddress((void**)&qg, d_qg);
    cudaGetSymbolAddress((void**)&kint, d_kint);
    cudaGetSymbolAddress((void**)&kg, d_kg);
    cudaGetSymbolAddress((void**)&glast, d_glast);
    cudaGetSymbolAddress((void**)&A, d_A);
    cudaGetSymbolAddress((void**)&o, d_o);

    cudaFuncSetAttribute(proj_qkvg_kernel,
                         cudaFuncAttributeMaxDynamicSharedMemorySize, GEMM_SMEM_BYTES);
    cudaFuncSetAttribute(gemm_wo_kernel,
                         cudaFuncAttributeMaxDynamicSharedMemorySize, GEMM_SMEM_BYTES);

    // pre-passes: fp16 conversions
    f2h_kernel<<<(BT * DM / 4) / 256, 256>>>((const float4*)x, (uint2*)xh, BT * DM / 4);
    f2h_kernel<<<(DM * HDK / 4) / 256, 256>>>((const float4*)Wq, (uint2*)Wqh, DM * HDK / 4);
    f2h_kernel<<<(DM * HDK / 4) / 256, 256>>>((const float4*)Wk, (uint2*)Wkh, DM * HDK / 4);
    f2h_kernel<<<(DM * HDV / 4) / 256, 256>>>((const float4*)Wv, (uint2*)Wvh, DM * HDV / 4);
    f2h_kernel<<<(DM * HDV / 4) / 256, 256>>>((const float4*)Wg, (uint2*)Wgh, DM * HDV / 4);
    f2h_kernel<<<(HDV * DM / 4) / 256, 256>>>((const float4*)Wo, (uint2*)Woh, HDV * DM / 4);

    // fused input projections (fp16 HMMA)
    proj_qkvg_kernel<<<dim3(12, BT / 128), 256, GEMM_SMEM_BYTES>>>(xh, Wqh, Wkh, Wvh, Wgh, q, k, v, g);

    // low-rank gate path (exact fp32 on original x)
    gk1_kernel<<<BT / 8, 256>>>(x, Wgk1, x1);
    gk2_kernel<<<(BT * HDK) / 256, 256>>>(x1, Wgk2, bgk2, gk);

    // decay factors (tf32-rounded at store)
    decay_prep_kernel<<<NCHUNK * 4, 128>>>(q, k, gk, qg, kint, kg, glast);

    // round v in place (feeds tf32 tensor ops in GLA)
    round_tf32_kernel<<<(BT * HDV / 4) / 256, 256>>>((const float4*)v, (float4*)v, BT * HDV / 4);

    // intra A matrices (once per chunk-head)
    gla_A_kernel<<<NCHUNK * HH, 256>>>(qg, kint, A);

    // fused chunkwise GLA
    gla_fused_kernel<<<BB * HH * 8, 256>>>(A, qg, kg, v, glast, o);

    // gated RMSNorm (fp16 y) + output projection (fp16 HMMA)
    norm_gate_kernel<<<(BT * HH) / 8, 256>>>(o, g, gnw, yh);
    gemm_wo_kernel<<<dim3(DM / 256, BT / 128), 256, GEMM_SMEM_BYTES>>>(yh, Woh, out);
}

// round 9
// speedup vs baseline: 2.7348x; 1.2433x over previous
#include <cuda_runtime.h>
#include <cuda_fp16.h>
#include <mma.h>
#include <cstdint>

using namespace nvcuda;

// ---------------- problem constants ----------------
#define BB 4
#define TT 2048
#define DM 1024
#define HH 4
#define DKd 128
#define DVd 256
#define HDK 512     // H*DK
#define HDV 1024    // H*DV
#define BT  8192    // B*T tokens
#define CH  64      // chunk
#define NC  32      // chunks per sequence
#define NCHUNK 128  // total chunks (B*NC)
#define LR 16       // gate low rank
#define GNORM 16.0f
#define EPS 1e-5f

// ---------------- scratch ----------------
__device__ __half d_xh [BT * DM];
__device__ __half d_Wqh[DM * HDK];
__device__ __half d_Wkh[DM * HDK];
__device__ __half d_Wvh[DM * HDV];
__device__ __half d_Wgh[DM * HDV];
__device__ __half d_Woh[HDV * DM];
__device__ __half d_yh [BT * HDV];
__device__ __half d_qgh[BT * HDK];      // fp16 qg (fused kernel)
__device__ __half d_kgh[BT * HDK];      // fp16 kg (fused kernel)
__device__ __half d_vh [BT * HDV];      // fp16 v (fused kernel)
__device__ __half d_Ah [NCHUNK * HH * CH * CH];  // fp16 masked intra A
__device__ float d_q   [BT * HDK];
__device__ float d_k   [BT * HDK];
__device__ float d_v   [BT * HDV];
__device__ float d_g   [BT * HDV];
__device__ float d_gk  [BT * HDK];
__device__ float d_x1  [BT * LR];
__device__ float d_qg  [BT * HDK];      // tf32-rounded (gla_A)
__device__ float d_kint[BT * HDK];      // tf32-rounded (gla_A; may exceed fp16 range)
__device__ float d_glast[NCHUNK * HDK];
__device__ float d_o   [BT * HDV];

// ---------------- helpers ----------------
__device__ __forceinline__ float rtf32(float x) {
    return wmma::__float_to_tf32(x);
}

// tf32 fragments (gla_A only)
typedef wmma::fragment<wmma::matrix_a, 16, 16, 8, wmma::precision::tf32, wmma::row_major> FragA;
typedef wmma::fragment<wmma::matrix_b, 16, 16, 8, wmma::precision::tf32, wmma::col_major> FragBT;
typedef wmma::fragment<wmma::accumulator, 16, 16, 8, float> FragC;

// fp16 fragments
typedef wmma::fragment<wmma::matrix_a, 16, 16, 16, __half, wmma::row_major> FragAh;
typedef wmma::fragment<wmma::matrix_a, 16, 16, 16, __half, wmma::col_major> FragAhT;
typedef wmma::fragment<wmma::matrix_b, 16, 16, 16, __half, wmma::row_major> FragBh;
typedef wmma::fragment<wmma::accumulator, 16, 16, 16, float> FragCh;

__device__ __forceinline__ uint32_t smem_u32(const void* p) {
    return (uint32_t)__cvta_generic_to_shared(p);
}
__device__ __forceinline__ void cpasync16(void* dst, const void* src) {
    asm volatile("cp.async.cg.shared.global [%0], [%1], 16;\n"
                 :: "r"(smem_u32(dst)), "l"(src));
}
__device__ __forceinline__ void cp_commit() {
    asm volatile("cp.async.commit_group;\n");
}

// ---------------- float -> half conversion ----------------
__global__ __launch_bounds__(256) void f2h_kernel(
    const float4* __restrict__ in, uint2* __restrict__ out, int n4)
{
    int i = blockIdx.x * 256 + threadIdx.x;
    if (i >= n4) return;
    float4 a = in[i];
    __half2 lo = __floats2half2_rn(a.x, a.y);
    __half2 hi = __floats2half2_rn(a.z, a.w);
    uint2 p;
    p.x = *(uint32_t*)&lo;
    p.y = *(uint32_t*)&hi;
    out[i] = p;
}

// ---------------- 3-stage pipelined fp16 GEMM: CTA 128x256, warp 64x64, BK=32 ----------------
#define AS_STRIDE 40     // halves
#define BS_STRIDE 264    // halves
#define STAGE_HALFS (128 * AS_STRIDE + 32 * BS_STRIDE)   // 13568
#define GEMM_SMEM_BYTES (3 * STAGE_HALFS * 2)            // 81408

__device__ __forceinline__ void gemm_load_tile_h(
    __half* sm, int buf, const __half* A, int lda, const __half* B, int ldb, int it, int tid)
{
    __half* As = sm + buf * STAGE_HALFS;
    __half* Bs = As + 128 * AS_STRIDE;
    const __half* Ab = A + it * 32;
    const __half* Bb = B + (size_t)it * 32 * ldb;
#pragma unroll
    for (int i = tid; i < 512; i += 256) {
        int r = i >> 2, c = i & 3;
        cpasync16(&As[r * AS_STRIDE + c * 8], Ab + (size_t)r * lda + c * 8);
    }
#pragma unroll
    for (int i = tid; i < 1024; i += 256) {
        int r = i >> 5, c = i & 31;
        cpasync16(&Bs[r * BS_STRIDE + c * 8], Bb + (size_t)r * ldb + c * 8);
    }
    cp_commit();
}

__device__ __forceinline__ void gemm128x256_fp16(
    const __half* __restrict__ A, int lda,
    const __half* __restrict__ B, int ldb,
    float* __restrict__ C, int ldc,
    int K, __half* sm)
{
    const int tid = threadIdx.x;
    const int w = tid >> 5;
    const int wr = w >> 2;
    const int wc = w & 3;

    FragCh acc[4][4];
#pragma unroll
    for (int r = 0; r < 4; r++)
#pragma unroll
        for (int c = 0; c < 4; c++) wmma::fill_fragment(acc[r][c], 0.0f);

    const int ntiles = K / 32;

    gemm_load_tile_h(sm, 0, A, lda, B, ldb, 0, tid);
    gemm_load_tile_h(sm, 1, A, lda, B, ldb, 1, tid);

    for (int it = 0; it < ntiles; it++) {
        if (it < ntiles - 1) {
            asm volatile("cp.async.wait_group 1;\n");
        } else {
            asm volatile("cp.async.wait_group 0;\n");
        }
        __syncthreads();
        if (it + 2 < ntiles)
            gemm_load_tile_h(sm, (it + 2) % 3, A, lda, B, ldb, it + 2, tid);

        __half* Ac = sm + (it % 3) * STAGE_HALFS;
        __half* Bc = Ac + 128 * AS_STRIDE;
#pragma unroll
        for (int kk = 0; kk < 32; kk += 16) {
            FragAh af[4];
            FragBh bf[4];
#pragma unroll
            for (int r = 0; r < 4; r++)
                wmma::load_matrix_sync(af[r], &Ac[(wr * 64 + r * 16) * AS_STRIDE + kk], AS_STRIDE);
#pragma unroll
            for (int c = 0; c < 4; c++)
                wmma::load_matrix_sync(bf[c], &Bc[kk * BS_STRIDE + wc * 64 + c * 16], BS_STRIDE);
#pragma unroll
            for (int r = 0; r < 4; r++)
#pragma unroll
                for (int c = 0; c < 4; c++)
                    wmma::mma_sync(acc[r][c], af[r], bf[c], acc[r][c]);
        }
    }
    __syncthreads();

#pragma unroll
    for (int r = 0; r < 4; r++)
#pragma unroll
        for (int c = 0; c < 4; c++)
            wmma::store_matrix_sync(
                C + (size_t)(wr * 64 + r * 16) * ldc + wc * 64 + c * 16,
                acc[r][c], ldc, wmma::mem_row_major);
}

// ---------------- fused q/k/v/g projections (fp16) ----------------
__global__ __launch_bounds__(256) void proj_qkvg_kernel(
    const __half* __restrict__ xh,
    const __half* __restrict__ Wq, const __half* __restrict__ Wk,
    const __half* __restrict__ Wv, const __half* __restrict__ Wg,
    float* __restrict__ q, float* __restrict__ k,
    float* __restrict__ v, float* __restrict__ g)
{
    extern __shared__ __half smh[];
    const int bn = blockIdx.x;
    const int bm = blockIdx.y;
    const __half* B;
    float* C;
    int n0, ldn;
    if (bn < 2)       { B = Wq; C = q; n0 = bn;     ldn = HDK; }
    else if (bn < 4)  { B = Wk; C = k; n0 = bn - 2; ldn = HDK; }
    else if (bn < 8)  { B = Wv; C = v; n0 = bn - 4; ldn = HDV; }
    else              { B = Wg; C = g; n0 = bn - 8; ldn = HDV; }
    gemm128x256_fp16(xh + (size_t)bm * 128 * DM, DM,
                     B + n0 * 256, ldn,
                     C + (size_t)bm * 128 * ldn + n0 * 256, ldn,
                     DM, smh);
}

// ---------------- output projection (fp16) ----------------
__global__ __launch_bounds__(256) void gemm_wo_kernel(
    const __half* __restrict__ yh, const __half* __restrict__ Wo, float* __restrict__ out)
{
    extern __shared__ __half smh[];
    const int bn = blockIdx.x, bm = blockIdx.y;
    gemm128x256_fp16(yh + (size_t)bm * 128 * HDV, HDV,
                     Wo + bn * 256, DM,
                     out + (size_t)bm * 128 * DM + bn * 256,
                     DM, HDV, smh);
}

// ---------------- low-rank gate: x1 = x @ Wgk1 (exact fp32) ----------------
__global__ __launch_bounds__(256) void gk1_kernel(
    const float* __restrict__ x, const float* __restrict__ W, float* __restrict__ x1)
{
    int t = blockIdx.x * 8 + (threadIdx.x >> 5);
    int lane = threadIdx.x & 31;
    if (t >= BT) return;
    const float* xr = x + (size_t)t * DM;
    float acc[LR];
#pragma unroll
    for (int n = 0; n < LR; n++) acc[n] = 0.0f;
    for (int j = lane; j < DM; j += 32) {
        float xv = xr[j];
        const float* wr = W + (size_t)j * LR;
#pragma unroll
        for (int n = 0; n < LR; n++) acc[n] += xv * wr[n];
    }
#pragma unroll
    for (int n = 0; n < LR; n++) {
#pragma unroll
        for (int off = 16; off > 0; off >>= 1)
            acc[n] += __shfl_xor_sync(0xffffffff, acc[n], off);
    }
    if (lane == 0) {
#pragma unroll
        for (int n = 0; n < LR; n++) x1[(size_t)t * LR + n] = acc[n];
    }
}

// ---------------- gk = log_sigmoid(x1 @ Wgk2 + b) / 16 ----------------
__global__ __launch_bounds__(256) void gk2_kernel(
    const float* __restrict__ x1, const float* __restrict__ W2,
    const float* __restrict__ bias, float* __restrict__ gk)
{
    int idx = blockIdx.x * 256 + threadIdx.x;
    if (idx >= BT * HDK) return;
    int t = idx >> 9;
    int n = idx & 511;
    const float* xr = x1 + (size_t)t * LR;
    float a = bias[n];
#pragma unroll
    for (int kx = 0; kx < LR; kx++) a += xr[kx] * W2[kx * HDK + n];
    float ls = fminf(a, 0.0f) - log1pf(expf(-fabsf(a)));
    gk[idx] = ls * (1.0f / GNORM);
}

// ---------------- decay prep: fp32 qg/kint (gla_A) + fp16 qg/kg (fused) ----------------
__global__ __launch_bounds__(128) void decay_prep_kernel(
    const float* __restrict__ q, const float* __restrict__ k, const float* __restrict__ gk,
    float* __restrict__ qg, float* __restrict__ kint,
    __half* __restrict__ qgh, __half* __restrict__ kgh,
    float* __restrict__ glast)
{
    int c = blockIdx.x >> 2;
    int col = ((blockIdx.x & 3) << 7) + threadIdx.x;
    size_t base = (size_t)c * CH * HDK + col;
    float tot = 0.0f;
#pragma unroll 8
    for (int i = 0; i < CH; i++) tot += gk[base + (size_t)i * HDK];
    glast[(size_t)c * HDK + col] = __expf(tot);
    const float scale = 0.088388347648318447f;   // 128^-0.5
    float run = 0.0f;
#pragma unroll 4
    for (int i = 0; i < CH; i++) {
        size_t idx = base + (size_t)i * HDK;
        run += gk[idx];
        float qv = q[idx] * __expf(run) * scale;
        float kgv = k[idx] * __expf(tot - run);
        qg[idx]   = rtf32(qv);
        kint[idx] = rtf32(k[idx] * __expf(-run));
        qgh[idx]  = __float2half(qv);
        kgh[idx]  = __float2half(kgv);
    }
}

// ---------------- intra A matrix: tf32 compute, fp16 masked store ----------------
__global__ __launch_bounds__(256) void gla_A_kernel(
    const float* __restrict__ qg, const float* __restrict__ kint, __half* __restrict__ Ah)
{
    __shared__ float As[64 * 72];
    const int ch = blockIdx.x;
    const int c = ch >> 2, h = ch & 3;
    const size_t t0 = (size_t)c * CH;
    const float* qgb = qg   + t0 * HDK + h * DKd;
    const float* kib = kint + t0 * HDK + h * DKd;
    const int tid = threadIdx.x, w = tid >> 5;

#pragma unroll
    for (int tIdx = w * 2; tIdx < w * 2 + 2; tIdx++) {
        int ti = tIdx >> 2, tj = tIdx & 3;
        FragC acc;
        wmma::fill_fragment(acc, 0.0f);
#pragma unroll
        for (int kk = 0; kk < DKd; kk += 8) {
            FragA a; FragBT b;
            wmma::load_matrix_sync(a, qgb + (size_t)(ti * 16) * HDK + kk, HDK);
            wmma::load_matrix_sync(b, kib + (size_t)(tj * 16) * HDK + kk, HDK);
            wmma::mma_sync(acc, a, b, acc);
        }
        wmma::store_matrix_sync(&As[(ti * 16) * 72 + tj * 16], acc, 72, wmma::mem_row_major);
    }
    __syncthreads();
    __half* Ab = Ah + (size_t)ch * CH * CH;
    for (int i = tid; i < 64 * 64; i += 256) {
        int r = i >> 6, cc = i & 63;
        Ab[i] = (cc > r) ? __float2half(0.0f) : __float2half(As[r * 72 + cc]);
    }
}

// ---------------- FUSED chunkwise GLA (fp16 MMAs, fp32 S master), dv-block = 32 ----------------
#define S_STRIDE 36     // fp32 master
#define SH_STRIDE 40    // fp16 shadow (halves)
#define VH_STRIDE 40    // halves
#define U_STRIDE 36

__global__ __launch_bounds__(256) void gla_fused_kernel(
    const __half* __restrict__ Amat, const __half* __restrict__ qgh,
    const __half* __restrict__ kgh, const __half* __restrict__ vh,
    const float* __restrict__ glast, float* __restrict__ o)
{
    __shared__ float  Ssm[128 * S_STRIDE];
    __shared__ __half Sh [128 * SH_STRIDE];
    __shared__ __half Vsh[64 * VH_STRIDE];
    __shared__ float  Us [128 * U_STRIDE];
    __shared__ float  sgl[128];

    const int id = blockIdx.x;
    const int b = id >> 5, h = (id >> 3) & 3, dvb = id & 7;
    const int tid = threadIdx.x, w = tid >> 5;

    for (int i = tid; i < 128 * S_STRIDE; i += 256) Ssm[i] = 0.0f;
    for (int i = tid; i < 128 * SH_STRIDE / 2; i += 256)
        *((__half2*)Sh + i) = __half2half2(__float2half(0.0f));

    for (int n = 0; n < NC; n++) {
        const int c = b * NC + n;
        const int ch = c * HH + h;
        const size_t t0 = (size_t)c * CH;
        const __half* qgb = qgh + t0 * HDK + h * DKd;
        const __half* kgb = kgh + t0 * HDK + h * DKd;
        const __half* vb  = vh  + t0 * HDV + h * DVd + dvb * 32;
        const __half* Ab  = Amat + (size_t)ch * CH * CH;
        float* ob         = o   + t0 * HDV + h * DVd + dvb * 32;

        __syncthreads();   // prev S/Sh update done; Vsh free

        // stage v slice (64 rows x 32 halves) -- uint4 = 16 B = 8 halves per thread
        {
            int r = tid >> 2, c8 = tid & 3;       // 256 thr -> 64 rows x 4 chunks of 8 halves
            *(uint4*)&Vsh[r * VH_STRIDE + c8 * 8] =
                *(const uint4*)&vb[(size_t)r * HDV + c8 * 8];
        }
        if (tid < 128) sgl[tid] = glast[(size_t)c * HDK + h * DKd + tid];
        __syncthreads();

        // ---- o = A @ Vsh + qg @ Sh  (64x32; warp -> one 16x16 frag) ----
        {
            int ti = w >> 1;
            int tj = w & 1;
            FragCh acc2;
            wmma::fill_fragment(acc2, 0.0f);
#pragma unroll
            for (int kk = 0; kk < CH; kk += 16) {
                FragAh a; FragBh bf;
                wmma::load_matrix_sync(a, Ab + (size_t)(ti * 16) * CH + kk, CH);
                wmma::load_matrix_sync(bf, &Vsh[kk * VH_STRIDE + tj * 16], VH_STRIDE);
                wmma::mma_sync(acc2, a, bf, acc2);
            }
#pragma unroll
            for (int kk = 0; kk < DKd; kk += 16) {
                FragAh a; FragBh bf;
                wmma::load_matrix_sync(a, qgb + (size_t)(ti * 16) * HDK + kk, HDK);
                wmma::load_matrix_sync(bf, &Sh[kk * SH_STRIDE + tj * 16], SH_STRIDE);
                wmma::mma_sync(acc2, a, bf, acc2);
            }
            wmma::store_matrix_sync(ob + (size_t)(ti * 16) * HDV + tj * 16,
                                    acc2, HDV, wmma::mem_row_major);
        }

        // ---- U = kg^T (128x32) @ Vsh (64x32) ----
        {
            FragCh acc4[2];
#pragma unroll
            for (int j = 0; j < 2; j++) wmma::fill_fragment(acc4[j], 0.0f);
#pragma unroll
            for (int kk = 0; kk < CH; kk += 16) {
                FragAhT a;
                wmma::load_matrix_sync(a, kgb + (size_t)kk * HDK + w * 16, HDK);
#pragma unroll
                for (int j = 0; j < 2; j++) {
                    FragBh bf;
                    wmma::load_matrix_sync(bf, &Vsh[kk * VH_STRIDE + j * 16], VH_STRIDE);
                    wmma::mma_sync(acc4[j], a, bf, acc4[j]);
                }
            }
#pragma unroll
            for (int j = 0; j < 2; j++)
                wmma::store_matrix_sync(&Us[(w * 16) * U_STRIDE + j * 16], acc4[j],
                                        U_STRIDE, wmma::mem_row_major);
        }
        __syncthreads();

        // ---- S = S * diag(gl) + U  (fp32 master + fp16 shadow) ----
#pragma unroll
        for (int j = 0; j < 16; j++) {
            int i = j * 256 + tid;
            int r = i >> 5, cc = i & 31;
            float s = Ssm[r * S_STRIDE + cc] * sgl[r] + Us[r * U_STRIDE + cc];
            Ssm[r * S_STRIDE + cc] = s;
            Sh[r * SH_STRIDE + cc] = __float2half(s);
        }
    }
}

// ---------------- gated RMSNorm (emits fp16 y) ----------------
__global__ __launch_bounds__(256) void norm_gate_kernel(
    const float* __restrict__ o, const float* __restrict__ g,
    const float* __restrict__ gnw, __half* __restrict__ yh)
{
    int row = blockIdx.x * 8 + (threadIdx.x >> 5);
    int lane = threadIdx.x & 31;
    size_t base = (size_t)row * DVd;
    float v[8];
    float ss = 0.0f;
#pragma unroll
    for (int j = 0; j < 8; j++) {
        v[j] = o[base + lane + j * 32];
        ss += v[j] * v[j];
    }
#pragma unroll
    for (int off = 16; off > 0; off >>= 1)
        ss += __shfl_xor_sync(0xffffffff, ss, off);
    float r = rsqrtf(ss * (1.0f / DVd) + EPS);
#pragma unroll
    for (int j = 0; j < 8; j++) {
        int dv = lane + j * 32;
        float gv = g[base + dv];
        float sw = gv / (1.0f + expf(-gv));
        yh[base + dv] = __float2half(v[j] * r * gnw[dv] * sw);
    }
}

// ---------------- launch ----------------
extern "C" void kernel_launch(void* const* d_in, const int* in_sizes, int n_in,
                              void* d_out, int out_size)
{
    const float* x    = (const float*)d_in[0];
    const float* Wq   = (const float*)d_in[1];
    const float* Wk   = (const float*)d_in[2];
    const float* Wv   = (const float*)d_in[3];
    const float* Wg   = (const float*)d_in[4];
    const float* Wgk1 = (const float*)d_in[5];
    const float* Wgk2 = (const float*)d_in[6];
    const float* bgk2 = (const float*)d_in[7];
    const float* Wo   = (const float*)d_in[8];
    const float* gnw  = (const float*)d_in[9];
    float* out = (float*)d_out;

    __half *xh, *Wqh, *Wkh, *Wvh, *Wgh, *Woh, *yh, *qgh, *kgh, *vh, *Ah;
    float *q, *k, *v, *g, *gk, *x1, *qg, *kint, *glast, *o;
    cudaGetSymbolAddress((void**)&xh, d_xh);
    cudaGetSymbolAddress((void**)&Wqh, d_Wqh);
    cudaGetSymbolAddress((void**)&Wkh, d_Wkh);
    cudaGetSymbolAddress((void**)&Wvh, d_Wvh);
    cudaGetSymbolAddress((void**)&Wgh, d_Wgh);
    cudaGetSymbolAddress((void**)&Woh, d_Woh);
    cudaGetSymbolAddress((void**)&yh, d_yh);
    cudaGetSymbolAddress((void**)&qgh, d_qgh);
    cudaGetSymbolAddress((void**)&kgh, d_kgh);
    cudaGetSymbolAddress((void**)&vh, d_vh);
    cudaGetSymbolAddress((void**)&Ah, d_Ah);
    cudaGetSymbolAddress((void**)&q, d_q);
    cudaGetSymbolAddress((void**)&k, d_k);
    cudaGetSymbolAddress((void**)&v, d_v);
    cudaGetSymbolAddress((void**)&g, d_g);
    cudaGetSymbolAddress((void**)&gk, d_gk);
    cudaGetSymbolAddress((void**)&x1, d_x1);
    cudaGetSymbolAddress((void**)&qg, d_qg);
    cudaGetSymbolAddress((void**)&kint, d_kint);
    cudaGetSymbolAddress((void**)&glast, d_glast);
    cudaGetSymbolAddress((void**)&o, d_o);

    cudaFuncSetAttribute(proj_qkvg_kernel,
                         cudaFuncAttributeMaxDynamicSharedMemorySize, GEMM_SMEM_BYTES);
    cudaFuncSetAttribute(gemm_wo_kernel,
                         cudaFuncAttributeMaxDynamicSharedMemorySize, GEMM_SMEM_BYTES);

    // pre-passes: fp16 conversions
    f2h_kernel<<<(BT * DM / 4) / 256, 256>>>((const float4*)x, (uint2*)xh, BT * DM / 4);
    f2h_kernel<<<(DM * HDK / 4) / 256, 256>>>((const float4*)Wq, (uint2*)Wqh, DM * HDK / 4);
    f2h_kernel<<<(DM * HDK / 4) / 256, 256>>>((const float4*)Wk, (uint2*)Wkh, DM * HDK / 4);
    f2h_kernel<<<(DM * HDV / 4) / 256, 256>>>((const float4*)Wv, (uint2*)Wvh, DM * HDV / 4);
    f2h_kernel<<<(DM * HDV / 4) / 256, 256>>>((const float4*)Wg, (uint2*)Wgh, DM * HDV / 4);
    f2h_kernel<<<(HDV * DM / 4) / 256, 256>>>((const float4*)Wo, (uint2*)Woh, HDV * DM / 4);

    // fused input projections (fp16 HMMA)
    proj_qkvg_kernel<<<dim3(12, BT / 128), 256, GEMM_SMEM_BYTES>>>(xh, Wqh, Wkh, Wvh, Wgh, q, k, v, g);

    // low-rank gate path (exact fp32 on original x)
    gk1_kernel<<<BT / 8, 256>>>(x, Wgk1, x1);
    gk2_kernel<<<(BT * HDK) / 256, 256>>>(x1, Wgk2, bgk2, gk);

    // decay factors: fp32 (tf32-rounded) for gla_A, fp16 for fused
    decay_prep_kernel<<<NCHUNK * 4, 128>>>(q, k, gk, qg, kint, qgh, kgh, glast);

    // v -> fp16 for fused kernel
    f2h_kernel<<<(BT * HDV / 4) / 256, 256>>>((const float4*)v, (uint2*)vh, BT * HDV / 4);

    // intra A matrices (tf32 compute, fp16 store)
    gla_A_kernel<<<NCHUNK * HH, 256>>>(qg, kint, Ah);

    // fused chunkwise GLA (fp16 MMAs, fp32 S master)
    gla_fused_kernel<<<BB * HH * 8, 256>>>(Ah, qgh, kgh, vh, glast, o);

    // gated RMSNorm (fp16 y) + output projection (fp16 HMMA)
    norm_gate_kernel<<<(BT * HH) / 8, 256>>>(o, g, gnw, yh);
    gemm_wo_kernel<<<dim3(DM / 256, BT / 128), 256, GEMM_SMEM_BYTES>>>(yh, Woh, out);
}

// round 10
// speedup vs baseline: 2.9016x; 1.0610x over previous
#include <cuda_runtime.h>
#include <cuda_fp16.h>
#include <mma.h>
#include <cstdint>

using namespace nvcuda;

// ---------------- problem constants ----------------
#define BB 4
#define TT 2048
#define DM 1024
#define HH 4
#define DKd 128
#define DVd 256
#define HDK 512     // H*DK
#define HDV 1024    // H*DV
#define BT  8192    // B*T tokens
#define CH  64      // chunk
#define NC  32      // chunks per sequence
#define NCHUNK 128  // total chunks (B*NC)
#define LR 16       // gate low rank
#define GNORM 16.0f
#define EPS 1e-5f

// ---------------- scratch ----------------
__device__ __half d_xh [BT * DM];
__device__ __half d_Wqh[DM * HDK];
__device__ __half d_Wkh[DM * HDK];
__device__ __half d_Wvh[DM * HDV];
__device__ __half d_Wgh[DM * HDV];
__device__ __half d_Woh[HDV * DM];
__device__ __half d_yh [BT * HDV];
__device__ __half d_qgh[BT * HDK];      // fp16 qg (fused kernel)
__device__ __half d_kgh[BT * HDK];      // fp16 kg (fused kernel)
__device__ __half d_Ah [NCHUNK * HH * CH * CH];  // fp16 masked intra A
__device__ float d_q   [BT * HDK];
__device__ float d_k   [BT * HDK];
__device__ float d_v   [BT * HDV];
__device__ float d_g   [BT * HDV];
__device__ float d_gk  [BT * HDK];
__device__ float d_qg  [BT * HDK];      // tf32-rounded (gla_A)
__device__ float d_kint[BT * HDK];      // tf32-rounded (gla_A; may exceed fp16 range)
__device__ float d_glast[NCHUNK * HDK];
__device__ float d_o   [BT * HDV];

// ---------------- helpers ----------------
__device__ __forceinline__ float rtf32(float x) {
    return wmma::__float_to_tf32(x);
}

// tf32 fragments (gla_A only)
typedef wmma::fragment<wmma::matrix_a, 16, 16, 8, wmma::precision::tf32, wmma::row_major> FragA;
typedef wmma::fragment<wmma::matrix_b, 16, 16, 8, wmma::precision::tf32, wmma::col_major> FragBT;
typedef wmma::fragment<wmma::accumulator, 16, 16, 8, float> FragC;

// fp16 fragments
typedef wmma::fragment<wmma::matrix_a, 16, 16, 16, __half, wmma::row_major> FragAh;
typedef wmma::fragment<wmma::matrix_a, 16, 16, 16, __half, wmma::col_major> FragAhT;
typedef wmma::fragment<wmma::matrix_b, 16, 16, 16, __half, wmma::row_major> FragBh;
typedef wmma::fragment<wmma::accumulator, 16, 16, 16, float> FragCh;

__device__ __forceinline__ uint32_t smem_u32(const void* p) {
    return (uint32_t)__cvta_generic_to_shared(p);
}
__device__ __forceinline__ void cpasync16(void* dst, const void* src) {
    asm volatile("cp.async.cg.shared.global [%0], [%1], 16;\n"
                 :: "r"(smem_u32(dst)), "l"(src));
}
__device__ __forceinline__ void cp_commit() {
    asm volatile("cp.async.commit_group;\n");
}

// ---------------- float -> half conversion ----------------
__device__ __forceinline__ void f2h_body(const float4* in, uint2* out, int i) {
    float4 a = in[i];
    __half2 lo = __floats2half2_rn(a.x, a.y);
    __half2 hi = __floats2half2_rn(a.z, a.w);
    uint2 p;
    p.x = *(uint32_t*)&lo;
    p.y = *(uint32_t*)&hi;
    out[i] = p;
}

__global__ __launch_bounds__(256) void f2h_kernel(
    const float4* __restrict__ in, uint2* __restrict__ out, int n4)
{
    int i = blockIdx.x * 256 + threadIdx.x;
    if (i >= n4) return;
    f2h_body(in, out, i);
}

// 5 weight conversions in one launch (blockIdx.y selects the job)
__global__ __launch_bounds__(256) void f2h_multi_kernel(
    const float4* i0, uint2* o0, int n0,
    const float4* i1, uint2* o1, int n1,
    const float4* i2, uint2* o2, int n2,
    const float4* i3, uint2* o3, int n3,
    const float4* i4, uint2* o4, int n4)
{
    const float4* in; uint2* out; int n;
    switch (blockIdx.y) {
        case 0: in = i0; out = o0; n = n0; break;
        case 1: in = i1; out = o1; n = n1; break;
        case 2: in = i2; out = o2; n = n2; break;
        case 3: in = i3; out = o3; n = n3; break;
        default: in = i4; out = o4; n = n4; break;
    }
    int i = blockIdx.x * 256 + threadIdx.x;
    if (i >= n) return;
    f2h_body(in, out, i);
}

// ---------------- 3-stage pipelined fp16 GEMM: CTA 128x256, warp 64x64, BK=32 ----------------
#define AS_STRIDE 40     // halves
#define BS_STRIDE 264    // halves
#define STAGE_HALFS (128 * AS_STRIDE + 32 * BS_STRIDE)   // 13568
#define GEMM_SMEM_BYTES (3 * STAGE_HALFS * 2)            // 81408

__device__ __forceinline__ void gemm_load_tile_h(
    __half* sm, int buf, const __half* A, int lda, const __half* B, int ldb, int it, int tid)
{
    __half* As = sm + buf * STAGE_HALFS;
    __half* Bs = As + 128 * AS_STRIDE;
    const __half* Ab = A + it * 32;
    const __half* Bb = B + (size_t)it * 32 * ldb;
#pragma unroll
    for (int i = tid; i < 512; i += 256) {
        int r = i >> 2, c = i & 3;
        cpasync16(&As[r * AS_STRIDE + c * 8], Ab + (size_t)r * lda + c * 8);
    }
#pragma unroll
    for (int i = tid; i < 1024; i += 256) {
        int r = i >> 5, c = i & 31;
        cpasync16(&Bs[r * BS_STRIDE + c * 8], Bb + (size_t)r * ldb + c * 8);
    }
    cp_commit();
}

__device__ __forceinline__ void gemm128x256_fp16(
    const __half* __restrict__ A, int lda,
    const __half* __restrict__ B, int ldb,
    float* __restrict__ C, int ldc,
    int K, __half* sm)
{
    const int tid = threadIdx.x;
    const int w = tid >> 5;
    const int wr = w >> 2;
    const int wc = w & 3;

    FragCh acc[4][4];
#pragma unroll
    for (int r = 0; r < 4; r++)
#pragma unroll
        for (int c = 0; c < 4; c++) wmma::fill_fragment(acc[r][c], 0.0f);

    const int ntiles = K / 32;

    gemm_load_tile_h(sm, 0, A, lda, B, ldb, 0, tid);
    gemm_load_tile_h(sm, 1, A, lda, B, ldb, 1, tid);

    for (int it = 0; it < ntiles; it++) {
        if (it < ntiles - 1) {
            asm volatile("cp.async.wait_group 1;\n");
        } else {
            asm volatile("cp.async.wait_group 0;\n");
        }
        __syncthreads();
        if (it + 2 < ntiles)
            gemm_load_tile_h(sm, (it + 2) % 3, A, lda, B, ldb, it + 2, tid);

        __half* Ac = sm + (it % 3) * STAGE_HALFS;
        __half* Bc = Ac + 128 * AS_STRIDE;
#pragma unroll
        for (int kk = 0; kk < 32; kk += 16) {
            FragAh af[4];
            FragBh bf[4];
#pragma unroll
            for (int r = 0; r < 4; r++)
                wmma::load_matrix_sync(af[r], &Ac[(wr * 64 + r * 16) * AS_STRIDE + kk], AS_STRIDE);
#pragma unroll
            for (int c = 0; c < 4; c++)
                wmma::load_matrix_sync(bf[c], &Bc[kk * BS_STRIDE + wc * 64 + c * 16], BS_STRIDE);
#pragma unroll
            for (int r = 0; r < 4; r++)
#pragma unroll
                for (int c = 0; c < 4; c++)
                    wmma::mma_sync(acc[r][c], af[r], bf[c], acc[r][c]);
        }
    }
    __syncthreads();

#pragma unroll
    for (int r = 0; r < 4; r++)
#pragma unroll
        for (int c = 0; c < 4; c++)
            wmma::store_matrix_sync(
                C + (size_t)(wr * 64 + r * 16) * ldc + wc * 64 + c * 16,
                acc[r][c], ldc, wmma::mem_row_major);
}

// ---------------- fused q/k/v/g projections (fp16) ----------------
__global__ __launch_bounds__(256) void proj_qkvg_kernel(
    const __half* __restrict__ xh,
    const __half* __restrict__ Wq, const __half* __restrict__ Wk,
    const __half* __restrict__ Wv, const __half* __restrict__ Wg,
    float* __restrict__ q, float* __restrict__ k,
    float* __restrict__ v, float* __restrict__ g)
{
    extern __shared__ __half smh[];
    const int bn = blockIdx.x;
    const int bm = blockIdx.y;
    const __half* B;
    float* C;
    int n0, ldn;
    if (bn < 2)       { B = Wq; C = q; n0 = bn;     ldn = HDK; }
    else if (bn < 4)  { B = Wk; C = k; n0 = bn - 2; ldn = HDK; }
    else if (bn < 8)  { B = Wv; C = v; n0 = bn - 4; ldn = HDV; }
    else              { B = Wg; C = g; n0 = bn - 8; ldn = HDV; }
    gemm128x256_fp16(xh + (size_t)bm * 128 * DM, DM,
                     B + n0 * 256, ldn,
                     C + (size_t)bm * 128 * ldn + n0 * 256, ldn,
                     DM, smh);
}

// ---------------- output projection (fp16) ----------------
__global__ __launch_bounds__(256) void gemm_wo_kernel(
    const __half* __restrict__ yh, const __half* __restrict__ Wo, float* __restrict__ out)
{
    extern __shared__ __half smh[];
    const int bn = blockIdx.x, bm = blockIdx.y;
    gemm128x256_fp16(yh + (size_t)bm * 128 * HDV, HDV,
                     Wo + bn * 256, DM,
                     out + (size_t)bm * 128 * DM + bn * 256,
                     DM, HDV, smh);
}

// ---------------- fused low-rank gate: gk = logsig((x@Wgk1)@Wgk2 + b)/16 ----------------
__global__ __launch_bounds__(256) void gk_fused_kernel(
    const float* __restrict__ x, const float* __restrict__ W1,
    const float* __restrict__ W2, const float* __restrict__ bias,
    float* __restrict__ gk)
{
    int t = blockIdx.x * 8 + (threadIdx.x >> 5);
    int lane = threadIdx.x & 31;
    const float* xr = x + (size_t)t * DM;
    float acc[LR];
#pragma unroll
    for (int n = 0; n < LR; n++) acc[n] = 0.0f;
    for (int j = lane; j < DM; j += 32) {
        float xv = xr[j];
        const float* wr = W1 + (size_t)j * LR;
#pragma unroll
        for (int n = 0; n < LR; n++) acc[n] += xv * wr[n];
    }
    // butterfly: every lane ends with the full x1[16]
#pragma unroll
    for (int n = 0; n < LR; n++) {
#pragma unroll
        for (int off = 16; off > 0; off >>= 1)
            acc[n] += __shfl_xor_sync(0xffffffff, acc[n], off);
    }
    float* gkt = gk + (size_t)t * HDK;
#pragma unroll
    for (int j = 0; j < 16; j++) {
        int n = j * 32 + lane;
        float a = bias[n];
#pragma unroll
        for (int kx = 0; kx < LR; kx++) a += acc[kx] * W2[kx * HDK + n];
        float ls = fminf(a, 0.0f) - log1pf(expf(-fabsf(a)));
        gkt[n] = ls * (1.0f / GNORM);
    }
}

// ---------------- decay prep: fp32 qg/kint (gla_A) + fp16 qg/kg (fused) ----------------
__global__ __launch_bounds__(128) void decay_prep_kernel(
    const float* __restrict__ q, const float* __restrict__ k, const float* __restrict__ gk,
    float* __restrict__ qg, float* __restrict__ kint,
    __half* __restrict__ qgh, __half* __restrict__ kgh,
    float* __restrict__ glast)
{
    int c = blockIdx.x >> 2;
    int col = ((blockIdx.x & 3) << 7) + threadIdx.x;
    size_t base = (size_t)c * CH * HDK + col;
    float tot = 0.0f;
#pragma unroll 8
    for (int i = 0; i < CH; i++) tot += gk[base + (size_t)i * HDK];
    glast[(size_t)c * HDK + col] = __expf(tot);
    const float scale = 0.088388347648318447f;   // 128^-0.5
    float run = 0.0f;
#pragma unroll 4
    for (int i = 0; i < CH; i++) {
        size_t idx = base + (size_t)i * HDK;
        run += gk[idx];
        float qv = q[idx] * __expf(run) * scale;
        float kgv = k[idx] * __expf(tot - run);
        qg[idx]   = rtf32(qv);
        kint[idx] = rtf32(k[idx] * __expf(-run));
        qgh[idx]  = __float2half(qv);
        kgh[idx]  = __float2half(kgv);
    }
}

// ---------------- intra A matrix: tf32 compute, fp16 masked store ----------------
__global__ __launch_bounds__(256) void gla_A_kernel(
    const float* __restrict__ qg, const float* __restrict__ kint, __half* __restrict__ Ah)
{
    __shared__ float As[64 * 72];
    const int ch = blockIdx.x;
    const int c = ch >> 2, h = ch & 3;
    const size_t t0 = (size_t)c * CH;
    const float* qgb = qg   + t0 * HDK + h * DKd;
    const float* kib = kint + t0 * HDK + h * DKd;
    const int tid = threadIdx.x, w = tid >> 5;

#pragma unroll
    for (int tIdx = w * 2; tIdx < w * 2 + 2; tIdx++) {
        int ti = tIdx >> 2, tj = tIdx & 3;
        FragC acc;
        wmma::fill_fragment(acc, 0.0f);
#pragma unroll
        for (int kk = 0; kk < DKd; kk += 8) {
            FragA a; FragBT b;
            wmma::load_matrix_sync(a, qgb + (size_t)(ti * 16) * HDK + kk, HDK);
            wmma::load_matrix_sync(b, kib + (size_t)(tj * 16) * HDK + kk, HDK);
            wmma::mma_sync(acc, a, b, acc);
        }
        wmma::store_matrix_sync(&As[(ti * 16) * 72 + tj * 16], acc, 72, wmma::mem_row_major);
    }
    __syncthreads();
    __half* Ab = Ah + (size_t)ch * CH * CH;
    for (int i = tid; i < 64 * 64; i += 256) {
        int r = i >> 6, cc = i & 63;
        Ab[i] = (cc > r) ? __float2half(0.0f) : __float2half(As[r * 72 + cc]);
    }
}

// ---------------- FUSED chunkwise GLA (fp16 MMAs, fp32 S master), dv-block = 32 ----------------
// Warp-specialized: warps 0-3 -> o, warps 4-7 -> U.  V prefetched via cp.async (fp32).
#define S_STRIDE 36     // fp32 master
#define SH_STRIDE 40    // fp16 shadow (halves)
#define VH_STRIDE 40    // halves
#define VF_STRIDE 68    // fp32 prefetch buffer
#define U_STRIDE 36
// smem bytes: Ssm 18432 + Vf 34816 + Us 18432 + sglf 1024 + Sh 10240 + Vsh 5120
#define FUSED_SMEM_BYTES (128*S_STRIDE*4 + 2*64*VF_STRIDE*4 + 128*U_STRIDE*4 + 2*128*4 \
                          + 128*SH_STRIDE*2 + 64*VH_STRIDE*2)

__global__ __launch_bounds__(256) void gla_fused_kernel(
    const __half* __restrict__ Amat, const __half* __restrict__ qgh,
    const __half* __restrict__ kgh, const float* __restrict__ v,
    const float* __restrict__ glast, float* __restrict__ o)
{
    extern __shared__ char smraw[];
    float*  Ssm  = (float*)smraw;                    // 128 x 36
    float*  Vf   = Ssm + 128 * S_STRIDE;             // 2 x 64 x 68
    float*  Us   = Vf + 2 * 64 * VF_STRIDE;          // 128 x 36
    float*  sglf = Us + 128 * U_STRIDE;              // 2 x 128
    __half* Sh   = (__half*)(sglf + 2 * 128);        // 128 x 40
    __half* Vsh  = Sh + 128 * SH_STRIDE;             // 64 x 40

    const int id = blockIdx.x;
    const int b = id >> 5, h = (id >> 3) & 3, dvb = id & 7;
    const int tid = threadIdx.x, w = tid >> 5;

    for (int i = tid; i < 128 * S_STRIDE; i += 256) Ssm[i] = 0.0f;
    for (int i = tid; i < 128 * SH_STRIDE / 2; i += 256)
        *((__half2*)Sh + i) = __half2half2(__float2half(0.0f));

    auto issue_load = [&](int n, int buf) {
        const float* vb = v + (size_t)(b * NC + n) * CH * HDV + h * DVd + dvb * 32;
        const float* gl = glast + (size_t)(b * NC + n) * HDK + h * DKd;
#pragma unroll
        for (int cidx = 0; cidx < 2; cidx++) {
            int idx = cidx * 256 + tid;          // 0..511
            int r = idx >> 3, c = idx & 7;
            cpasync16(Vf + buf * 64 * VF_STRIDE + r * VF_STRIDE + c * 4,
                      vb + (size_t)r * HDV + c * 4);
        }
        if (tid < 32) cpasync16(sglf + buf * 128 + tid * 4, gl + tid * 4);
        cp_commit();
    };

    issue_load(0, 0);

    for (int n = 0; n < NC; n++) {
        const int buf = n & 1;
        const int c = b * NC + n;
        const int ch = c * HH + h;
        const size_t t0 = (size_t)c * CH;
        const __half* qgb = qgh + t0 * HDK + h * DKd;
        const __half* kgb = kgh + t0 * HDK + h * DKd;
        const __half* Ab  = Amat + (size_t)ch * CH * CH;
        float* ob         = o + t0 * HDV + h * DVd + dvb * 32;

        asm volatile("cp.async.wait_group 0;\n");
        __syncthreads();   // V(n)/sgl(n) arrived; prev S update complete

        if (n + 1 < NC) issue_load(n + 1, buf ^ 1);

        // convert Vf[buf] -> Vsh (fp16)
        {
            int r = tid >> 2, c8 = tid & 3;
            const float* src = Vf + buf * 64 * VF_STRIDE + r * VF_STRIDE + c8 * 8;
            float4 a4 = *(const float4*)src;
            float4 b4 = *(const float4*)(src + 4);
            __half2 h0 = __floats2half2_rn(a4.x, a4.y);
            __half2 h1 = __floats2half2_rn(a4.z, a4.w);
            __half2 h2 = __floats2half2_rn(b4.x, b4.y);
            __half2 h3 = __floats2half2_rn(b4.z, b4.w);
            uint4 u;
            u.x = *(uint32_t*)&h0; u.y = *(uint32_t*)&h1;
            u.z = *(uint32_t*)&h2; u.w = *(uint32_t*)&h3;
            *(uint4*)&Vsh[r * VH_STRIDE + c8 * 8] = u;
        }
        __syncthreads();

        if (w < 4) {
            // ---- o = A @ Vsh + qg @ Sh  (64x32; warp -> row tile w, both col tiles) ----
            FragCh acc2[2];
#pragma unroll
            for (int j = 0; j < 2; j++) wmma::fill_fragment(acc2[j], 0.0f);
#pragma unroll
            for (int kk = 0; kk < CH; kk += 16) {
                FragAh a;
                wmma::load_matrix_sync(a, Ab + (size_t)(w * 16) * CH + kk, CH);
#pragma unroll
                for (int j = 0; j < 2; j++) {
                    FragBh bf;
                    wmma::load_matrix_sync(bf, &Vsh[kk * VH_STRIDE + j * 16], VH_STRIDE);
                    wmma::mma_sync(acc2[j], a, bf, acc2[j]);
                }
            }
#pragma unroll
            for (int kk = 0; kk < DKd; kk += 16) {
                FragAh a;
                wmma::load_matrix_sync(a, qgb + (size_t)(w * 16) * HDK + kk, HDK);
#pragma unroll
                for (int j = 0; j < 2; j++) {
                    FragBh bf;
                    wmma::load_matrix_sync(bf, &Sh[kk * SH_STRIDE + j * 16], SH_STRIDE);
                    wmma::mma_sync(acc2[j], a, bf, acc2[j]);
                }
            }
#pragma unroll
            for (int j = 0; j < 2; j++)
                wmma::store_matrix_sync(ob + (size_t)(w * 16) * HDV + j * 16,
                                        acc2[j], HDV, wmma::mem_row_major);
        } else {
            // ---- U = kg^T (128x32) @ Vsh (64x32): warp wu -> rows 32wu..32wu+31 ----
            const int wu = w - 4;
            FragCh acc4[2][2];
#pragma unroll
            for (int r = 0; r < 2; r++)
#pragma unroll
                for (int j = 0; j < 2; j++) wmma::fill_fragment(acc4[r][j], 0.0f);
#pragma unroll
            for (int kk = 0; kk < CH; kk += 16) {
                FragAhT a[2];
                FragBh bf[2];
#pragma unroll
                for (int r = 0; r < 2; r++)
                    wmma::load_matrix_sync(a[r], kgb + (size_t)kk * HDK + (2 * wu + r) * 16, HDK);
#pragma unroll
                for (int j = 0; j < 2; j++)
                    wmma::load_matrix_sync(bf[j], &Vsh[kk * VH_STRIDE + j * 16], VH_STRIDE);
#pragma unroll
                for (int r = 0; r < 2; r++)
#pragma unroll
                    for (int j = 0; j < 2; j++)
                        wmma::mma_sync(acc4[r][j], a[r], bf[j], acc4[r][j]);
            }
#pragma unroll
            for (int r = 0; r < 2; r++)
#pragma unroll
                for (int j = 0; j < 2; j++)
                    wmma::store_matrix_sync(&Us[((2 * wu + r) * 16) * U_STRIDE + j * 16],
                                            acc4[r][j], U_STRIDE, wmma::mem_row_major);
        }
        __syncthreads();

        // ---- S = S * diag(gl) + U  (fp32 master + fp16 shadow) ----
        const float* sgl = sglf + buf * 128;
#pragma unroll
        for (int j = 0; j < 16; j++) {
            int i = j * 256 + tid;
            int r = i >> 5, cc = i & 31;
            float s = Ssm[r * S_STRIDE + cc] * sgl[r] + Us[r * U_STRIDE + cc];
            Ssm[r * S_STRIDE + cc] = s;
            Sh[r * SH_STRIDE + cc] = __float2half(s);
        }
    }
}

// ---------------- gated RMSNorm (emits fp16 y) ----------------
__global__ __launch_bounds__(256) void norm_gate_kernel(
    const float* __restrict__ o, const float* __restrict__ g,
    const float* __restrict__ gnw, __half* __restrict__ yh)
{
    int row = blockIdx.x * 8 + (threadIdx.x >> 5);
    int lane = threadIdx.x & 31;
    size_t base = (size_t)row * DVd;
    float v[8];
    float ss = 0.0f;
#pragma unroll
    for (int j = 0; j < 8; j++) {
        v[j] = o[base + lane + j * 32];
        ss += v[j] * v[j];
    }
#pragma unroll
    for (int off = 16; off > 0; off >>= 1)
        ss += __shfl_xor_sync(0xffffffff, ss, off);
    float r = rsqrtf(ss * (1.0f / DVd) + EPS);
#pragma unroll
    for (int j = 0; j < 8; j++) {
        int dv = lane + j * 32;
        float gv = g[base + dv];
        float sw = gv / (1.0f + expf(-gv));
        yh[base + dv] = __float2half(v[j] * r * gnw[dv] * sw);
    }
}

// ---------------- launch ----------------
extern "C" void kernel_launch(void* const* d_in, const int* in_sizes, int n_in,
                              void* d_out, int out_size)
{
    const float* x    = (const float*)d_in[0];
    const float* Wq   = (const float*)d_in[1];
    const float* Wk   = (const float*)d_in[2];
    const float* Wv   = (const float*)d_in[3];
    const float* Wg   = (const float*)d_in[4];
    const float* Wgk1 = (const float*)d_in[5];
    const float* Wgk2 = (const float*)d_in[6];
    const float* bgk2 = (const float*)d_in[7];
    const float* Wo   = (const float*)d_in[8];
    const float* gnw  = (const float*)d_in[9];
    float* out = (float*)d_out;

    __half *xh, *Wqh, *Wkh, *Wvh, *Wgh, *Woh, *yh, *qgh, *kgh, *Ah;
    float *q, *k, *v, *g, *gk, *qg, *kint, *glast, *o;
    cudaGetSymbolAddress((void**)&xh, d_xh);
    cudaGetSymbolAddress((void**)&Wqh, d_Wqh);
    cudaGetSymbolAddress((void**)&Wkh, d_Wkh);
    cudaGetSymbolAddress((void**)&Wvh, d_Wvh);
    cudaGetSymbolAddress((void**)&Wgh, d_Wgh);
    cudaGetSymbolAddress((void**)&Woh, d_Woh);
    cudaGetSymbolAddress((void**)&yh, d_yh);
    cudaGetSymbolAddress((void**)&qgh, d_qgh);
    cudaGetSymbolAddress((void**)&kgh, d_kgh);
    cudaGetSymbolAddress((void**)&Ah, d_Ah);
    cudaGetSymbolAddress((void**)&q, d_q);
    cudaGetSymbolAddress((void**)&k, d_k);
    cudaGetSymbolAddress((void**)&v, d_v);
    cudaGetSymbolAddress((void**)&g, d_g);
    cudaGetSymbolAddress((void**)&gk, d_gk);
    cudaGetSymbolAddress((void**)&qg, d_qg);
    cudaGetSymbolAddress((void**)&kint, d_kint);
    cudaGetSymbolAddress((void**)&glast, d_glast);
    cudaGetSymbolAddress((void**)&o, d_o);

    cudaFuncSetAttribute(proj_qkvg_kernel,
                         cudaFuncAttributeMaxDynamicSharedMemorySize, GEMM_SMEM_BYTES);
    cudaFuncSetAttribute(gemm_wo_kernel,
                         cudaFuncAttributeMaxDynamicSharedMemorySize, GEMM_SMEM_BYTES);
    cudaFuncSetAttribute(gla_fused_kernel,
                         cudaFuncAttributeMaxDynamicSharedMemorySize, FUSED_SMEM_BYTES);

    // conversions: x (big) + 5 weights (one launch)
    f2h_kernel<<<(BT * DM / 4) / 256, 256>>>((const float4*)x, (uint2*)xh, BT * DM / 4);
    f2h_multi_kernel<<<dim3(1024, 5), 256>>>(
        (const float4*)Wq, (uint2*)Wqh, DM * HDK / 4,
        (const float4*)Wk, (uint2*)Wkh, DM * HDK / 4,
        (const float4*)Wv, (uint2*)Wvh, DM * HDV / 4,
        (const float4*)Wg, (uint2*)Wgh, DM * HDV / 4,
        (const float4*)Wo, (uint2*)Woh, HDV * DM / 4);

    // fused input projections (fp16 HMMA)
    proj_qkvg_kernel<<<dim3(12, BT / 128), 256, GEMM_SMEM_BYTES>>>(xh, Wqh, Wkh, Wvh, Wgh, q, k, v, g);

    // fused low-rank gate path (exact fp32 on original x)
    gk_fused_kernel<<<BT / 8, 256>>>(x, Wgk1, Wgk2, bgk2, gk);

    // decay factors
    decay_prep_kernel<<<NCHUNK * 4, 128>>>(q, k, gk, qg, kint, qgh, kgh, glast);

    // intra A matrices (tf32 compute, fp16 store)
    gla_A_kernel<<<NCHUNK * HH, 256>>>(qg, kint, Ah);

    // fused chunkwise GLA (warp-specialized, V prefetch)
    gla_fused_kernel<<<BB * HH * 8, 256, FUSED_SMEM_BYTES>>>(Ah, qgh, kgh, v, glast, o);

    // gated RMSNorm (fp16 y) + output projection (fp16 HMMA)
    norm_gate_kernel<<<(BT * HH) / 8, 256>>>(o, g, gnw, yh);
    gemm_wo_kernel<<<dim3(DM / 256, BT / 128), 256, GEMM_SMEM_BYTES>>>(yh, Woh, out);
}

// round 11
// speedup vs baseline: 3.9463x; 1.3600x over previous
#include <cuda_runtime.h>
#include <cuda_fp16.h>
#include <mma.h>
#include <cstdint>

using namespace nvcuda;

// ---------------- problem constants ----------------
#define BB 4
#define TT 2048
#define DM 1024
#define HH 4
#define DKd 128
#define DVd 256
#define HDK 512     // H*DK
#define HDV 1024    // H*DV
#define BT  8192    // B*T tokens
#define CH  64      // chunk
#define NC  32      // chunks per sequence
#define NCHUNK 128  // total chunks (B*NC)
#define LR 16       // gate low rank
#define GNORM 16.0f
#define EPS 1e-5f

// ---------------- scratch ----------------
__device__ __half d_xh [BT * DM];
__device__ __half d_Wqh[DM * HDK];
__device__ __half d_Wkh[DM * HDK];
__device__ __half d_Wvh[DM * HDV];
__device__ __half d_Wgh[DM * HDV];
__device__ __half d_Woh[HDV * DM];
__device__ __half d_yh [BT * HDV];
__device__ __half d_qgh[BT * HDK];      // fp16 qg (fused kernel)
__device__ __half d_kgh[BT * HDK];      // fp16 kg (fused kernel)
__device__ __half d_Ah [NCHUNK * HH * CH * CH];  // fp16 masked intra A
__device__ float d_W1t [LR * DM];       // transposed Wgk1 [16,1024]
__device__ float d_q   [BT * HDK];
__device__ float d_k   [BT * HDK];
__device__ float d_v   [BT * HDV];
__device__ float d_g   [BT * HDV];
__device__ float d_gk  [BT * HDK];
__device__ float d_qg  [BT * HDK];      // tf32-rounded (gla_A)
__device__ float d_kint[BT * HDK];      // tf32-rounded (gla_A; may exceed fp16 range)
__device__ float d_glast[NCHUNK * HDK];
__device__ float d_o   [BT * HDV];

// ---------------- helpers ----------------
__device__ __forceinline__ float rtf32(float x) {
    return wmma::__float_to_tf32(x);
}

// tf32 fragments (gla_A only)
typedef wmma::fragment<wmma::matrix_a, 16, 16, 8, wmma::precision::tf32, wmma::row_major> FragA;
typedef wmma::fragment<wmma::matrix_b, 16, 16, 8, wmma::precision::tf32, wmma::col_major> FragBT;
typedef wmma::fragment<wmma::accumulator, 16, 16, 8, float> FragC;

// fp16 fragments
typedef wmma::fragment<wmma::matrix_a, 16, 16, 16, __half, wmma::row_major> FragAh;
typedef wmma::fragment<wmma::matrix_a, 16, 16, 16, __half, wmma::col_major> FragAhT;
typedef wmma::fragment<wmma::matrix_b, 16, 16, 16, __half, wmma::row_major> FragBh;
typedef wmma::fragment<wmma::accumulator, 16, 16, 16, float> FragCh;

__device__ __forceinline__ uint32_t smem_u32(const void* p) {
    return (uint32_t)__cvta_generic_to_shared(p);
}
__device__ __forceinline__ void cpasync16(void* dst, const void* src) {
    asm volatile("cp.async.cg.shared.global [%0], [%1], 16;\n"
                 :: "r"(smem_u32(dst)), "l"(src));
}
__device__ __forceinline__ void cp_commit() {
    asm volatile("cp.async.commit_group;\n");
}

// ---------------- float -> half conversion ----------------
__device__ __forceinline__ void f2h_body(const float4* in, uint2* out, int i) {
    float4 a = in[i];
    __half2 lo = __floats2half2_rn(a.x, a.y);
    __half2 hi = __floats2half2_rn(a.z, a.w);
    uint2 p;
    p.x = *(uint32_t*)&lo;
    p.y = *(uint32_t*)&hi;
    out[i] = p;
}

__global__ __launch_bounds__(256) void f2h_kernel(
    const float4* __restrict__ in, uint2* __restrict__ out, int n4)
{
    int i = blockIdx.x * 256 + threadIdx.x;
    if (i >= n4) return;
    f2h_body(in, out, i);
}

// 5 weight conversions in one launch (blockIdx.y selects the job)
__global__ __launch_bounds__(256) void f2h_multi_kernel(
    const float4* i0, uint2* o0, int n0,
    const float4* i1, uint2* o1, int n1,
    const float4* i2, uint2* o2, int n2,
    const float4* i3, uint2* o3, int n3,
    const float4* i4, uint2* o4, int n4)
{
    const float4* in; uint2* out; int n;
    switch (blockIdx.y) {
        case 0: in = i0; out = o0; n = n0; break;
        case 1: in = i1; out = o1; n = n1; break;
        case 2: in = i2; out = o2; n = n2; break;
        case 3: in = i3; out = o3; n = n3; break;
        default: in = i4; out = o4; n = n4; break;
    }
    int i = blockIdx.x * 256 + threadIdx.x;
    if (i >= n) return;
    f2h_body(in, out, i);
}

// ---------------- W1 transpose: W1t[n*DM + j] = W1[j*LR + n] ----------------
__global__ __launch_bounds__(256) void w1_transpose_kernel(
    const float* __restrict__ W1, float* __restrict__ W1t)
{
    int i = blockIdx.x * 256 + threadIdx.x;   // over 16384 elements, output-linear
    int n = i >> 10;          // 0..15
    int j = i & 1023;         // 0..1023
    W1t[i] = W1[j * LR + n];
}

// ---------------- 3-stage pipelined fp16 GEMM: CTA 128x256, warp 64x64, BK=32 ----------------
#define AS_STRIDE 40     // halves
#define BS_STRIDE 264    // halves
#define STAGE_HALFS (128 * AS_STRIDE + 32 * BS_STRIDE)   // 13568
#define GEMM_SMEM_BYTES (3 * STAGE_HALFS * 2)            // 81408

__device__ __forceinline__ void gemm_load_tile_h(
    __half* sm, int buf, const __half* A, int lda, const __half* B, int ldb, int it, int tid)
{
    __half* As = sm + buf * STAGE_HALFS;
    __half* Bs = As + 128 * AS_STRIDE;
    const __half* Ab = A + it * 32;
    const __half* Bb = B + (size_t)it * 32 * ldb;
#pragma unroll
    for (int i = tid; i < 512; i += 256) {
        int r = i >> 2, c = i & 3;
        cpasync16(&As[r * AS_STRIDE + c * 8], Ab + (size_t)r * lda + c * 8);
    }
#pragma unroll
    for (int i = tid; i < 1024; i += 256) {
        int r = i >> 5, c = i & 31;
        cpasync16(&Bs[r * BS_STRIDE + c * 8], Bb + (size_t)r * ldb + c * 8);
    }
    cp_commit();
}

__device__ __forceinline__ void gemm128x256_fp16(
    const __half* __restrict__ A, int lda,
    const __half* __restrict__ B, int ldb,
    float* __restrict__ C, int ldc,
    int K, __half* sm)
{
    const int tid = threadIdx.x;
    const int w = tid >> 5;
    const int wr = w >> 2;
    const int wc = w & 3;

    FragCh acc[4][4];
#pragma unroll
    for (int r = 0; r < 4; r++)
#pragma unroll
        for (int c = 0; c < 4; c++) wmma::fill_fragment(acc[r][c], 0.0f);

    const int ntiles = K / 32;

    gemm_load_tile_h(sm, 0, A, lda, B, ldb, 0, tid);
    gemm_load_tile_h(sm, 1, A, lda, B, ldb, 1, tid);

    for (int it = 0; it < ntiles; it++) {
        if (it < ntiles - 1) {
            asm volatile("cp.async.wait_group 1;\n");
        } else {
            asm volatile("cp.async.wait_group 0;\n");
        }
        __syncthreads();
        if (it + 2 < ntiles)
            gemm_load_tile_h(sm, (it + 2) % 3, A, lda, B, ldb, it + 2, tid);

        __half* Ac = sm + (it % 3) * STAGE_HALFS;
        __half* Bc = Ac + 128 * AS_STRIDE;
#pragma unroll
        for (int kk = 0; kk < 32; kk += 16) {
            FragAh af[4];
            FragBh bf[4];
#pragma unroll
            for (int r = 0; r < 4; r++)
                wmma::load_matrix_sync(af[r], &Ac[(wr * 64 + r * 16) * AS_STRIDE + kk], AS_STRIDE);
#pragma unroll
            for (int c = 0; c < 4; c++)
                wmma::load_matrix_sync(bf[c], &Bc[kk * BS_STRIDE + wc * 64 + c * 16], BS_STRIDE);
#pragma unroll
            for (int r = 0; r < 4; r++)
#pragma unroll
                for (int c = 0; c < 4; c++)
                    wmma::mma_sync(acc[r][c], af[r], bf[c], acc[r][c]);
        }
    }
    __syncthreads();

#pragma unroll
    for (int r = 0; r < 4; r++)
#pragma unroll
        for (int c = 0; c < 4; c++)
            wmma::store_matrix_sync(
                C + (size_t)(wr * 64 + r * 16) * ldc + wc * 64 + c * 16,
                acc[r][c], ldc, wmma::mem_row_major);
}

// ---------------- fused q/k/v/g projections (fp16) ----------------
__global__ __launch_bounds__(256) void proj_qkvg_kernel(
    const __half* __restrict__ xh,
    const __half* __restrict__ Wq, const __half* __restrict__ Wk,
    const __half* __restrict__ Wv, const __half* __restrict__ Wg,
    float* __restrict__ q, float* __restrict__ k,
    float* __restrict__ v, float* __restrict__ g)
{
    extern __shared__ __half smh[];
    const int bn = blockIdx.x;
    const int bm = blockIdx.y;
    const __half* B;
    float* C;
    int n0, ldn;
    if (bn < 2)       { B = Wq; C = q; n0 = bn;     ldn = HDK; }
    else if (bn < 4)  { B = Wk; C = k; n0 = bn - 2; ldn = HDK; }
    else if (bn < 8)  { B = Wv; C = v; n0 = bn - 4; ldn = HDV; }
    else              { B = Wg; C = g; n0 = bn - 8; ldn = HDV; }
    gemm128x256_fp16(xh + (size_t)bm * 128 * DM, DM,
                     B + n0 * 256, ldn,
                     C + (size_t)bm * 128 * ldn + n0 * 256, ldn,
                     DM, smh);
}

// ---------------- output projection (fp16) ----------------
__global__ __launch_bounds__(256) void gemm_wo_kernel(
    const __half* __restrict__ yh, const __half* __restrict__ Wo, float* __restrict__ out)
{
    extern __shared__ __half smh[];
    const int bn = blockIdx.x, bm = blockIdx.y;
    gemm128x256_fp16(yh + (size_t)bm * 128 * HDV, HDV,
                     Wo + bn * 256, DM,
                     out + (size_t)bm * 128 * DM + bn * 256,
                     DM, HDV, smh);
}

// ---------------- fused low-rank gate (coalesced W1t): gk = logsig((x@W1)@W2 + b)/16 ----------------
__global__ __launch_bounds__(256) void gk_fused_kernel(
    const float* __restrict__ x, const float* __restrict__ W1t,
    const float* __restrict__ W2, const float* __restrict__ bias,
    float* __restrict__ gk)
{
    int t = blockIdx.x * 8 + (threadIdx.x >> 5);
    int lane = threadIdx.x & 31;
    const float* xr = x + (size_t)t * DM;

    // stage 0: x row into registers (coalesced; same j = lane + 32i order as before)
    float xreg[32];
#pragma unroll
    for (int i = 0; i < 32; i++) xreg[i] = xr[lane + 32 * i];

    // stage 1: acc[n] = sum_j x[j] * W1t[n][j]   (W1t reads fully coalesced)
    float acc[LR];
#pragma unroll
    for (int n = 0; n < LR; n++) {
        const float* wrow = W1t + (size_t)n * DM;
        float s = 0.0f;
#pragma unroll
        for (int i = 0; i < 32; i++) s += xreg[i] * wrow[lane + 32 * i];
        acc[n] = s;
    }
    // butterfly: every lane ends with the full x1[16]
#pragma unroll
    for (int n = 0; n < LR; n++) {
#pragma unroll
        for (int off = 16; off > 0; off >>= 1)
            acc[n] += __shfl_xor_sync(0xffffffff, acc[n], off);
    }

    // stage 2: 16 coalesced outputs per lane
    float* gkt = gk + (size_t)t * HDK;
#pragma unroll
    for (int j = 0; j < 16; j++) {
        int n = j * 32 + lane;
        float a = bias[n];
#pragma unroll
        for (int kx = 0; kx < LR; kx++) a += acc[kx] * W2[kx * HDK + n];
        float ls = fminf(a, 0.0f) - log1pf(expf(-fabsf(a)));
        gkt[n] = ls * (1.0f / GNORM);
    }
}

// ---------------- decay prep: fp32 qg/kint (gla_A) + fp16 qg/kg (fused) ----------------
__global__ __launch_bounds__(128) void decay_prep_kernel(
    const float* __restrict__ q, const float* __restrict__ k, const float* __restrict__ gk,
    float* __restrict__ qg, float* __restrict__ kint,
    __half* __restrict__ qgh, __half* __restrict__ kgh,
    float* __restrict__ glast)
{
    int c = blockIdx.x >> 2;
    int col = ((blockIdx.x & 3) << 7) + threadIdx.x;
    size_t base = (size_t)c * CH * HDK + col;
    float tot = 0.0f;
#pragma unroll 8
    for (int i = 0; i < CH; i++) tot += gk[base + (size_t)i * HDK];
    glast[(size_t)c * HDK + col] = __expf(tot);
    const float scale = 0.088388347648318447f;   // 128^-0.5
    float run = 0.0f;
#pragma unroll 4
    for (int i = 0; i < CH; i++) {
        size_t idx = base + (size_t)i * HDK;
        run += gk[idx];
        float qv = q[idx] * __expf(run) * scale;
        float kgv = k[idx] * __expf(tot - run);
        qg[idx]   = rtf32(qv);
        kint[idx] = rtf32(k[idx] * __expf(-run));
        qgh[idx]  = __float2half(qv);
        kgh[idx]  = __float2half(kgv);
    }
}

// ---------------- intra A matrix: tf32 compute, fp16 masked store ----------------
__global__ __launch_bounds__(256) void gla_A_kernel(
    const float* __restrict__ qg, const float* __restrict__ kint, __half* __restrict__ Ah)
{
    __shared__ float As[64 * 72];
    const int ch = blockIdx.x;
    const int c = ch >> 2, h = ch & 3;
    const size_t t0 = (size_t)c * CH;
    const float* qgb = qg   + t0 * HDK + h * DKd;
    const float* kib = kint + t0 * HDK + h * DKd;
    const int tid = threadIdx.x, w = tid >> 5;

#pragma unroll
    for (int tIdx = w * 2; tIdx < w * 2 + 2; tIdx++) {
        int ti = tIdx >> 2, tj = tIdx & 3;
        FragC acc;
        wmma::fill_fragment(acc, 0.0f);
#pragma unroll
        for (int kk = 0; kk < DKd; kk += 8) {
            FragA a; FragBT b;
            wmma::load_matrix_sync(a, qgb + (size_t)(ti * 16) * HDK + kk, HDK);
            wmma::load_matrix_sync(b, kib + (size_t)(tj * 16) * HDK + kk, HDK);
            wmma::mma_sync(acc, a, b, acc);
        }
        wmma::store_matrix_sync(&As[(ti * 16) * 72 + tj * 16], acc, 72, wmma::mem_row_major);
    }
    __syncthreads();
    __half* Ab = Ah + (size_t)ch * CH * CH;
    for (int i = tid; i < 64 * 64; i += 256) {
        int r = i >> 6, cc = i & 63;
        Ab[i] = (cc > r) ? __float2half(0.0f) : __float2half(As[r * 72 + cc]);
    }
}

// ---------------- FUSED chunkwise GLA (fp16 MMAs, fp32 S master), dv-block = 32 ----------------
// Warp-specialized: warps 0-3 -> o, warps 4-7 -> U.  V prefetched via cp.async (fp32).
#define S_STRIDE 36     // fp32 master
#define SH_STRIDE 40    // fp16 shadow (halves)
#define VH_STRIDE 40    // halves
#define VF_STRIDE 68    // fp32 prefetch buffer
#define U_STRIDE 36
#define FUSED_SMEM_BYTES (128*S_STRIDE*4 + 2*64*VF_STRIDE*4 + 128*U_STRIDE*4 + 2*128*4 \
                          + 128*SH_STRIDE*2 + 64*VH_STRIDE*2)

__global__ __launch_bounds__(256) void gla_fused_kernel(
    const __half* __restrict__ Amat, const __half* __restrict__ qgh,
    const __half* __restrict__ kgh, const float* __restrict__ v,
    const float* __restrict__ glast, float* __restrict__ o)
{
    extern __shared__ char smraw[];
    float*  Ssm  = (float*)smraw;                    // 128 x 36
    float*  Vf   = Ssm + 128 * S_STRIDE;             // 2 x 64 x 68
    float*  Us   = Vf + 2 * 64 * VF_STRIDE;          // 128 x 36
    float*  sglf = Us + 128 * U_STRIDE;              // 2 x 128
    __half* Sh   = (__half*)(sglf + 2 * 128);        // 128 x 40
    __half* Vsh  = Sh + 128 * SH_STRIDE;             // 64 x 40

    const int id = blockIdx.x;
    const int b = id >> 5, h = (id >> 3) & 3, dvb = id & 7;
    const int tid = threadIdx.x, w = tid >> 5;

    for (int i = tid; i < 128 * S_STRIDE; i += 256) Ssm[i] = 0.0f;
    for (int i = tid; i < 128 * SH_STRIDE / 2; i += 256)
        *((__half2*)Sh + i) = __half2half2(__float2half(0.0f));

    auto issue_load = [&](int n, int buf) {
        const float* vb = v + (size_t)(b * NC + n) * CH * HDV + h * DVd + dvb * 32;
        const float* gl = glast + (size_t)(b * NC + n) * HDK + h * DKd;
#pragma unroll
        for (int cidx = 0; cidx < 2; cidx++) {
            int idx = cidx * 256 + tid;          // 0..511
            int r = idx >> 3, c = idx & 7;
            cpasync16(Vf + buf * 64 * VF_STRIDE + r * VF_STRIDE + c * 4,
                      vb + (size_t)r * HDV + c * 4);
        }
        if (tid < 32) cpasync16(sglf + buf * 128 + tid * 4, gl + tid * 4);
        cp_commit();
    };

    issue_load(0, 0);

    for (int n = 0; n < NC; n++) {
        const int buf = n & 1;
        const int c = b * NC + n;
        const int ch = c * HH + h;
        const size_t t0 = (size_t)c * CH;
        const __half* qgb = qgh + t0 * HDK + h * DKd;
        const __half* kgb = kgh + t0 * HDK + h * DKd;
        const __half* Ab  = Amat + (size_t)ch * CH * CH;
        float* ob         = o + t0 * HDV + h * DVd + dvb * 32;

        asm volatile("cp.async.wait_group 0;\n");
        __syncthreads();   // V(n)/sgl(n) arrived; prev S update complete

        if (n + 1 < NC) issue_load(n + 1, buf ^ 1);

        // convert Vf[buf] -> Vsh (fp16)
        {
            int r = tid >> 2, c8 = tid & 3;
            const float* src = Vf + buf * 64 * VF_STRIDE + r * VF_STRIDE + c8 * 8;
            float4 a4 = *(const float4*)src;
            float4 b4 = *(const float4*)(src + 4);
            __half2 h0 = __floats2half2_rn(a4.x, a4.y);
            __half2 h1 = __floats2half2_rn(a4.z, a4.w);
            __half2 h2 = __floats2half2_rn(b4.x, b4.y);
            __half2 h3 = __floats2half2_rn(b4.z, b4.w);
            uint4 u;
            u.x = *(uint32_t*)&h0; u.y = *(uint32_t*)&h1;
            u.z = *(uint32_t*)&h2; u.w = *(uint32_t*)&h3;
            *(uint4*)&Vsh[r * VH_STRIDE + c8 * 8] = u;
        }
        __syncthreads();

        if (w < 4) {
            // ---- o = A @ Vsh + qg @ Sh ----
            FragCh acc2[2];
#pragma unroll
            for (int j = 0; j < 2; j++) wmma::fill_fragment(acc2[j], 0.0f);
#pragma unroll
            for (int kk = 0; kk < CH; kk += 16) {
                FragAh a;
                wmma::load_matrix_sync(a, Ab + (size_t)(w * 16) * CH + kk, CH);
#pragma unroll
                for (int j = 0; j < 2; j++) {
                    FragBh bf;
                    wmma::load_matrix_sync(bf, &Vsh[kk * VH_STRIDE + j * 16], VH_STRIDE);
                    wmma::mma_sync(acc2[j], a, bf, acc2[j]);
                }
            }
#pragma unroll
            for (int kk = 0; kk < DKd; kk += 16) {
                FragAh a;
                wmma::load_matrix_sync(a, qgb + (size_t)(w * 16) * HDK + kk, HDK);
#pragma unroll
                for (int j = 0; j < 2; j++) {
                    FragBh bf;
                    wmma::load_matrix_sync(bf, &Sh[kk * SH_STRIDE + j * 16], SH_STRIDE);
                    wmma::mma_sync(acc2[j], a, bf, acc2[j]);
                }
            }
#pragma unroll
            for (int j = 0; j < 2; j++)
                wmma::store_matrix_sync(ob + (size_t)(w * 16) * HDV + j * 16,
                                        acc2[j], HDV, wmma::mem_row_major);
        } else {
            // ---- U = kg^T @ Vsh ----
            const int wu = w - 4;
            FragCh acc4[2][2];
#pragma unroll
            for (int r = 0; r < 2; r++)
#pragma unroll
                for (int j = 0; j < 2; j++) wmma::fill_fragment(acc4[r][j], 0.0f);
#pragma unroll
            for (int kk = 0; kk < CH; kk += 16) {
                FragAhT a[2];
                FragBh bf[2];
#pragma unroll
                for (int r = 0; r < 2; r++)
                    wmma::load_matrix_sync(a[r], kgb + (size_t)kk * HDK + (2 * wu + r) * 16, HDK);
#pragma unroll
                for (int j = 0; j < 2; j++)
                    wmma::load_matrix_sync(bf[j], &Vsh[kk * VH_STRIDE + j * 16], VH_STRIDE);
#pragma unroll
                for (int r = 0; r < 2; r++)
#pragma unroll
                    for (int j = 0; j < 2; j++)
                        wmma::mma_sync(acc4[r][j], a[r], bf[j], acc4[r][j]);
            }
#pragma unroll
            for (int r = 0; r < 2; r++)
#pragma unroll
                for (int j = 0; j < 2; j++)
                    wmma::store_matrix_sync(&Us[((2 * wu + r) * 16) * U_STRIDE + j * 16],
                                            acc4[r][j], U_STRIDE, wmma::mem_row_major);
        }
        __syncthreads();

        // ---- S = S * diag(gl) + U ----
        const float* sgl = sglf + buf * 128;
#pragma unroll
        for (int j = 0; j < 16; j++) {
            int i = j * 256 + tid;
            int r = i >> 5, cc = i & 31;
            float s = Ssm[r * S_STRIDE + cc] * sgl[r] + Us[r * U_STRIDE + cc];
            Ssm[r * S_STRIDE + cc] = s;
            Sh[r * SH_STRIDE + cc] = __float2half(s);
        }
    }
}

// ---------------- gated RMSNorm (emits fp16 y) ----------------
__global__ __launch_bounds__(256) void norm_gate_kernel(
    const float* __restrict__ o, const float* __restrict__ g,
    const float* __restrict__ gnw, __half* __restrict__ yh)
{
    int row = blockIdx.x * 8 + (threadIdx.x >> 5);
    int lane = threadIdx.x & 31;
    size_t base = (size_t)row * DVd;
    float v[8];
    float ss = 0.0f;
#pragma unroll
    for (int j = 0; j < 8; j++) {
        v[j] = o[base + lane + j * 32];
        ss += v[j] * v[j];
    }
#pragma unroll
    for (int off = 16; off > 0; off >>= 1)
        ss += __shfl_xor_sync(0xffffffff, ss, off);
    float r = rsqrtf(ss * (1.0f / DVd) + EPS);
#pragma unroll
    for (int j = 0; j < 8; j++) {
        int dv = lane + j * 32;
        float gv = g[base + dv];
        float sw = gv / (1.0f + expf(-gv));
        yh[base + dv] = __float2half(v[j] * r * gnw[dv] * sw);
    }
}

// ---------------- launch ----------------
extern "C" void kernel_launch(void* const* d_in, const int* in_sizes, int n_in,
                              void* d_out, int out_size)
{
    const float* x    = (const float*)d_in[0];
    const float* Wq   = (const float*)d_in[1];
    const float* Wk   = (const float*)d_in[2];
    const float* Wv   = (const float*)d_in[3];
    const float* Wg   = (const float*)d_in[4];
    const float* Wgk1 = (const float*)d_in[5];
    const float* Wgk2 = (const float*)d_in[6];
    const float* bgk2 = (const float*)d_in[7];
    const float* Wo   = (const float*)d_in[8];
    const float* gnw  = (const float*)d_in[9];
    float* out = (float*)d_out;

    __half *xh, *Wqh, *Wkh, *Wvh, *Wgh, *Woh, *yh, *qgh, *kgh, *Ah;
    float *W1t, *q, *k, *v, *g, *gk, *qg, *kint, *glast, *o;
    cudaGetSymbolAddress((void**)&xh, d_xh);
    cudaGetSymbolAddress((void**)&Wqh, d_Wqh);
    cudaGetSymbolAddress((void**)&Wkh, d_Wkh);
    cudaGetSymbolAddress((void**)&Wvh, d_Wvh);
    cudaGetSymbolAddress((void**)&Wgh, d_Wgh);
    cudaGetSymbolAddress((void**)&Woh, d_Woh);
    cudaGetSymbolAddress((void**)&yh, d_yh);
    cudaGetSymbolAddress((void**)&qgh, d_qgh);
    cudaGetSymbolAddress((void**)&kgh, d_kgh);
    cudaGetSymbolAddress((void**)&Ah, d_Ah);
    cudaGetSymbolAddress((void**)&W1t, d_W1t);
    cudaGetSymbolAddress((void**)&q, d_q);
    cudaGetSymbolAddress((void**)&k, d_k);
    cudaGetSymbolAddress((void**)&v, d_v);
    cudaGetSymbolAddress((void**)&g, d_g);
    cudaGetSymbolAddress((void**)&gk, d_gk);
    cudaGetSymbolAddress((void**)&qg, d_qg);
    cudaGetSymbolAddress((void**)&kint, d_kint);
    cudaGetSymbolAddress((void**)&glast, d_glast);
    cudaGetSymbolAddress((void**)&o, d_o);

    cudaFuncSetAttribute(proj_qkvg_kernel,
                         cudaFuncAttributeMaxDynamicSharedMemorySize, GEMM_SMEM_BYTES);
    cudaFuncSetAttribute(gemm_wo_kernel,
                         cudaFuncAttributeMaxDynamicSharedMemorySize, GEMM_SMEM_BYTES);
    cudaFuncSetAttribute(gla_fused_kernel,
                         cudaFuncAttributeMaxDynamicSharedMemorySize, FUSED_SMEM_BYTES);

    // conversions: x (big) + 5 weights (one launch) + W1 transpose
    f2h_kernel<<<(BT * DM / 4) / 256, 256>>>((const float4*)x, (uint2*)xh, BT * DM / 4);
    f2h_multi_kernel<<<dim3(1024, 5), 256>>>(
        (const float4*)Wq, (uint2*)Wqh, DM * HDK / 4,
        (const float4*)Wk, (uint2*)Wkh, DM * HDK / 4,
        (const float4*)Wv, (uint2*)Wvh, DM * HDV / 4,
        (const float4*)Wg, (uint2*)Wgh, DM * HDV / 4,
        (const float4*)Wo, (uint2*)Woh, HDV * DM / 4);
    w1_transpose_kernel<<<(LR * DM) / 256, 256>>>(Wgk1, W1t);

    // fused input projections (fp16 HMMA)
    proj_qkvg_kernel<<<dim3(12, BT / 128), 256, GEMM_SMEM_BYTES>>>(xh, Wqh, Wkh, Wvh, Wgh, q, k, v, g);

    // fused low-rank gate path (coalesced W1t)
    gk_fused_kernel<<<BT / 8, 256>>>(x, W1t, Wgk2, bgk2, gk);

    // decay factors
    decay_prep_kernel<<<NCHUNK * 4, 128>>>(q, k, gk, qg, kint, qgh, kgh, glast);

    // intra A matrices (tf32 compute, fp16 store)
    gla_A_kernel<<<NCHUNK * HH, 256>>>(qg, kint, Ah);

    // fused chunkwise GLA (warp-specialized, V prefetch)
    gla_fused_kernel<<<BB * HH * 8, 256, FUSED_SMEM_BYTES>>>(Ah, qgh, kgh, v, glast, o);

    // gated RMSNorm (fp16 y) + output projection (fp16 HMMA)
    norm_gate_kernel<<<(BT * HH) / 8, 256>>>(o, g, gnw, yh);
    gemm_wo_kernel<<<dim3(DM / 256, BT / 128), 256, GEMM_SMEM_BYTES>>>(yh, Woh, out);
}